// round 3
// baseline (speedup 1.0000x reference)
#include <cuda_runtime.h>
#include <cstdint>

typedef unsigned long long ull;

#define ASTR 20   // A smem row stride (16 k + 4 pad floats)

// ---------- packed fp32 helpers ----------
__device__ __forceinline__ ull pack2(float x, float y) {
    ull r; asm("mov.b64 %0, {%1, %2};" : "=l"(r) : "f"(x), "f"(y)); return r;
}
__device__ __forceinline__ void fma2(ull& acc, ull a, ull b) {
    asm("fma.rn.f32x2 %0, %1, %2, %0;" : "+l"(acc) : "l"(a), "l"(b));
}
__device__ __forceinline__ float2 unpack2(ull a) {
    float2 r; asm("mov.b64 {%0, %1}, %2;" : "=f"(r.x), "=f"(r.y) : "l"(a)); return r;
}
__device__ __forceinline__ uint32_t su32(const void* p) {
    uint32_t a;
    asm("{ .reg .u64 t; cvta.to.shared.u64 t, %1; cvt.u32.u64 %0, t; }" : "=r"(a) : "l"(p));
    return a;
}
__device__ __forceinline__ void cpasync16(uint32_t saddr, const void* g) {
    asm volatile("cp.async.cg.shared.global [%0], [%1], 16;" :: "r"(saddr), "l"(g));
}
#define CP_COMMIT asm volatile("cp.async.commit_group;")
#define CP_WAIT0  asm volatile("cp.async.wait_group 0;")

// ---------- scratch ----------
__device__ float g_FWVW[480 * 1024];
__device__ float g_h1[(size_t)51200 * 1024];
__device__ float g_h1t[(size_t)6240 * 1024];
__device__ float g_part[51200 * 8];
__device__ float g_partt[6240 * 8];
__device__ float g_S[64];

// =====================================================================
// FW/VW precompute (round-1 kernel, unchanged: 480x1024 = f@Wf / v@Ws)
// =====================================================================
__global__ __launch_bounds__(256) void fwvw_kernel(
    const float* __restrict__ span, const float* __restrict__ img,
    const float* __restrict__ gW1)
{
    __shared__ float At[32 * 33];
    __shared__ float Wt[32 * 128];
    const int g0 = blockIdx.x * 32;
    const int n0 = blockIdx.y * 128;
    const int t = threadIdx.x, tx = t & 15, ty = t >> 4;
    const bool isv = (g0 >= 320);
    const float* Wsrc = gW1 + (isv ? (size_t)1024 * 1024 : 0);

    ull acc[8] = {0,0,0,0,0,0,0,0};
    for (int kt = 0; kt < 32; ++kt) {
#pragma unroll
        for (int it = 0; it < 4; ++it) {
            int idx = t + it * 256; int k = idx & 31, r = idx >> 5;
            int g = g0 + r;
            const float* srow = isv ? (img + (size_t)(g - 320) * 1024) : (span + (size_t)g * 1024);
            At[k * 33 + r] = srow[kt * 32 + k];
        }
#pragma unroll
        for (int it = 0; it < 4; ++it) {
            int idx = t + it * 256; int kk = idx >> 5, c4 = idx & 31;
            ((float4*)Wt)[kk * 32 + c4] =
                *(const float4*)&Wsrc[(size_t)(kt * 32 + kk) * 1024 + n0 + c4 * 4];
        }
        __syncthreads();
#pragma unroll
        for (int k = 0; k < 32; ++k) {
            float a0s = At[k * 33 + 2 * ty], a1s = At[k * 33 + 2 * ty + 1];
            ull A0 = pack2(a0s, a0s), A1 = pack2(a1s, a1s);
            const ull* wrow = (const ull*)&Wt[k * 128 + tx * 8];
            ull w0 = wrow[0], w1 = wrow[1], w2 = wrow[2], w3 = wrow[3];
            fma2(acc[0], A0, w0); fma2(acc[1], A0, w1); fma2(acc[2], A0, w2); fma2(acc[3], A0, w3);
            fma2(acc[4], A1, w0); fma2(acc[5], A1, w1); fma2(acc[6], A1, w2); fma2(acc[7], A1, w3);
        }
        __syncthreads();
    }
#pragma unroll
    for (int dr = 0; dr < 2; ++dr) {
        int g = g0 + 2 * ty + dr;
#pragma unroll
        for (int cp = 0; cp < 4; ++cp) {
            float2 v = unpack2(acc[dr * 4 + cp]);
            int n = n0 + tx * 8 + cp * 2;
            g_FWVW[(size_t)g * 1024 + n] = v.x;
            g_FWVW[(size_t)g * 1024 + n + 1] = v.y;
        }
    }
}

// =====================================================================
// Shared GEMM micro-kernel pieces (128x128x16 tile, 256 thr, 8x8/thread)
// thread map: w=t>>5, l=t&31; wr=w&3 (32 rows), wc=w>>2 (64 cols)
//             lane_r=l&3, lane_c=l>>2; rows rbase+4m, cols coff+0..7
// =====================================================================
#define GEMM_IDX                                                     \
    const int t = threadIdx.x, l = t & 31, w = t >> 5;               \
    const int wr = w & 3, wc = w >> 2;                               \
    const int lane_r = l & 3, lane_c = l >> 2;                       \
    const int coff = wc * 64 + lane_c * 8;                           \
    const int rbase = wr * 32 + lane_r;

__device__ __forceinline__ void compute_tile(
    const float* __restrict__ Ac, const float* __restrict__ Bc,
    ull acc[8][4], int rbase, int coff)
{
#pragma unroll
    for (int k = 0; k < 16; ++k) {
        const ull* bp = (const ull*)&Bc[k * 128 + coff];
        ull b0 = bp[0], b1 = bp[1], b2 = bp[2], b3 = bp[3];
#pragma unroll
        for (int m = 0; m < 8; ++m) {
            float a = Ac[(rbase + 4 * m) * ASTR + k];
            ull a2 = pack2(a, a);
            fma2(acc[m][0], a2, b0); fma2(acc[m][1], a2, b1);
            fma2(acc[m][2], a2, b2); fma2(acc[m][3], a2, b3);
        }
    }
}

// =====================================================================
// Grounding GEMM1: h1 = relu((f o v) @ Wp + FW[i] + VW[j] + b1)
// =====================================================================
__global__ __launch_bounds__(256, 2) void g_gemm1(
    const float* __restrict__ span, const float* __restrict__ img,
    const float* __restrict__ gW1, const float* __restrict__ gb1)
{
    __shared__ float As[2][128 * ASTR];
    __shared__ float Bs[2][16 * 128];
    GEMM_IDX;
    const int n0 = blockIdx.x * 128, p0 = blockIdx.y * 128;
    const float* Wp = gW1 + (size_t)2 * 1024 * 1024;

    // A-gen setup: thread owns k=kk for 8 rows rg*8+e
    const int kk = t & 15, rg = t >> 4;
    int off_f[8], off_v[8];
#pragma unroll
    for (int e = 0; e < 8; ++e) {
        int p = p0 + rg * 8 + e;
        int i = p / 160, j = p - i * 160;
        off_f[e] = i * 1024 + kk;
        off_v[e] = j * 1024 + kk;
    }
    const int bkk = t >> 5, bc4 = t & 31;   // B: 2 float4 per thread

    // prologue: tile 0
    {
#pragma unroll
        for (int e = 0; e < 8; ++e)
            As[0][(rg * 8 + e) * ASTR + kk] = span[off_f[e]] * img[off_v[e]];
        cpasync16(su32(&Bs[0][bkk * 128 + bc4 * 4]),       Wp + (size_t)bkk * 1024 + n0 + bc4 * 4);
        cpasync16(su32(&Bs[0][(bkk + 8) * 128 + bc4 * 4]), Wp + (size_t)(bkk + 8) * 1024 + n0 + bc4 * 4);
        CP_COMMIT;
    }
    ull acc[8][4];
#pragma unroll
    for (int m = 0; m < 8; ++m) { acc[m][0]=0; acc[m][1]=0; acc[m][2]=0; acc[m][3]=0; }

    for (int kt = 0; kt < 64; ++kt) {
        CP_WAIT0; __syncthreads();
        const float* Ac = As[kt & 1];
        const float* Bc = Bs[kt & 1];
        float av[8];
        const bool nxt = (kt < 63);
        if (nxt) {
            int k0n = (kt + 1) * 16;
#pragma unroll
            for (int e = 0; e < 8; ++e)
                av[e] = span[off_f[e] + k0n] * img[off_v[e] + k0n];
            float* Bn = Bs[(kt + 1) & 1];
            cpasync16(su32(&Bn[bkk * 128 + bc4 * 4]),       Wp + (size_t)(k0n + bkk) * 1024 + n0 + bc4 * 4);
            cpasync16(su32(&Bn[(bkk + 8) * 128 + bc4 * 4]), Wp + (size_t)(k0n + bkk + 8) * 1024 + n0 + bc4 * 4);
        }
        compute_tile(Ac, Bc, acc, rbase, coff);
        if (nxt) {
            float* An = As[(kt + 1) & 1];
#pragma unroll
            for (int e = 0; e < 8; ++e) An[(rg * 8 + e) * ASTR + kk] = av[e];
            CP_COMMIT;
        }
    }
    // epilogue
    float bias[8];
#pragma unroll
    for (int q = 0; q < 8; ++q) bias[q] = gb1[n0 + coff + q];
#pragma unroll
    for (int m = 0; m < 8; ++m) {
        int r = rbase + 4 * m, p = p0 + r;
        int i = p / 160, j = p - i * 160;
        const float* fw = g_FWVW + (size_t)i * 1024 + n0 + coff;
        const float* vw = g_FWVW + (size_t)(320 + j) * 1024 + n0 + coff;
        float o[8];
#pragma unroll
        for (int q = 0; q < 4; ++q) {
            float2 xy = unpack2(acc[m][q]);
            o[2*q]   = fmaxf(xy.x + fw[2*q]   + vw[2*q]   + bias[2*q],   0.f);
            o[2*q+1] = fmaxf(xy.y + fw[2*q+1] + vw[2*q+1] + bias[2*q+1], 0.f);
        }
        float4* dst = (float4*)&g_h1[(size_t)p * 1024 + n0 + coff];
        dst[0] = make_float4(o[0], o[1], o[2], o[3]);
        dst[1] = make_float4(o[4], o[5], o[6], o[7]);
    }
}

// =====================================================================
// Grounding GEMM2: partial[p][nb] = sum_c relu(h1@W2 + b2)[c] * W3[c]
// =====================================================================
__global__ __launch_bounds__(256, 2) void g_gemm2(
    const float* __restrict__ gW2, const float* __restrict__ gb2,
    const float* __restrict__ gW3)
{
    __shared__ float As[2][128 * ASTR];
    __shared__ float Bs[2][16 * 128];
    __shared__ float red[2][128];
    GEMM_IDX;
    const int n0 = blockIdx.x * 128, p0 = blockIdx.y * 128;
    const int ar0 = t >> 2, ak0 = t & 3;     // A: 2 float4 per thread
    const int bkk = t >> 5, bc4 = t & 31;

    {
        cpasync16(su32(&As[0][ar0 * ASTR + ak0 * 4]),        &g_h1[(size_t)(p0 + ar0) * 1024 + ak0 * 4]);
        cpasync16(su32(&As[0][(ar0 + 64) * ASTR + ak0 * 4]), &g_h1[(size_t)(p0 + ar0 + 64) * 1024 + ak0 * 4]);
        cpasync16(su32(&Bs[0][bkk * 128 + bc4 * 4]),       gW2 + (size_t)bkk * 1024 + n0 + bc4 * 4);
        cpasync16(su32(&Bs[0][(bkk + 8) * 128 + bc4 * 4]), gW2 + (size_t)(bkk + 8) * 1024 + n0 + bc4 * 4);
        CP_COMMIT;
    }
    ull acc[8][4];
#pragma unroll
    for (int m = 0; m < 8; ++m) { acc[m][0]=0; acc[m][1]=0; acc[m][2]=0; acc[m][3]=0; }

    for (int kt = 0; kt < 64; ++kt) {
        CP_WAIT0; __syncthreads();
        const float* Ac = As[kt & 1];
        const float* Bc = Bs[kt & 1];
        const bool nxt = (kt < 63);
        if (nxt) {
            int k0n = (kt + 1) * 16;
            float* An = As[(kt + 1) & 1];
            float* Bn = Bs[(kt + 1) & 1];
            cpasync16(su32(&An[ar0 * ASTR + ak0 * 4]),        &g_h1[(size_t)(p0 + ar0) * 1024 + k0n + ak0 * 4]);
            cpasync16(su32(&An[(ar0 + 64) * ASTR + ak0 * 4]), &g_h1[(size_t)(p0 + ar0 + 64) * 1024 + k0n + ak0 * 4]);
            cpasync16(su32(&Bn[bkk * 128 + bc4 * 4]),       gW2 + (size_t)(k0n + bkk) * 1024 + n0 + bc4 * 4);
            cpasync16(su32(&Bn[(bkk + 8) * 128 + bc4 * 4]), gW2 + (size_t)(k0n + bkk + 8) * 1024 + n0 + bc4 * 4);
        }
        compute_tile(Ac, Bc, acc, rbase, coff);
        if (nxt) CP_COMMIT;
    }
    float b2r[8], w3r[8];
#pragma unroll
    for (int q = 0; q < 8; ++q) { b2r[q] = gb2[n0 + coff + q]; w3r[q] = gW3[n0 + coff + q]; }
#pragma unroll
    for (int m = 0; m < 8; ++m) {
        float s = 0.f;
#pragma unroll
        for (int q = 0; q < 4; ++q) {
            float2 xy = unpack2(acc[m][q]);
            s += fmaxf(xy.x + b2r[2*q],   0.f) * w3r[2*q];
            s += fmaxf(xy.y + b2r[2*q+1], 0.f) * w3r[2*q+1];
        }
        s += __shfl_xor_sync(0xffffffffu, s, 4);
        s += __shfl_xor_sync(0xffffffffu, s, 8);
        s += __shfl_xor_sync(0xffffffffu, s, 16);
        if (l < 4) red[wc][rbase + 4 * m] = s;
    }
    __syncthreads();
    if (t < 128)
        g_part[(size_t)(p0 + t) * 8 + blockIdx.x] = red[0][t] + red[1][t];
}

// =====================================================================
// Text GEMM1: h1t = relu([f,s,f*s] @ tW1 + b1), K = 3072
// =====================================================================
__global__ __launch_bounds__(256, 2) void t_gemm1(
    const float* __restrict__ span,
    const float* __restrict__ tW1, const float* __restrict__ tb1)
{
    __shared__ float As[2][128 * ASTR];
    __shared__ float Bs[2][16 * 128];
    GEMM_IDX;
    const int n0 = blockIdx.x * 128, p0 = blockIdx.y * 128;

    const int kk = t & 15, rg = t >> 4;
    int off_a[8], off_b[8];
#pragma unroll
    for (int e = 0; e < 8; ++e) {
        int p = p0 + rg * 8 + e;
        int R = p < 6240 ? p : 6239;
        int b = R / 780, q = R - b * 780;
        int fi = 0, cnt = 39, rem = q;
        while (rem >= cnt) { rem -= cnt; fi++; cnt--; }
        int si = fi + 1 + rem;
        off_a[e] = (b * 40 + fi) * 1024 + kk;
        off_b[e] = (b * 40 + si) * 1024 + kk;
    }
    const int bkk = t >> 5, bc4 = t & 31;

    // A-gen for tile kt
    auto agen = [&](int k0, float av[8]) {
        int region = k0 >> 10;
        int dbase = k0 & 1023;
#pragma unroll
        for (int e = 0; e < 8; ++e) {
            float a = span[off_a[e] + dbase];
            float bval = span[off_b[e] + dbase];
            av[e] = (region == 0) ? a : (region == 1) ? bval : a * bval;
        }
    };

    {
        float av[8]; agen(0, av);
#pragma unroll
        for (int e = 0; e < 8; ++e) As[0][(rg * 8 + e) * ASTR + kk] = av[e];
        cpasync16(su32(&Bs[0][bkk * 128 + bc4 * 4]),       tW1 + (size_t)bkk * 1024 + n0 + bc4 * 4);
        cpasync16(su32(&Bs[0][(bkk + 8) * 128 + bc4 * 4]), tW1 + (size_t)(bkk + 8) * 1024 + n0 + bc4 * 4);
        CP_COMMIT;
    }
    ull acc[8][4];
#pragma unroll
    for (int m = 0; m < 8; ++m) { acc[m][0]=0; acc[m][1]=0; acc[m][2]=0; acc[m][3]=0; }

    for (int kt = 0; kt < 192; ++kt) {
        CP_WAIT0; __syncthreads();
        const float* Ac = As[kt & 1];
        const float* Bc = Bs[kt & 1];
        float av[8];
        const bool nxt = (kt < 191);
        if (nxt) {
            int k0n = (kt + 1) * 16;
            agen(k0n, av);
            float* Bn = Bs[(kt + 1) & 1];
            cpasync16(su32(&Bn[bkk * 128 + bc4 * 4]),       tW1 + (size_t)(k0n + bkk) * 1024 + n0 + bc4 * 4);
            cpasync16(su32(&Bn[(bkk + 8) * 128 + bc4 * 4]), tW1 + (size_t)(k0n + bkk + 8) * 1024 + n0 + bc4 * 4);
        }
        compute_tile(Ac, Bc, acc, rbase, coff);
        if (nxt) {
            float* An = As[(kt + 1) & 1];
#pragma unroll
            for (int e = 0; e < 8; ++e) An[(rg * 8 + e) * ASTR + kk] = av[e];
            CP_COMMIT;
        }
    }
    float bias[8];
#pragma unroll
    for (int q = 0; q < 8; ++q) bias[q] = tb1[n0 + coff + q];
#pragma unroll
    for (int m = 0; m < 8; ++m) {
        int r = rbase + 4 * m, p = p0 + r;
        if (p >= 6240) continue;
        float o[8];
#pragma unroll
        for (int q = 0; q < 4; ++q) {
            float2 xy = unpack2(acc[m][q]);
            o[2*q]   = fmaxf(xy.x + bias[2*q],   0.f);
            o[2*q+1] = fmaxf(xy.y + bias[2*q+1], 0.f);
        }
        float4* dst = (float4*)&g_h1t[(size_t)p * 1024 + n0 + coff];
        dst[0] = make_float4(o[0], o[1], o[2], o[3]);
        dst[1] = make_float4(o[4], o[5], o[6], o[7]);
    }
}

// =====================================================================
// Text GEMM2
// =====================================================================
__global__ __launch_bounds__(256, 2) void t_gemm2(
    const float* __restrict__ tW2, const float* __restrict__ tb2,
    const float* __restrict__ tW3)
{
    __shared__ float As[2][128 * ASTR];
    __shared__ float Bs[2][16 * 128];
    __shared__ float red[2][128];
    GEMM_IDX;
    const int n0 = blockIdx.x * 128, p0 = blockIdx.y * 128;
    const int ar0 = t >> 2, ak0 = t & 3;
    const int bkk = t >> 5, bc4 = t & 31;
    const int r0c = (p0 + ar0)      < 6240 ? (p0 + ar0)      : 6239;
    const int r1c = (p0 + ar0 + 64) < 6240 ? (p0 + ar0 + 64) : 6239;

    {
        cpasync16(su32(&As[0][ar0 * ASTR + ak0 * 4]),        &g_h1t[(size_t)r0c * 1024 + ak0 * 4]);
        cpasync16(su32(&As[0][(ar0 + 64) * ASTR + ak0 * 4]), &g_h1t[(size_t)r1c * 1024 + ak0 * 4]);
        cpasync16(su32(&Bs[0][bkk * 128 + bc4 * 4]),       tW2 + (size_t)bkk * 1024 + n0 + bc4 * 4);
        cpasync16(su32(&Bs[0][(bkk + 8) * 128 + bc4 * 4]), tW2 + (size_t)(bkk + 8) * 1024 + n0 + bc4 * 4);
        CP_COMMIT;
    }
    ull acc[8][4];
#pragma unroll
    for (int m = 0; m < 8; ++m) { acc[m][0]=0; acc[m][1]=0; acc[m][2]=0; acc[m][3]=0; }

    for (int kt = 0; kt < 64; ++kt) {
        CP_WAIT0; __syncthreads();
        const float* Ac = As[kt & 1];
        const float* Bc = Bs[kt & 1];
        const bool nxt = (kt < 63);
        if (nxt) {
            int k0n = (kt + 1) * 16;
            float* An = As[(kt + 1) & 1];
            float* Bn = Bs[(kt + 1) & 1];
            cpasync16(su32(&An[ar0 * ASTR + ak0 * 4]),        &g_h1t[(size_t)r0c * 1024 + k0n + ak0 * 4]);
            cpasync16(su32(&An[(ar0 + 64) * ASTR + ak0 * 4]), &g_h1t[(size_t)r1c * 1024 + k0n + ak0 * 4]);
            cpasync16(su32(&Bn[bkk * 128 + bc4 * 4]),       tW2 + (size_t)(k0n + bkk) * 1024 + n0 + bc4 * 4);
            cpasync16(su32(&Bn[(bkk + 8) * 128 + bc4 * 4]), tW2 + (size_t)(k0n + bkk + 8) * 1024 + n0 + bc4 * 4);
        }
        compute_tile(Ac, Bc, acc, rbase, coff);
        if (nxt) CP_COMMIT;
    }
    float b2r[8], w3r[8];
#pragma unroll
    for (int q = 0; q < 8; ++q) { b2r[q] = tb2[n0 + coff + q]; w3r[q] = tW3[n0 + coff + q]; }
#pragma unroll
    for (int m = 0; m < 8; ++m) {
        float s = 0.f;
#pragma unroll
        for (int q = 0; q < 4; ++q) {
            float2 xy = unpack2(acc[m][q]);
            s += fmaxf(xy.x + b2r[2*q],   0.f) * w3r[2*q];
            s += fmaxf(xy.y + b2r[2*q+1], 0.f) * w3r[2*q+1];
        }
        s += __shfl_xor_sync(0xffffffffu, s, 4);
        s += __shfl_xor_sync(0xffffffffu, s, 8);
        s += __shfl_xor_sync(0xffffffffu, s, 16);
        if (l < 4) red[wc][rbase + 4 * m] = s;
    }
    __syncthreads();
    if (t < 128 && p0 + t < 6240)
        g_partt[(size_t)(p0 + t) * 8 + blockIdx.x] = red[0][t] + red[1][t];
}

// =====================================================================
// Finalize + reductions
// =====================================================================
__global__ void fin_g(const float* __restrict__ smask, const float* __restrict__ imask,
                      const float* __restrict__ gb3, float* __restrict__ out_g)
{
    int p = blockIdx.x * 256 + threadIdx.x;
    float s = gb3[0];
#pragma unroll
    for (int nb = 0; nb < 8; ++nb) s += g_part[(size_t)p * 8 + nb];
    int i = p / 160, j = p - i * 160;
    out_g[p] = s * (smask[i] * imask[j]);
}

__global__ void fin_t(const float* __restrict__ tb3, float* __restrict__ out_t)
{
    int p = blockIdx.x * 256 + threadIdx.x;
    if (p >= 6240) return;
    float s = tb3[0];
#pragma unroll
    for (int nb = 0; nb < 8; ++nb) s += g_partt[(size_t)p * 8 + nb];
    out_t[p] = s;
}

__global__ void sreduce_kernel(const float* __restrict__ gsc) {
    __shared__ float red[256];
    int k = blockIdx.x;
    float s = 0.f;
    for (int idx = threadIdx.x; idx < 800; idx += 256) s += gsc[k * 800 + idx];
    red[threadIdx.x] = s;
    __syncthreads();
    for (int st = 128; st > 0; st >>= 1) {
        if (threadIdx.x < st) red[threadIdx.x] += red[threadIdx.x + st];
        __syncthreads();
    }
    if (threadIdx.x == 0) g_S[k] = red[0];
}

__global__ void loss_kernel(float* __restrict__ out) {
    if (threadIdx.x == 0) {
        float S[64];
        for (int k = 0; k < 64; ++k) S[k] = g_S[k];
        float lr = 0.f, lc = 0.f, tot = 0.f;
        for (int r = 0; r < 8; ++r) {
            float m = -1e30f;
            for (int c = 0; c < 8; ++c) m = fmaxf(m, S[r * 8 + c]);
            float e = 0.f;
            for (int c = 0; c < 8; ++c) e += expf(S[r * 8 + c] - m);
            lr += m + logf(e);
        }
        for (int c = 0; c < 8; ++c) {
            float m = -1e30f;
            for (int r = 0; r < 8; ++r) m = fmaxf(m, S[r * 8 + c]);
            float e = 0.f;
            for (int r = 0; r < 8; ++r) e += expf(S[r * 8 + c] - m);
            lc += m + logf(e);
        }
        for (int k = 0; k < 64; ++k) tot += S[k];
        out[0] = -(2.f * tot - 8.f * (lr + lc)) / 8.f;
    }
}

// =====================================================================
extern "C" void kernel_launch(void* const* d_in, const int* in_sizes, int n_in,
                              void* d_out, int out_size) {
    (void)in_sizes; (void)n_in; (void)out_size;
    const float* span  = (const float*)d_in[0];
    const float* img   = (const float*)d_in[1];
    const float* smask = (const float*)d_in[2];
    const float* imask = (const float*)d_in[3];
    const float* tW1 = (const float*)d_in[4];  const float* tb1 = (const float*)d_in[5];
    const float* tW2 = (const float*)d_in[6];  const float* tb2 = (const float*)d_in[7];
    const float* tW3 = (const float*)d_in[8];  const float* tb3 = (const float*)d_in[9];
    const float* gW1 = (const float*)d_in[10]; const float* gb1 = (const float*)d_in[11];
    const float* gW2 = (const float*)d_in[12]; const float* gb2 = (const float*)d_in[13];
    const float* gW3 = (const float*)d_in[14]; const float* gb3 = (const float*)d_in[15];
    float* out = (float*)d_out;

    fwvw_kernel<<<dim3(15, 8), 256>>>(span, img, gW1);
    g_gemm1<<<dim3(8, 400), 256>>>(span, img, gW1, gb1);
    g_gemm2<<<dim3(8, 400), 256>>>(gW2, gb2, gW3);
    t_gemm1<<<dim3(8, 49), 256>>>(span, tW1, tb1);
    t_gemm2<<<dim3(8, 49), 256>>>(tW2, tb2, tW3);
    fin_g<<<200, 256>>>(smask, imask, gb3, out + 1);
    fin_t<<<25, 256>>>(tb3, out + 1 + 51200);
    sreduce_kernel<<<64, 256>>>(out + 1);
    loss_kernel<<<1, 32>>>(out);
}

// round 5
// speedup vs baseline: 1.9049x; 1.9049x over previous
#include <cuda_runtime.h>
#include <cuda_bf16.h>
#include <cstdint>

typedef unsigned long long ull;
typedef unsigned int u32;

// ---------------- helpers ----------------
__device__ __forceinline__ ull pack2(float x, float y) {
    ull r; asm("mov.b64 %0, {%1, %2};" : "=l"(r) : "f"(x), "f"(y)); return r;
}
__device__ __forceinline__ void fma2(ull& acc, ull a, ull b) {
    asm("fma.rn.f32x2 %0, %1, %2, %0;" : "+l"(acc) : "l"(a), "l"(b));
}
__device__ __forceinline__ float2 unpack2(ull a) {
    float2 r; asm("mov.b64 {%0, %1}, %2;" : "=f"(r.x), "=f"(r.y) : "l"(a)); return r;
}
__device__ __forceinline__ u32 su32(const void* p) {
    u32 a;
    asm("{ .reg .u64 t; cvta.to.shared.u64 t, %1; cvt.u32.u64 %0, t; }" : "=r"(a) : "l"(p));
    return a;
}
__device__ __forceinline__ void cpa16(u32 s, const void* g) {
    asm volatile("cp.async.cg.shared.global [%0], [%1], 16;" :: "r"(s), "l"(g));
}
#define CP_COMMIT asm volatile("cp.async.commit_group;")
#define CP_WAIT0  asm volatile("cp.async.wait_group 0;")

#define LDSM4(r, a) \
    asm volatile("ldmatrix.sync.aligned.m8n8.x4.shared.b16 {%0,%1,%2,%3}, [%4];" \
        : "=r"((r)[0]), "=r"((r)[1]), "=r"((r)[2]), "=r"((r)[3]) : "r"(a))
#define LDSM4T(r, a) \
    asm volatile("ldmatrix.sync.aligned.m8n8.x4.trans.shared.b16 {%0,%1,%2,%3}, [%4];" \
        : "=r"((r)[0]), "=r"((r)[1]), "=r"((r)[2]), "=r"((r)[3]) : "r"(a))

__device__ __forceinline__ void mma_bf16(float* c, const u32* a, u32 b0, u32 b1) {
    asm volatile(
        "mma.sync.aligned.m16n8k16.row.col.f32.bf16.bf16.f32 "
        "{%0,%1,%2,%3}, {%4,%5,%6,%7}, {%8,%9}, {%0,%1,%2,%3};"
        : "+f"(c[0]), "+f"(c[1]), "+f"(c[2]), "+f"(c[3])
        : "r"(a[0]), "r"(a[1]), "r"(a[2]), "r"(a[3]), "r"(b0), "r"(b1));
}
__device__ __forceinline__ void bsplit2(float a, float b, u32& hi, u32& lo) {
    __nv_bfloat16 ha = __float2bfloat16_rn(a), hb = __float2bfloat16_rn(b);
    __nv_bfloat16 la = __float2bfloat16_rn(a - __bfloat162float(ha));
    __nv_bfloat16 lb = __float2bfloat16_rn(b - __bfloat162float(hb));
    hi = (u32)__bfloat16_as_ushort(ha) | ((u32)__bfloat16_as_ushort(hb) << 16);
    lo = (u32)__bfloat16_as_ushort(la) | ((u32)__bfloat16_as_ushort(lb) << 16);
}

// ---------------- scratch ----------------
__device__ float g_FWVW[480 * 1024];
__device__ float g_S[64];
__device__ __nv_bfloat16 g_Wp[2][1024 * 1024];
__device__ __nv_bfloat16 g_W2[2][1024 * 1024];
__device__ __nv_bfloat16 g_tW1[2][(size_t)3072 * 1024];
__device__ __nv_bfloat16 g_tW2[2][1024 * 1024];
__device__ __nv_bfloat16 g_h1hi[(size_t)51200 * 1024];
__device__ __nv_bfloat16 g_h1lo[(size_t)51200 * 1024];
__device__ __nv_bfloat16 g_h1thi[(size_t)6272 * 1024];
__device__ __nv_bfloat16 g_h1tlo[(size_t)6272 * 1024];
__device__ float g_part[(size_t)51200 * 8];
__device__ float g_partt[6240 * 8];

// =====================================================================
// weight bf16 hi/lo split (same [k][n] layout, no transpose)
// =====================================================================
template<int WSEL>
__global__ void wconv(const float* __restrict__ W, int n)
{
    __nv_bfloat16 *hi, *lo;
    if constexpr (WSEL == 0) { hi = g_Wp[0];  lo = g_Wp[1];  }
    else if constexpr (WSEL == 1) { hi = g_W2[0];  lo = g_W2[1];  }
    else if constexpr (WSEL == 2) { hi = g_tW1[0]; lo = g_tW1[1]; }
    else { hi = g_tW2[0]; lo = g_tW2[1]; }
    int i = blockIdx.x * 256 + threadIdx.x;
    if (i < n) {
        float x = W[i];
        __nv_bfloat16 h = __float2bfloat16_rn(x);
        __nv_bfloat16 l = __float2bfloat16_rn(x - __bfloat162float(h));
        hi[i] = h; lo[i] = l;
    }
}

// =====================================================================
// FW/VW precompute (exact fp32)
// =====================================================================
__global__ __launch_bounds__(256) void fwvw_kernel(
    const float* __restrict__ span, const float* __restrict__ img,
    const float* __restrict__ gW1)
{
    __shared__ float At[32 * 33];
    __shared__ float Wt[32 * 128];
    const int g0 = blockIdx.x * 32;
    const int n0 = blockIdx.y * 128;
    const int t = threadIdx.x, tx = t & 15, ty = t >> 4;
    const bool isv = (g0 >= 320);
    const float* Wsrc = gW1 + (isv ? (size_t)1024 * 1024 : 0);

    ull acc[8] = {0,0,0,0,0,0,0,0};
    for (int kt = 0; kt < 32; ++kt) {
#pragma unroll
        for (int it = 0; it < 4; ++it) {
            int idx = t + it * 256; int k = idx & 31, r = idx >> 5;
            int g = g0 + r;
            const float* srow = isv ? (img + (size_t)(g - 320) * 1024) : (span + (size_t)g * 1024);
            At[k * 33 + r] = srow[kt * 32 + k];
        }
#pragma unroll
        for (int it = 0; it < 4; ++it) {
            int idx = t + it * 256; int kk = idx >> 5, c4 = idx & 31;
            ((float4*)Wt)[kk * 32 + c4] =
                *(const float4*)&Wsrc[(size_t)(kt * 32 + kk) * 1024 + n0 + c4 * 4];
        }
        __syncthreads();
#pragma unroll
        for (int k = 0; k < 32; ++k) {
            float a0s = At[k * 33 + 2 * ty], a1s = At[k * 33 + 2 * ty + 1];
            ull A0 = pack2(a0s, a0s), A1 = pack2(a1s, a1s);
            const ull* wrow = (const ull*)&Wt[k * 128 + tx * 8];
            ull w0 = wrow[0], w1 = wrow[1], w2 = wrow[2], w3 = wrow[3];
            fma2(acc[0], A0, w0); fma2(acc[1], A0, w1); fma2(acc[2], A0, w2); fma2(acc[3], A0, w3);
            fma2(acc[4], A1, w0); fma2(acc[5], A1, w1); fma2(acc[6], A1, w2); fma2(acc[7], A1, w3);
        }
        __syncthreads();
    }
#pragma unroll
    for (int dr = 0; dr < 2; ++dr) {
        int g = g0 + 2 * ty + dr;
#pragma unroll
        for (int cp = 0; cp < 4; ++cp) {
            float2 v = unpack2(acc[dr * 4 + cp]);
            int n = n0 + tx * 8 + cp * 2;
            g_FWVW[(size_t)g * 1024 + n] = v.x;
            g_FWVW[(size_t)g * 1024 + n + 1] = v.y;
        }
    }
}

// =====================================================================
// HMMA GEMM. MODE: 0 ground L1, 1 ground L2, 2 text L1 (K=3072), 3 text L2
// CTA tile 128x128, 8 warps (2Mx4N), warp tile 64x32, bf16 hi/lo 3-pass.
// smem stage: A_hi[128][40]b16, A_lo, B_hi[32][136]b16, B_lo. 2 stages.
// =====================================================================
#define AHO 0
#define ALO 10240
#define BHO 20480
#define BLO 29184
#define STG_SZ 37888
#define RED_O 75776
#define HM_SMEM (75776 + 2048)

template<int MODE>
__global__ __launch_bounds__(256) void hmma_kernel(
    const float* __restrict__ span, const float* __restrict__ img,
    const float* __restrict__ bias1, const float* __restrict__ w3v)
{
    constexpr int KB  = (MODE == 2) ? 3072 : 1024;
    constexpr int NCH = KB / 32;
    extern __shared__ char sm[];
    const u32 smb = su32(sm);
    float* red = (float*)(sm + RED_O);
    const int t = threadIdx.x, w = t >> 5, lane = t & 31;
    const int wm = w >> 2, wn = w & 3;
    const int n0 = blockIdx.x * 128, p0 = blockIdx.y * 128;

    const __nv_bfloat16 *Wh, *Wl;
    if constexpr (MODE == 0) { Wh = g_Wp[0];  Wl = g_Wp[1];  }
    else if constexpr (MODE == 1) { Wh = g_W2[0];  Wl = g_W2[1];  }
    else if constexpr (MODE == 2) { Wh = g_tW1[0]; Wl = g_tW1[1]; }
    else { Wh = g_tW2[0]; Wl = g_tW2[1]; }
    const __nv_bfloat16 *Ah = nullptr, *Al = nullptr;
    if constexpr (MODE == 1) { Ah = g_h1hi;  Al = g_h1lo;  }
    if constexpr (MODE == 3) { Ah = g_h1thi; Al = g_h1tlo; }

    // ---- A-gen setup (MODE 0/2): thread -> row gr, k-half gh ----
    const int gr = t >> 1, gh = t & 1;
    const float *fp = nullptr, *vp = nullptr;
    if constexpr (MODE == 0) {
        int p = p0 + gr, i = p / 160, j = p - i * 160;
        fp = span + (size_t)i * 1024 + gh * 16;
        vp = img  + (size_t)j * 1024 + gh * 16;
    }
    if constexpr (MODE == 2) {
        int p = p0 + gr; if (p > 6239) p = 6239;
        int b = p / 780, q = p - b * 780, fi = 0, cnt = 39, rem = q;
        while (rem >= cnt) { rem -= cnt; fi++; cnt--; }
        fp = span + (size_t)(b * 40 + fi) * 1024 + gh * 16;
        vp = span + (size_t)(b * 40 + fi + 1 + rem) * 1024 + gh * 16;
    }

    // ldmatrix lane addressing
    const int lr = lane & 15, lh = lane >> 4;              // A
    const u32 a_lane = (u32)((wm * 64 + lr) * 80 + lh * 16);
    const int bg = lane >> 3, bk = lane & 7;               // B (.trans)
    const u32 b_lane = (u32)(((bg & 1) * 8 + bk) * 272 + (wn * 32 + (bg >> 1) * 8) * 2);

    float acc[4][4][4];
#pragma unroll
    for (int am = 0; am < 4; ++am)
#pragma unroll
        for (int an = 0; an < 4; ++an) { acc[am][an][0]=0.f; acc[am][an][1]=0.f; acc[am][an][2]=0.f; acc[am][an][3]=0.f; }

    // ---- stage fill helpers (as code blocks) ----
    // B fill: 32 rows x 16 chunks x 2 arrays = 1024 cp.async
    // A fill (MODE 1/3): 128 rows x 4 chunks x 2 arrays = 1024 cp.async
    // A gen (MODE 0/2): regs -> split -> STS

    // prologue: fill stage 0 (chunk 0)
    {
        const u32 sb = smb;
#pragma unroll
        for (int it = 0; it < 4; ++it) {
            int idx = t + it * 256;
            int m = idx >> 9, rem = idx & 511, row = rem >> 4, cc = rem & 15;
            const __nv_bfloat16* src = (m ? Wl : Wh) + (size_t)row * 1024 + n0 + cc * 8;
            cpa16(sb + (m ? BLO : BHO) + row * 272 + cc * 16, src);
        }
        if constexpr (MODE == 1 || MODE == 3) {
#pragma unroll
            for (int it = 0; it < 4; ++it) {
                int idx = t + it * 256;
                int m = idx >> 9, rem = idx & 511, row = rem >> 2, cc = rem & 3;
                int prow = p0 + row; if (MODE == 3 && prow > 6239) prow = 6239;
                const __nv_bfloat16* src = (m ? Al : Ah) + (size_t)prow * 1024 + cc * 8;
                cpa16(sb + (m ? ALO : AHO) + row * 80 + cc * 16, src);
            }
        } else {
            float pr[16];
            const float *fa = fp, *vb = vp;
            int reg = 0;
            if constexpr (MODE == 2) reg = 0;
#pragma unroll
            for (int q = 0; q < 4; ++q) {
                float4 x = *(const float4*)(fa + q * 4);
                float4 y = *(const float4*)(vb + q * 4);
                float4 z;
                if (MODE == 0 || reg == 2) { z.x=x.x*y.x; z.y=x.y*y.y; z.z=x.z*y.z; z.w=x.w*y.w; }
                else if (reg == 0) z = x; else z = y;
                pr[q*4+0]=z.x; pr[q*4+1]=z.y; pr[q*4+2]=z.z; pr[q*4+3]=z.w;
            }
            u32 hw[8], lw[8];
#pragma unroll
            for (int q = 0; q < 8; ++q) bsplit2(pr[2*q], pr[2*q+1], hw[q], lw[q]);
            u32 da = sb + AHO + gr * 80 + gh * 32;
            asm volatile("st.shared.v4.b32 [%0], {%1,%2,%3,%4};" :: "r"(da), "r"(hw[0]), "r"(hw[1]), "r"(hw[2]), "r"(hw[3]));
            asm volatile("st.shared.v4.b32 [%0], {%1,%2,%3,%4};" :: "r"(da+16), "r"(hw[4]), "r"(hw[5]), "r"(hw[6]), "r"(hw[7]));
            u32 dl = sb + ALO + gr * 80 + gh * 32;
            asm volatile("st.shared.v4.b32 [%0], {%1,%2,%3,%4};" :: "r"(dl), "r"(lw[0]), "r"(lw[1]), "r"(lw[2]), "r"(lw[3]));
            asm volatile("st.shared.v4.b32 [%0], {%1,%2,%3,%4};" :: "r"(dl+16), "r"(lw[4]), "r"(lw[5]), "r"(lw[6]), "r"(lw[7]));
        }
        CP_COMMIT;
    }

    for (int c = 0; c < NCH; ++c) {
        CP_WAIT0;
        __syncthreads();
        const u32 sb = smb + (u32)(c & 1) * STG_SZ;
        const u32 nb = smb + (u32)((c + 1) & 1) * STG_SZ;
        const bool nxt = (c + 1 < NCH);
        float xr[16], yr[16];
        if (nxt) {
            int k0n = (c + 1) * 32;
            // B cp.async for next chunk
#pragma unroll
            for (int it = 0; it < 4; ++it) {
                int idx = t + it * 256;
                int m = idx >> 9, rem = idx & 511, row = rem >> 4, cc = rem & 15;
                const __nv_bfloat16* src = (m ? Wl : Wh) + (size_t)(k0n + row) * 1024 + n0 + cc * 8;
                cpa16(nb + (m ? BLO : BHO) + row * 272 + cc * 16, src);
            }
            if constexpr (MODE == 1 || MODE == 3) {
#pragma unroll
                for (int it = 0; it < 4; ++it) {
                    int idx = t + it * 256;
                    int m = idx >> 9, rem = idx & 511, row = rem >> 2, cc = rem & 3;
                    int prow = p0 + row; if (MODE == 3 && prow > 6239) prow = 6239;
                    const __nv_bfloat16* src = (m ? Al : Ah) + (size_t)prow * 1024 + k0n + cc * 8;
                    cpa16(nb + (m ? ALO : AHO) + row * 80 + cc * 16, src);
                }
            } else {
                int db = k0n & 1023;
                const float *fa = fp + db, *vb = vp + db;
#pragma unroll
                for (int q = 0; q < 4; ++q) {
                    float4 x = *(const float4*)(fa + q * 4);
                    float4 y = *(const float4*)(vb + q * 4);
                    xr[q*4+0]=x.x; xr[q*4+1]=x.y; xr[q*4+2]=x.z; xr[q*4+3]=x.w;
                    yr[q*4+0]=y.x; yr[q*4+1]=y.y; yr[q*4+2]=y.z; yr[q*4+3]=y.w;
                }
            }
        }
        // ---- compute: 2 k16 steps ----
#pragma unroll
        for (int ks = 0; ks < 2; ++ks) {
            u32 ah[4][4], al[4][4], bh[2][4], bl[2][4];
#pragma unroll
            for (int am = 0; am < 4; ++am) {
                u32 aaddr = sb + a_lane + (u32)(am * 16 * 80 + ks * 32);
                LDSM4(ah[am], aaddr + AHO);
                LDSM4(al[am], aaddr + ALO);
            }
#pragma unroll
            for (int gn = 0; gn < 2; ++gn) {
                u32 baddr = sb + b_lane + (u32)(ks * 16 * 272 + gn * 32);
                LDSM4T(bh[gn], baddr + BHO);
                LDSM4T(bl[gn], baddr + BLO);
            }
#pragma unroll
            for (int am = 0; am < 4; ++am)
#pragma unroll
                for (int gn = 0; gn < 2; ++gn)
#pragma unroll
                    for (int sub = 0; sub < 2; ++sub) {
                        float* cc4 = acc[am][gn * 2 + sub];
                        mma_bf16(cc4, ah[am], bh[gn][sub*2], bh[gn][sub*2+1]);
                        mma_bf16(cc4, ah[am], bl[gn][sub*2], bl[gn][sub*2+1]);
                        mma_bf16(cc4, al[am], bh[gn][sub*2], bh[gn][sub*2+1]);
                    }
        }
        if (nxt) {
            if constexpr (MODE == 0 || MODE == 2) {
                int reg = ((c + 1) * 32) >> 10;
                float pr[16];
#pragma unroll
                for (int q = 0; q < 16; ++q) {
                    float z;
                    if (MODE == 0 || reg == 2) z = xr[q] * yr[q];
                    else if (reg == 0) z = xr[q]; else z = yr[q];
                    pr[q] = z;
                }
                u32 hw[8], lw[8];
#pragma unroll
                for (int q = 0; q < 8; ++q) bsplit2(pr[2*q], pr[2*q+1], hw[q], lw[q]);
                u32 da = nb + AHO + gr * 80 + gh * 32;
                asm volatile("st.shared.v4.b32 [%0], {%1,%2,%3,%4};" :: "r"(da), "r"(hw[0]), "r"(hw[1]), "r"(hw[2]), "r"(hw[3]));
                asm volatile("st.shared.v4.b32 [%0], {%1,%2,%3,%4};" :: "r"(da+16), "r"(hw[4]), "r"(hw[5]), "r"(hw[6]), "r"(hw[7]));
                u32 dl = nb + ALO + gr * 80 + gh * 32;
                asm volatile("st.shared.v4.b32 [%0], {%1,%2,%3,%4};" :: "r"(dl), "r"(lw[0]), "r"(lw[1]), "r"(lw[2]), "r"(lw[3]));
                asm volatile("st.shared.v4.b32 [%0], {%1,%2,%3,%4};" :: "r"(dl+16), "r"(lw[4]), "r"(lw[5]), "r"(lw[6]), "r"(lw[7]));
            }
        }
        CP_COMMIT;
    }

    // ---------------- epilogue ----------------
    if constexpr (MODE == 0 || MODE == 2) {
        __nv_bfloat16* OH = (MODE == 0) ? g_h1hi : g_h1thi;
        __nv_bfloat16* OL = (MODE == 0) ? g_h1lo : g_h1tlo;
#pragma unroll
        for (int am = 0; am < 4; ++am) {
            int row0 = p0 + wm * 64 + am * 16 + (lane >> 2);
#pragma unroll
            for (int h = 0; h < 2; ++h) {
                int p = row0 + h * 8;
                bool act = (MODE == 0) || (p < 6240);
                const float *fw = nullptr, *vw = nullptr;
                if constexpr (MODE == 0) {
                    int i = p / 160, j = p - i * 160;
                    fw = g_FWVW + (size_t)i * 1024;
                    vw = g_FWVW + (size_t)(320 + j) * 1024;
                }
#pragma unroll
                for (int an = 0; an < 4; ++an) {
                    int col = n0 + wn * 32 + an * 8 + (lane & 3) * 2;
                    float v0 = acc[am][an][h * 2 + 0];
                    float v1 = acc[am][an][h * 2 + 1];
                    float x0 = v0 + bias1[col], x1 = v1 + bias1[col + 1];
                    if (MODE == 0) { x0 += fw[col] + vw[col]; x1 += fw[col + 1] + vw[col + 1]; }
                    x0 = fmaxf(x0, 0.f); x1 = fmaxf(x1, 0.f);
                    u32 hp, lp; bsplit2(x0, x1, hp, lp);
                    if (act) {
                        *(u32*)(OH + (size_t)p * 1024 + col) = hp;
                        *(u32*)(OL + (size_t)p * 1024 + col) = lp;
                    }
                }
            }
        }
    } else {
        float s[8];
#pragma unroll
        for (int q = 0; q < 8; ++q) s[q] = 0.f;
#pragma unroll
        for (int am = 0; am < 4; ++am)
#pragma unroll
            for (int an = 0; an < 4; ++an) {
                int col = n0 + wn * 32 + an * 8 + (lane & 3) * 2;
                float b0 = bias1[col], b1v = bias1[col + 1];
                float w0 = w3v[col],  w1v = w3v[col + 1];
                s[am*2+0] += fmaxf(acc[am][an][0] + b0, 0.f) * w0 + fmaxf(acc[am][an][1] + b1v, 0.f) * w1v;
                s[am*2+1] += fmaxf(acc[am][an][2] + b0, 0.f) * w0 + fmaxf(acc[am][an][3] + b1v, 0.f) * w1v;
            }
#pragma unroll
        for (int q = 0; q < 8; ++q) {
            float v = s[q];
            v += __shfl_xor_sync(0xffffffffu, v, 1);
            v += __shfl_xor_sync(0xffffffffu, v, 2);
            if ((lane & 3) == 0) {
                int rowl = wm * 64 + (q >> 1) * 16 + (lane >> 2) + (q & 1) * 8;
                red[wn * 128 + rowl] = v;
            }
        }
        __syncthreads();
        if (t < 128) {
            int pp = p0 + t;
            float v = red[t] + red[128 + t] + red[256 + t] + red[384 + t];
            if (MODE == 1) g_part[(size_t)pp * 8 + blockIdx.x] = v;
            else if (pp < 6240) g_partt[(size_t)pp * 8 + blockIdx.x] = v;
        }
    }
}

// =====================================================================
// finalize + reductions
// =====================================================================
__global__ void fin_g(const float* __restrict__ smask, const float* __restrict__ imask,
                      const float* __restrict__ gb3, float* __restrict__ out_g)
{
    int p = blockIdx.x * 256 + threadIdx.x;
    float s = gb3[0];
#pragma unroll
    for (int nb = 0; nb < 8; ++nb) s += g_part[(size_t)p * 8 + nb];
    int i = p / 160, j = p - i * 160;
    out_g[p] = s * (smask[i] * imask[j]);
}

__global__ void fin_t(const float* __restrict__ tb3, float* __restrict__ out_t)
{
    int p = blockIdx.x * 256 + threadIdx.x;
    if (p >= 6240) return;
    float s = tb3[0];
#pragma unroll
    for (int nb = 0; nb < 8; ++nb) s += g_partt[(size_t)p * 8 + nb];
    out_t[p] = s;
}

__global__ void sreduce_kernel(const float* __restrict__ gsc) {
    __shared__ float red[256];
    int k = blockIdx.x;
    float s = 0.f;
    for (int idx = threadIdx.x; idx < 800; idx += 256) s += gsc[k * 800 + idx];
    red[threadIdx.x] = s;
    __syncthreads();
    for (int st = 128; st > 0; st >>= 1) {
        if (threadIdx.x < st) red[threadIdx.x] += red[threadIdx.x + st];
        __syncthreads();
    }
    if (threadIdx.x == 0) g_S[k] = red[0];
}

__global__ void loss_kernel(float* __restrict__ out) {
    if (threadIdx.x == 0) {
        float S[64];
        for (int k = 0; k < 64; ++k) S[k] = g_S[k];
        float lr = 0.f, lc = 0.f, tot = 0.f;
        for (int r = 0; r < 8; ++r) {
            float m = -1e30f;
            for (int c = 0; c < 8; ++c) m = fmaxf(m, S[r * 8 + c]);
            float e = 0.f;
            for (int c = 0; c < 8; ++c) e += expf(S[r * 8 + c] - m);
            lr += m + logf(e);
        }
        for (int c = 0; c < 8; ++c) {
            float m = -1e30f;
            for (int r = 0; r < 8; ++r) m = fmaxf(m, S[r * 8 + c]);
            float e = 0.f;
            for (int r = 0; r < 8; ++r) e += expf(S[r * 8 + c] - m);
            lc += m + logf(e);
        }
        for (int k = 0; k < 64; ++k) tot += S[k];
        out[0] = -(2.f * tot - 8.f * (lr + lc)) / 8.f;
    }
}

// =====================================================================
extern "C" void kernel_launch(void* const* d_in, const int* in_sizes, int n_in,
                              void* d_out, int out_size) {
    (void)in_sizes; (void)n_in; (void)out_size;
    const float* span  = (const float*)d_in[0];
    const float* img   = (const float*)d_in[1];
    const float* smask = (const float*)d_in[2];
    const float* imask = (const float*)d_in[3];
    const float* tW1 = (const float*)d_in[4];  const float* tb1 = (const float*)d_in[5];
    const float* tW2 = (const float*)d_in[6];  const float* tb2 = (const float*)d_in[7];
    const float* tW3 = (const float*)d_in[8];  const float* tb3 = (const float*)d_in[9];
    const float* gW1 = (const float*)d_in[10]; const float* gb1 = (const float*)d_in[11];
    const float* gW2 = (const float*)d_in[12]; const float* gb2 = (const float*)d_in[13];
    const float* gW3 = (const float*)d_in[14]; const float* gb3 = (const float*)d_in[15];
    float* out = (float*)d_out;

    cudaFuncSetAttribute(hmma_kernel<0>, cudaFuncAttributeMaxDynamicSharedMemorySize, HM_SMEM);
    cudaFuncSetAttribute(hmma_kernel<1>, cudaFuncAttributeMaxDynamicSharedMemorySize, HM_SMEM);
    cudaFuncSetAttribute(hmma_kernel<2>, cudaFuncAttributeMaxDynamicSharedMemorySize, HM_SMEM);
    cudaFuncSetAttribute(hmma_kernel<3>, cudaFuncAttributeMaxDynamicSharedMemorySize, HM_SMEM);

    wconv<0><<<4096,  256>>>(gW1 + (size_t)2 * 1024 * 1024, 1024 * 1024);
    wconv<1><<<4096,  256>>>(gW2, 1024 * 1024);
    wconv<2><<<12288, 256>>>(tW1, 3072 * 1024);
    wconv<3><<<4096,  256>>>(tW2, 1024 * 1024);
    fwvw_kernel<<<dim3(15, 8), 256>>>(span, img, gW1);

    hmma_kernel<0><<<dim3(8, 400), 256, HM_SMEM>>>(span, img, gb1, nullptr);
    hmma_kernel<1><<<dim3(8, 400), 256, HM_SMEM>>>(nullptr, nullptr, gb2, gW3);
    hmma_kernel<2><<<dim3(8, 49),  256, HM_SMEM>>>(span, nullptr, tb1, nullptr);
    hmma_kernel<3><<<dim3(8, 49),  256, HM_SMEM>>>(nullptr, nullptr, tb2, tW3);

    fin_g<<<200, 256>>>(smask, imask, gb3, out + 1);
    fin_t<<<25, 256>>>(tb3, out + 1 + 51200);
    sreduce_kernel<<<64, 256>>>(out + 1);
    loss_kernel<<<1, 32>>>(out);
}

// round 6
// speedup vs baseline: 1.9237x; 1.0099x over previous
#include <cuda_runtime.h>
#include <cuda_bf16.h>
#include <cstdint>

typedef unsigned long long ull;
typedef unsigned int u32;

// ---------------- helpers ----------------
__device__ __forceinline__ ull pack2(float x, float y) {
    ull r; asm("mov.b64 %0, {%1, %2};" : "=l"(r) : "f"(x), "f"(y)); return r;
}
__device__ __forceinline__ void fma2(ull& acc, ull a, ull b) {
    asm("fma.rn.f32x2 %0, %1, %2, %0;" : "+l"(acc) : "l"(a), "l"(b));
}
__device__ __forceinline__ float2 unpack2(ull a) {
    float2 r; asm("mov.b64 {%0, %1}, %2;" : "=f"(r.x), "=f"(r.y) : "l"(a)); return r;
}
__device__ __forceinline__ u32 su32(const void* p) {
    u32 a;
    asm("{ .reg .u64 t; cvta.to.shared.u64 t, %1; cvt.u32.u64 %0, t; }" : "=r"(a) : "l"(p));
    return a;
}
__device__ __forceinline__ void cpa16(u32 s, const void* g) {
    asm volatile("cp.async.cg.shared.global [%0], [%1], 16;" :: "r"(s), "l"(g));
}
#define CP_COMMIT asm volatile("cp.async.commit_group;")
#define CP_WAIT2  asm volatile("cp.async.wait_group 2;")

#define LDSM4(r, a) \
    asm volatile("ldmatrix.sync.aligned.m8n8.x4.shared.b16 {%0,%1,%2,%3}, [%4];" \
        : "=r"((r)[0]), "=r"((r)[1]), "=r"((r)[2]), "=r"((r)[3]) : "r"(a))
#define LDSM4T(r, a) \
    asm volatile("ldmatrix.sync.aligned.m8n8.x4.trans.shared.b16 {%0,%1,%2,%3}, [%4];" \
        : "=r"((r)[0]), "=r"((r)[1]), "=r"((r)[2]), "=r"((r)[3]) : "r"(a))

__device__ __forceinline__ void mma_bf16(float* c, const u32* a, u32 b0, u32 b1) {
    asm volatile(
        "mma.sync.aligned.m16n8k16.row.col.f32.bf16.bf16.f32 "
        "{%0,%1,%2,%3}, {%4,%5,%6,%7}, {%8,%9}, {%0,%1,%2,%3};"
        : "+f"(c[0]), "+f"(c[1]), "+f"(c[2]), "+f"(c[3])
        : "r"(a[0]), "r"(a[1]), "r"(a[2]), "r"(a[3]), "r"(b0), "r"(b1));
}
__device__ __forceinline__ void bsplit2(float a, float b, u32& hi, u32& lo) {
    __nv_bfloat16 ha = __float2bfloat16_rn(a), hb = __float2bfloat16_rn(b);
    __nv_bfloat16 la = __float2bfloat16_rn(a - __bfloat162float(ha));
    __nv_bfloat16 lb = __float2bfloat16_rn(b - __bfloat162float(hb));
    hi = (u32)__bfloat16_as_ushort(ha) | ((u32)__bfloat16_as_ushort(hb) << 16);
    lo = (u32)__bfloat16_as_ushort(la) | ((u32)__bfloat16_as_ushort(lb) << 16);
}

// ---------------- scratch ----------------
__device__ float g_FWVW[480 * 1024];
__device__ float g_S[64];
__device__ __nv_bfloat16 g_Wp[2][1024 * 1024];
__device__ __nv_bfloat16 g_W2[2][1024 * 1024];
__device__ __nv_bfloat16 g_tW1[2][(size_t)3072 * 1024];
__device__ __nv_bfloat16 g_tW2[2][1024 * 1024];
__device__ __nv_bfloat16 g_h1hi[(size_t)51200 * 1024];
__device__ __nv_bfloat16 g_h1lo[(size_t)51200 * 1024];
__device__ __nv_bfloat16 g_h1thi[(size_t)6272 * 1024];
__device__ __nv_bfloat16 g_h1tlo[(size_t)6272 * 1024];
__device__ float g_part[(size_t)51200 * 8];
__device__ float g_partt[6240 * 8];

// =====================================================================
// weight bf16 hi/lo split
// =====================================================================
template<int WSEL>
__global__ void wconv(const float* __restrict__ W, int n)
{
    __nv_bfloat16 *hi, *lo;
    if constexpr (WSEL == 0) { hi = g_Wp[0];  lo = g_Wp[1];  }
    else if constexpr (WSEL == 1) { hi = g_W2[0];  lo = g_W2[1];  }
    else if constexpr (WSEL == 2) { hi = g_tW1[0]; lo = g_tW1[1]; }
    else { hi = g_tW2[0]; lo = g_tW2[1]; }
    int i = blockIdx.x * 256 + threadIdx.x;
    if (i < n) {
        float x = W[i];
        __nv_bfloat16 h = __float2bfloat16_rn(x);
        __nv_bfloat16 l = __float2bfloat16_rn(x - __bfloat162float(h));
        hi[i] = h; lo[i] = l;
    }
}

// =====================================================================
// FW/VW precompute (exact fp32)
// =====================================================================
__global__ __launch_bounds__(256) void fwvw_kernel(
    const float* __restrict__ span, const float* __restrict__ img,
    const float* __restrict__ gW1)
{
    __shared__ float At[32 * 33];
    __shared__ float Wt[32 * 128];
    const int g0 = blockIdx.x * 32;
    const int n0 = blockIdx.y * 128;
    const int t = threadIdx.x, tx = t & 15, ty = t >> 4;
    const bool isv = (g0 >= 320);
    const float* Wsrc = gW1 + (isv ? (size_t)1024 * 1024 : 0);

    ull acc[8] = {0,0,0,0,0,0,0,0};
    for (int kt = 0; kt < 32; ++kt) {
#pragma unroll
        for (int it = 0; it < 4; ++it) {
            int idx = t + it * 256; int k = idx & 31, r = idx >> 5;
            int g = g0 + r;
            const float* srow = isv ? (img + (size_t)(g - 320) * 1024) : (span + (size_t)g * 1024);
            At[k * 33 + r] = srow[kt * 32 + k];
        }
#pragma unroll
        for (int it = 0; it < 4; ++it) {
            int idx = t + it * 256; int kk = idx >> 5, c4 = idx & 31;
            ((float4*)Wt)[kk * 32 + c4] =
                *(const float4*)&Wsrc[(size_t)(kt * 32 + kk) * 1024 + n0 + c4 * 4];
        }
        __syncthreads();
#pragma unroll
        for (int k = 0; k < 32; ++k) {
            float a0s = At[k * 33 + 2 * ty], a1s = At[k * 33 + 2 * ty + 1];
            ull A0 = pack2(a0s, a0s), A1 = pack2(a1s, a1s);
            const ull* wrow = (const ull*)&Wt[k * 128 + tx * 8];
            ull w0 = wrow[0], w1 = wrow[1], w2 = wrow[2], w3 = wrow[3];
            fma2(acc[0], A0, w0); fma2(acc[1], A0, w1); fma2(acc[2], A0, w2); fma2(acc[3], A0, w3);
            fma2(acc[4], A1, w0); fma2(acc[5], A1, w1); fma2(acc[6], A1, w2); fma2(acc[7], A1, w3);
        }
        __syncthreads();
    }
#pragma unroll
    for (int dr = 0; dr < 2; ++dr) {
        int g = g0 + 2 * ty + dr;
#pragma unroll
        for (int cp = 0; cp < 4; ++cp) {
            float2 v = unpack2(acc[dr * 4 + cp]);
            int n = n0 + tx * 8 + cp * 2;
            g_FWVW[(size_t)g * 1024 + n] = v.x;
            g_FWVW[(size_t)g * 1024 + n + 1] = v.y;
        }
    }
}

// =====================================================================
// HMMA GEMM, 4-stage cp.async pipeline.
// MODE: 0 ground L1, 1 ground L2, 2 text L1 (K=3072), 3 text L2
// CTA tile 128x128, 8 warps (2Mx4N), warp tile 64x32, bf16 hi/lo 3-pass.
// =====================================================================
#define AHO 0
#define ALO 10240
#define BHO 20480
#define BLO 29184
#define STG_SZ 37888
#define RED_O (4 * STG_SZ)
#define HM_SMEM (RED_O + 2048)

template<int MODE>
__global__ __launch_bounds__(256) void hmma_kernel(
    const float* __restrict__ span, const float* __restrict__ img,
    const float* __restrict__ bias1, const float* __restrict__ w3v)
{
    constexpr int KB  = (MODE == 2) ? 3072 : 1024;
    constexpr int NCH = KB / 32;
    extern __shared__ char sm[];
    const u32 smb = su32(sm);
    float* red = (float*)(sm + RED_O);
    const int t = threadIdx.x, w = t >> 5, lane = t & 31;
    const int wm = w >> 2, wn = w & 3;
    const int n0 = blockIdx.x * 128, p0 = blockIdx.y * 128;

    const __nv_bfloat16 *Wh, *Wl;
    if constexpr (MODE == 0) { Wh = g_Wp[0];  Wl = g_Wp[1];  }
    else if constexpr (MODE == 1) { Wh = g_W2[0];  Wl = g_W2[1];  }
    else if constexpr (MODE == 2) { Wh = g_tW1[0]; Wl = g_tW1[1]; }
    else { Wh = g_tW2[0]; Wl = g_tW2[1]; }
    const __nv_bfloat16 *Ah = nullptr, *Al = nullptr;
    if constexpr (MODE == 1) { Ah = g_h1hi;  Al = g_h1lo;  }
    if constexpr (MODE == 3) { Ah = g_h1thi; Al = g_h1tlo; }

    // ---- A-gen setup (MODE 0/2): thread -> row gr, k-half gh ----
    const int gr = t >> 1, gh = t & 1;
    const float *fp = nullptr, *vp = nullptr;
    if constexpr (MODE == 0) {
        int p = p0 + gr, i = p / 160, j = p - i * 160;
        fp = span + (size_t)i * 1024 + gh * 16;
        vp = img  + (size_t)j * 1024 + gh * 16;
    }
    if constexpr (MODE == 2) {
        int p = p0 + gr; if (p > 6239) p = 6239;
        int b = p / 780, q = p - b * 780, fi = 0, cnt = 39, rem = q;
        while (rem >= cnt) { rem -= cnt; fi++; cnt--; }
        fp = span + (size_t)(b * 40 + fi) * 1024 + gh * 16;
        vp = span + (size_t)(b * 40 + fi + 1 + rem) * 1024 + gh * 16;
    }

    // ldmatrix lane addressing
    const int lr = lane & 15, lh = lane >> 4;              // A
    const u32 a_lane = (u32)((wm * 64 + lr) * 80 + lh * 16);
    const int bg = lane >> 3, bk = lane & 7;               // B (.trans)
    const u32 b_lane = (u32)(((bg & 1) * 8 + bk) * 272 + (wn * 32 + (bg >> 1) * 8) * 2);

    float acc[4][4][4];
#pragma unroll
    for (int am = 0; am < 4; ++am)
#pragma unroll
        for (int an = 0; an < 4; ++an) { acc[am][an][0]=0.f; acc[am][an][1]=0.f; acc[am][an][2]=0.f; acc[am][an][3]=0.f; }

    // ---- fill helpers ----
    auto fillB = [&](int cc, u32 sb) {
        int k0 = cc * 32;
#pragma unroll
        for (int it = 0; it < 4; ++it) {
            int idx = t + it * 256;
            int m = idx >> 9, rem = idx & 511, row = rem >> 4, ch = rem & 15;
            const __nv_bfloat16* src = (m ? Wl : Wh) + (size_t)(k0 + row) * 1024 + n0 + ch * 8;
            cpa16(sb + (m ? BLO : BHO) + row * 272 + ch * 16, src);
        }
    };
    auto fillA_async = [&](int cc, u32 sb) {
        if constexpr (MODE == 1 || MODE == 3) {
            int k0 = cc * 32;
#pragma unroll
            for (int it = 0; it < 4; ++it) {
                int idx = t + it * 256;
                int m = idx >> 9, rem = idx & 511, row = rem >> 2, ch = rem & 3;
                int prow = p0 + row; if (MODE == 3 && prow > 6239) prow = 6239;
                const __nv_bfloat16* src = (m ? Al : Ah) + (size_t)prow * 1024 + k0 + ch * 8;
                cpa16(sb + (m ? ALO : AHO) + row * 80 + ch * 16, src);
            }
        }
    };
    auto ldgA = [&](int cc, float* xr, float* yr) {
        if constexpr (MODE == 0 || MODE == 2) {
            int db = (cc * 32) & 1023;
            const float *fa = fp + db, *vb = vp + db;
#pragma unroll
            for (int q = 0; q < 4; ++q) {
                float4 x = *(const float4*)(fa + q * 4);
                float4 y = *(const float4*)(vb + q * 4);
                xr[q*4+0]=x.x; xr[q*4+1]=x.y; xr[q*4+2]=x.z; xr[q*4+3]=x.w;
                yr[q*4+0]=y.x; yr[q*4+1]=y.y; yr[q*4+2]=y.z; yr[q*4+3]=y.w;
            }
        }
    };
    auto stsA = [&](int cc, u32 sb, const float* xr, const float* yr) {
        if constexpr (MODE == 0 || MODE == 2) {
            int reg = (cc * 32) >> 10;
            float pr[16];
#pragma unroll
            for (int q = 0; q < 16; ++q) {
                float z;
                if (MODE == 0 || reg == 2) z = xr[q] * yr[q];
                else if (reg == 0) z = xr[q]; else z = yr[q];
                pr[q] = z;
            }
            u32 hw[8], lw[8];
#pragma unroll
            for (int q = 0; q < 8; ++q) bsplit2(pr[2*q], pr[2*q+1], hw[q], lw[q]);
            u32 da = sb + AHO + gr * 80 + gh * 32;
            asm volatile("st.shared.v4.b32 [%0], {%1,%2,%3,%4};" :: "r"(da), "r"(hw[0]), "r"(hw[1]), "r"(hw[2]), "r"(hw[3]));
            asm volatile("st.shared.v4.b32 [%0], {%1,%2,%3,%4};" :: "r"(da+16), "r"(hw[4]), "r"(hw[5]), "r"(hw[6]), "r"(hw[7]));
            u32 dl = sb + ALO + gr * 80 + gh * 32;
            asm volatile("st.shared.v4.b32 [%0], {%1,%2,%3,%4};" :: "r"(dl), "r"(lw[0]), "r"(lw[1]), "r"(lw[2]), "r"(lw[3]));
            asm volatile("st.shared.v4.b32 [%0], {%1,%2,%3,%4};" :: "r"(dl+16), "r"(lw[4]), "r"(lw[5]), "r"(lw[6]), "r"(lw[7]));
        }
    };

    // ---- prologue: fill stages 0..2, one commit each ----
#pragma unroll
    for (int pc = 0; pc < 3; ++pc) {
        u32 sb = smb + (u32)pc * STG_SZ;
        fillB(pc, sb);
        if constexpr (MODE == 1 || MODE == 3) {
            fillA_async(pc, sb);
        } else {
            float xr[16], yr[16];
            ldgA(pc, xr, yr);
            stsA(pc, sb, xr, yr);
        }
        CP_COMMIT;
    }

    // ---- main loop ----
    for (int c = 0; c < NCH; ++c) {
        CP_WAIT2;           // stage c's group (global group #c) is complete
        __syncthreads();
        const u32 sb = smb + (u32)(c & 3) * STG_SZ;
        const bool nxt = (c + 3 < NCH);
        const u32 nb = smb + (u32)((c + 3) & 3) * STG_SZ;
        float xr[16], yr[16];
        if (nxt) {
            fillB(c + 3, nb);
            fillA_async(c + 3, nb);
            ldgA(c + 3, xr, yr);
        }
        // ---- compute: 2 k16 steps ----
#pragma unroll
        for (int ks = 0; ks < 2; ++ks) {
            u32 ah[4][4], al[4][4], bh[2][4], bl[2][4];
#pragma unroll
            for (int am = 0; am < 4; ++am) {
                u32 aaddr = sb + a_lane + (u32)(am * 16 * 80 + ks * 32);
                LDSM4(ah[am], aaddr + AHO);
                LDSM4(al[am], aaddr + ALO);
            }
#pragma unroll
            for (int gn = 0; gn < 2; ++gn) {
                u32 baddr = sb + b_lane + (u32)(ks * 16 * 272 + gn * 32);
                LDSM4T(bh[gn], baddr + BHO);
                LDSM4T(bl[gn], baddr + BLO);
            }
#pragma unroll
            for (int am = 0; am < 4; ++am)
#pragma unroll
                for (int gn = 0; gn < 2; ++gn)
#pragma unroll
                    for (int sub = 0; sub < 2; ++sub) {
                        float* cc4 = acc[am][gn * 2 + sub];
                        mma_bf16(cc4, ah[am], bh[gn][sub*2], bh[gn][sub*2+1]);
                        mma_bf16(cc4, ah[am], bl[gn][sub*2], bl[gn][sub*2+1]);
                        mma_bf16(cc4, al[am], bh[gn][sub*2], bh[gn][sub*2+1]);
                    }
        }
        if (nxt) stsA(c + 3, nb, xr, yr);
        CP_COMMIT;          // exactly one group per iteration (may be empty)
    }

    // ---------------- epilogue ----------------
    if constexpr (MODE == 0 || MODE == 2) {
        __nv_bfloat16* OH = (MODE == 0) ? g_h1hi : g_h1thi;
        __nv_bfloat16* OL = (MODE == 0) ? g_h1lo : g_h1tlo;
#pragma unroll
        for (int am = 0; am < 4; ++am) {
            int row0 = p0 + wm * 64 + am * 16 + (lane >> 2);
#pragma unroll
            for (int h = 0; h < 2; ++h) {
                int p = row0 + h * 8;
                bool act = (MODE == 0) || (p < 6240);
                const float *fw = nullptr, *vw = nullptr;
                if constexpr (MODE == 0) {
                    int i = p / 160, j = p - i * 160;
                    fw = g_FWVW + (size_t)i * 1024;
                    vw = g_FWVW + (size_t)(320 + j) * 1024;
                }
#pragma unroll
                for (int an = 0; an < 4; ++an) {
                    int col = n0 + wn * 32 + an * 8 + (lane & 3) * 2;
                    float v0 = acc[am][an][h * 2 + 0];
                    float v1 = acc[am][an][h * 2 + 1];
                    float x0 = v0 + bias1[col], x1 = v1 + bias1[col + 1];
                    if (MODE == 0) { x0 += fw[col] + vw[col]; x1 += fw[col + 1] + vw[col + 1]; }
                    x0 = fmaxf(x0, 0.f); x1 = fmaxf(x1, 0.f);
                    u32 hp, lp; bsplit2(x0, x1, hp, lp);
                    if (act) {
                        *(u32*)(OH + (size_t)p * 1024 + col) = hp;
                        *(u32*)(OL + (size_t)p * 1024 + col) = lp;
                    }
                }
            }
        }
    } else {
        float s[8];
#pragma unroll
        for (int q = 0; q < 8; ++q) s[q] = 0.f;
#pragma unroll
        for (int am = 0; am < 4; ++am)
#pragma unroll
            for (int an = 0; an < 4; ++an) {
                int col = n0 + wn * 32 + an * 8 + (lane & 3) * 2;
                float b0 = bias1[col], b1v = bias1[col + 1];
                float w0 = w3v[col],  w1v = w3v[col + 1];
                s[am*2+0] += fmaxf(acc[am][an][0] + b0, 0.f) * w0 + fmaxf(acc[am][an][1] + b1v, 0.f) * w1v;
                s[am*2+1] += fmaxf(acc[am][an][2] + b0, 0.f) * w0 + fmaxf(acc[am][an][3] + b1v, 0.f) * w1v;
            }
#pragma unroll
        for (int q = 0; q < 8; ++q) {
            float v = s[q];
            v += __shfl_xor_sync(0xffffffffu, v, 1);
            v += __shfl_xor_sync(0xffffffffu, v, 2);
            if ((lane & 3) == 0) {
                int rowl = wm * 64 + (q >> 1) * 16 + (lane >> 2) + (q & 1) * 8;
                red[wn * 128 + rowl] = v;
            }
        }
        __syncthreads();
        if (t < 128) {
            int pp = p0 + t;
            float v = red[t] + red[128 + t] + red[256 + t] + red[384 + t];
            if (MODE == 1) g_part[(size_t)pp * 8 + blockIdx.x] = v;
            else if (pp < 6240) g_partt[(size_t)pp * 8 + blockIdx.x] = v;
        }
    }
}

// =====================================================================
// finalize + reductions
// =====================================================================
__global__ void fin_g(const float* __restrict__ smask, const float* __restrict__ imask,
                      const float* __restrict__ gb3, float* __restrict__ out_g)
{
    int p = blockIdx.x * 256 + threadIdx.x;
    float s = gb3[0];
#pragma unroll
    for (int nb = 0; nb < 8; ++nb) s += g_part[(size_t)p * 8 + nb];
    int i = p / 160, j = p - i * 160;
    out_g[p] = s * (smask[i] * imask[j]);
}

__global__ void fin_t(const float* __restrict__ tb3, float* __restrict__ out_t)
{
    int p = blockIdx.x * 256 + threadIdx.x;
    if (p >= 6240) return;
    float s = tb3[0];
#pragma unroll
    for (int nb = 0; nb < 8; ++nb) s += g_partt[(size_t)p * 8 + nb];
    out_t[p] = s;
}

__global__ void sreduce_kernel(const float* __restrict__ gsc) {
    __shared__ float red[256];
    int k = blockIdx.x;
    float s = 0.f;
    for (int idx = threadIdx.x; idx < 800; idx += 256) s += gsc[k * 800 + idx];
    red[threadIdx.x] = s;
    __syncthreads();
    for (int st = 128; st > 0; st >>= 1) {
        if (threadIdx.x < st) red[threadIdx.x] += red[threadIdx.x + st];
        __syncthreads();
    }
    if (threadIdx.x == 0) g_S[k] = red[0];
}

__global__ void loss_kernel(float* __restrict__ out) {
    if (threadIdx.x == 0) {
        float S[64];
        for (int k = 0; k < 64; ++k) S[k] = g_S[k];
        float lr = 0.f, lc = 0.f, tot = 0.f;
        for (int r = 0; r < 8; ++r) {
            float m = -1e30f;
            for (int c = 0; c < 8; ++c) m = fmaxf(m, S[r * 8 + c]);
            float e = 0.f;
            for (int c = 0; c < 8; ++c) e += expf(S[r * 8 + c] - m);
            lr += m + logf(e);
        }
        for (int c = 0; c < 8; ++c) {
            float m = -1e30f;
            for (int r = 0; r < 8; ++r) m = fmaxf(m, S[r * 8 + c]);
            float e = 0.f;
            for (int r = 0; r < 8; ++r) e += expf(S[r * 8 + c] - m);
            lc += m + logf(e);
        }
        for (int k = 0; k < 64; ++k) tot += S[k];
        out[0] = -(2.f * tot - 8.f * (lr + lc)) / 8.f;
    }
}

// =====================================================================
extern "C" void kernel_launch(void* const* d_in, const int* in_sizes, int n_in,
                              void* d_out, int out_size) {
    (void)in_sizes; (void)n_in; (void)out_size;
    const float* span  = (const float*)d_in[0];
    const float* img   = (const float*)d_in[1];
    const float* smask = (const float*)d_in[2];
    const float* imask = (const float*)d_in[3];
    const float* tW1 = (const float*)d_in[4];  const float* tb1 = (const float*)d_in[5];
    const float* tW2 = (const float*)d_in[6];  const float* tb2 = (const float*)d_in[7];
    const float* tW3 = (const float*)d_in[8];  const float* tb3 = (const float*)d_in[9];
    const float* gW1 = (const float*)d_in[10]; const float* gb1 = (const float*)d_in[11];
    const float* gW2 = (const float*)d_in[12]; const float* gb2 = (const float*)d_in[13];
    const float* gW3 = (const float*)d_in[14]; const float* gb3 = (const float*)d_in[15];
    float* out = (float*)d_out;

    cudaFuncSetAttribute(hmma_kernel<0>, cudaFuncAttributeMaxDynamicSharedMemorySize, HM_SMEM);
    cudaFuncSetAttribute(hmma_kernel<1>, cudaFuncAttributeMaxDynamicSharedMemorySize, HM_SMEM);
    cudaFuncSetAttribute(hmma_kernel<2>, cudaFuncAttributeMaxDynamicSharedMemorySize, HM_SMEM);
    cudaFuncSetAttribute(hmma_kernel<3>, cudaFuncAttributeMaxDynamicSharedMemorySize, HM_SMEM);

    wconv<0><<<4096,  256>>>(gW1 + (size_t)2 * 1024 * 1024, 1024 * 1024);
    wconv<1><<<4096,  256>>>(gW2, 1024 * 1024);
    wconv<2><<<12288, 256>>>(tW1, 3072 * 1024);
    wconv<3><<<4096,  256>>>(tW2, 1024 * 1024);
    fwvw_kernel<<<dim3(15, 8), 256>>>(span, img, gW1);

    hmma_kernel<0><<<dim3(8, 400), 256, HM_SMEM>>>(span, img, gb1, nullptr);
    hmma_kernel<1><<<dim3(8, 400), 256, HM_SMEM>>>(nullptr, nullptr, gb2, gW3);
    hmma_kernel<2><<<dim3(8, 49),  256, HM_SMEM>>>(span, nullptr, tb1, nullptr);
    hmma_kernel<3><<<dim3(8, 49),  256, HM_SMEM>>>(nullptr, nullptr, tb2, tW3);

    fin_g<<<200, 256>>>(smask, imask, gb3, out + 1);
    fin_t<<<25, 256>>>(tb3, out + 1 + 51200);
    sreduce_kernel<<<64, 256>>>(out + 1);
    loss_kernel<<<1, 32>>>(out);
}

// round 7
// speedup vs baseline: 2.0774x; 1.0799x over previous
#include <cuda_runtime.h>
#include <cuda_bf16.h>
#include <cstdint>

typedef unsigned long long ull;
typedef unsigned int u32;

// ---------------- helpers ----------------
__device__ __forceinline__ ull pack2(float x, float y) {
    ull r; asm("mov.b64 %0, {%1, %2};" : "=l"(r) : "f"(x), "f"(y)); return r;
}
__device__ __forceinline__ void fma2(ull& acc, ull a, ull b) {
    asm("fma.rn.f32x2 %0, %1, %2, %0;" : "+l"(acc) : "l"(a), "l"(b));
}
__device__ __forceinline__ float2 unpack2(ull a) {
    float2 r; asm("mov.b64 {%0, %1}, %2;" : "=f"(r.x), "=f"(r.y) : "l"(a)); return r;
}
__device__ __forceinline__ u32 su32(const void* p) {
    u32 a;
    asm("{ .reg .u64 t; cvta.to.shared.u64 t, %1; cvt.u32.u64 %0, t; }" : "=r"(a) : "l"(p));
    return a;
}
__device__ __forceinline__ void cpa16(u32 s, const void* g) {
    asm volatile("cp.async.cg.shared.global [%0], [%1], 16;" :: "r"(s), "l"(g));
}
#define CP_COMMIT asm volatile("cp.async.commit_group;")
#define CP_WAIT1  asm volatile("cp.async.wait_group 1;")

#define LDSM4(r, a) \
    asm volatile("ldmatrix.sync.aligned.m8n8.x4.shared.b16 {%0,%1,%2,%3}, [%4];" \
        : "=r"((r)[0]), "=r"((r)[1]), "=r"((r)[2]), "=r"((r)[3]) : "r"(a))
#define LDSM4T(r, a) \
    asm volatile("ldmatrix.sync.aligned.m8n8.x4.trans.shared.b16 {%0,%1,%2,%3}, [%4];" \
        : "=r"((r)[0]), "=r"((r)[1]), "=r"((r)[2]), "=r"((r)[3]) : "r"(a))

__device__ __forceinline__ void mma_bf16(float* c, const u32* a, u32 b0, u32 b1) {
    asm volatile(
        "mma.sync.aligned.m16n8k16.row.col.f32.bf16.bf16.f32 "
        "{%0,%1,%2,%3}, {%4,%5,%6,%7}, {%8,%9}, {%0,%1,%2,%3};"
        : "+f"(c[0]), "+f"(c[1]), "+f"(c[2]), "+f"(c[3])
        : "r"(a[0]), "r"(a[1]), "r"(a[2]), "r"(a[3]), "r"(b0), "r"(b1));
}
__device__ __forceinline__ void bsplit2(float a, float b, u32& hi, u32& lo) {
    __nv_bfloat16 ha = __float2bfloat16_rn(a), hb = __float2bfloat16_rn(b);
    __nv_bfloat16 la = __float2bfloat16_rn(a - __bfloat162float(ha));
    __nv_bfloat16 lb = __float2bfloat16_rn(b - __bfloat162float(hb));
    hi = (u32)__bfloat16_as_ushort(ha) | ((u32)__bfloat16_as_ushort(hb) << 16);
    lo = (u32)__bfloat16_as_ushort(la) | ((u32)__bfloat16_as_ushort(lb) << 16);
}

// ---------------- scratch ----------------
__device__ float g_FWVW[480 * 1024];
__device__ float g_S[64];
__device__ __nv_bfloat16 g_Wp[2][1024 * 1024];
__device__ __nv_bfloat16 g_W2[2][1024 * 1024];
__device__ __nv_bfloat16 g_tW1[2][(size_t)3072 * 1024];
__device__ __nv_bfloat16 g_tW2[2][1024 * 1024];
__device__ __nv_bfloat16 g_h1hi[(size_t)51200 * 1024];
__device__ __nv_bfloat16 g_h1lo[(size_t)51200 * 1024];
__device__ __nv_bfloat16 g_h1thi[(size_t)6272 * 1024];
__device__ __nv_bfloat16 g_h1tlo[(size_t)6272 * 1024];
__device__ float g_part[(size_t)51200 * 4];
__device__ float g_partt[6240 * 4];

// =====================================================================
// weight bf16 hi/lo split
// =====================================================================
template<int WSEL>
__global__ void wconv(const float* __restrict__ W, int n)
{
    __nv_bfloat16 *hi, *lo;
    if constexpr (WSEL == 0) { hi = g_Wp[0];  lo = g_Wp[1];  }
    else if constexpr (WSEL == 1) { hi = g_W2[0];  lo = g_W2[1];  }
    else if constexpr (WSEL == 2) { hi = g_tW1[0]; lo = g_tW1[1]; }
    else { hi = g_tW2[0]; lo = g_tW2[1]; }
    int i = blockIdx.x * 256 + threadIdx.x;
    if (i < n) {
        float x = W[i];
        __nv_bfloat16 h = __float2bfloat16_rn(x);
        __nv_bfloat16 l = __float2bfloat16_rn(x - __bfloat162float(h));
        hi[i] = h; lo[i] = l;
    }
}

// =====================================================================
// FW/VW precompute (exact fp32)
// =====================================================================
__global__ __launch_bounds__(256) void fwvw_kernel(
    const float* __restrict__ span, const float* __restrict__ img,
    const float* __restrict__ gW1)
{
    __shared__ float At[32 * 33];
    __shared__ float Wt[32 * 128];
    const int g0 = blockIdx.x * 32;
    const int n0 = blockIdx.y * 128;
    const int t = threadIdx.x, tx = t & 15, ty = t >> 4;
    const bool isv = (g0 >= 320);
    const float* Wsrc = gW1 + (isv ? (size_t)1024 * 1024 : 0);

    ull acc[8] = {0,0,0,0,0,0,0,0};
    for (int kt = 0; kt < 32; ++kt) {
#pragma unroll
        for (int it = 0; it < 4; ++it) {
            int idx = t + it * 256; int k = idx & 31, r = idx >> 5;
            int g = g0 + r;
            const float* srow = isv ? (img + (size_t)(g - 320) * 1024) : (span + (size_t)g * 1024);
            At[k * 33 + r] = srow[kt * 32 + k];
        }
#pragma unroll
        for (int it = 0; it < 4; ++it) {
            int idx = t + it * 256; int kk = idx >> 5, c4 = idx & 31;
            ((float4*)Wt)[kk * 32 + c4] =
                *(const float4*)&Wsrc[(size_t)(kt * 32 + kk) * 1024 + n0 + c4 * 4];
        }
        __syncthreads();
#pragma unroll
        for (int k = 0; k < 32; ++k) {
            float a0s = At[k * 33 + 2 * ty], a1s = At[k * 33 + 2 * ty + 1];
            ull A0 = pack2(a0s, a0s), A1 = pack2(a1s, a1s);
            const ull* wrow = (const ull*)&Wt[k * 128 + tx * 8];
            ull w0 = wrow[0], w1 = wrow[1], w2 = wrow[2], w3 = wrow[3];
            fma2(acc[0], A0, w0); fma2(acc[1], A0, w1); fma2(acc[2], A0, w2); fma2(acc[3], A0, w3);
            fma2(acc[4], A1, w0); fma2(acc[5], A1, w1); fma2(acc[6], A1, w2); fma2(acc[7], A1, w3);
        }
        __syncthreads();
    }
#pragma unroll
    for (int dr = 0; dr < 2; ++dr) {
        int g = g0 + 2 * ty + dr;
#pragma unroll
        for (int cp = 0; cp < 4; ++cp) {
            float2 v = unpack2(acc[dr * 4 + cp]);
            int n = n0 + tx * 8 + cp * 2;
            g_FWVW[(size_t)g * 1024 + n] = v.x;
            g_FWVW[(size_t)g * 1024 + n + 1] = v.y;
        }
    }
}

// =====================================================================
// HMMA GEMM, CTA tile 128x256, warp tile 64x64, 3-stage pipeline.
// MODE: 0 ground L1, 1 ground L2, 2 text L1 (K=3072), 3 text L2
// =====================================================================
#define AHO 0
#define ALO 10240
#define BHO 20480
#define BLO 37376
#define STG_SZ 54272
#define RED_O (3 * STG_SZ)
#define HM_SMEM (RED_O + 2048)

template<int MODE>
__global__ __launch_bounds__(256) void hmma_kernel(
    const float* __restrict__ span, const float* __restrict__ img,
    const float* __restrict__ bias1, const float* __restrict__ w3v)
{
    constexpr int KB  = (MODE == 2) ? 3072 : 1024;
    constexpr int NCH = KB / 32;
    extern __shared__ char sm[];
    const u32 smb = su32(sm);
    float* red = (float*)(sm + RED_O);
    const int t = threadIdx.x, w = t >> 5, lane = t & 31;
    const int wm = w >> 2, wn = w & 3;
    const int n0 = blockIdx.x * 256, p0 = blockIdx.y * 128;

    const __nv_bfloat16 *Wh, *Wl;
    if constexpr (MODE == 0) { Wh = g_Wp[0];  Wl = g_Wp[1];  }
    else if constexpr (MODE == 1) { Wh = g_W2[0];  Wl = g_W2[1];  }
    else if constexpr (MODE == 2) { Wh = g_tW1[0]; Wl = g_tW1[1]; }
    else { Wh = g_tW2[0]; Wl = g_tW2[1]; }
    const __nv_bfloat16 *Ah = nullptr, *Al = nullptr;
    if constexpr (MODE == 1) { Ah = g_h1hi;  Al = g_h1lo;  }
    if constexpr (MODE == 3) { Ah = g_h1thi; Al = g_h1tlo; }

    // ---- A-gen setup (MODE 0/2): thread -> row gr, k-half gh ----
    const int gr = t >> 1, gh = t & 1;
    const float *fp = nullptr, *vp = nullptr;
    if constexpr (MODE == 0) {
        int p = p0 + gr, i = p / 160, j = p - i * 160;
        fp = span + (size_t)i * 1024 + gh * 16;
        vp = img  + (size_t)j * 1024 + gh * 16;
    }
    if constexpr (MODE == 2) {
        int p = p0 + gr; if (p > 6239) p = 6239;
        int b = p / 780, q = p - b * 780, fi = 0, cnt = 39, rem = q;
        while (rem >= cnt) { rem -= cnt; fi++; cnt--; }
        fp = span + (size_t)(b * 40 + fi) * 1024 + gh * 16;
        vp = span + (size_t)(b * 40 + fi + 1 + rem) * 1024 + gh * 16;
    }

    // ldmatrix lane addressing
    const int lr = lane & 15, lh = lane >> 4;              // A
    const u32 a_lane = (u32)((wm * 64 + lr) * 80 + lh * 16);
    const int bg = lane >> 3, bk = lane & 7;               // B (.trans), stride 528
    const u32 b_lane = (u32)(((bg & 1) * 8 + bk) * 528 + (wn * 64 + (bg >> 1) * 8) * 2);

    float acc[4][8][4];
#pragma unroll
    for (int am = 0; am < 4; ++am)
#pragma unroll
        for (int nn = 0; nn < 8; ++nn) { acc[am][nn][0]=0.f; acc[am][nn][1]=0.f; acc[am][nn][2]=0.f; acc[am][nn][3]=0.f; }

    // ---- fill helpers ----
    auto fillB = [&](int cc, u32 sb) {
        int k0 = cc * 32;
#pragma unroll
        for (int it = 0; it < 8; ++it) {
            int idx = t + it * 256;
            int m = idx >> 10, rem = idx & 1023, row = rem >> 5, ch = rem & 31;
            const __nv_bfloat16* src = (m ? Wl : Wh) + (size_t)(k0 + row) * 1024 + n0 + ch * 8;
            cpa16(sb + (m ? BLO : BHO) + row * 528 + ch * 16, src);
        }
    };
    auto fillA_async = [&](int cc, u32 sb) {
        if constexpr (MODE == 1 || MODE == 3) {
            int k0 = cc * 32;
#pragma unroll
            for (int it = 0; it < 4; ++it) {
                int idx = t + it * 256;
                int m = idx >> 9, rem = idx & 511, row = rem >> 2, ch = rem & 3;
                int prow = p0 + row; if (MODE == 3 && prow > 6239) prow = 6239;
                const __nv_bfloat16* src = (m ? Al : Ah) + (size_t)prow * 1024 + k0 + ch * 8;
                cpa16(sb + (m ? ALO : AHO) + row * 80 + ch * 16, src);
            }
        }
    };
    auto ldgA = [&](int cc, float* xr, float* yr) {
        if constexpr (MODE == 0 || MODE == 2) {
            int db = (cc * 32) & 1023;
            const float *fa = fp + db, *vb = vp + db;
#pragma unroll
            for (int q = 0; q < 4; ++q) {
                float4 x = *(const float4*)(fa + q * 4);
                float4 y = *(const float4*)(vb + q * 4);
                xr[q*4+0]=x.x; xr[q*4+1]=x.y; xr[q*4+2]=x.z; xr[q*4+3]=x.w;
                yr[q*4+0]=y.x; yr[q*4+1]=y.y; yr[q*4+2]=y.z; yr[q*4+3]=y.w;
            }
        }
    };
    auto stsA = [&](int cc, u32 sb, const float* xr, const float* yr) {
        if constexpr (MODE == 0 || MODE == 2) {
            int reg = (cc * 32) >> 10;
            float pr[16];
#pragma unroll
            for (int q = 0; q < 16; ++q) {
                float z;
                if (MODE == 0 || reg == 2) z = xr[q] * yr[q];
                else if (reg == 0) z = xr[q]; else z = yr[q];
                pr[q] = z;
            }
            u32 hw[8], lw[8];
#pragma unroll
            for (int q = 0; q < 8; ++q) bsplit2(pr[2*q], pr[2*q+1], hw[q], lw[q]);
            u32 da = sb + AHO + gr * 80 + gh * 32;
            asm volatile("st.shared.v4.b32 [%0], {%1,%2,%3,%4};" :: "r"(da), "r"(hw[0]), "r"(hw[1]), "r"(hw[2]), "r"(hw[3]));
            asm volatile("st.shared.v4.b32 [%0], {%1,%2,%3,%4};" :: "r"(da+16), "r"(hw[4]), "r"(hw[5]), "r"(hw[6]), "r"(hw[7]));
            u32 dl = sb + ALO + gr * 80 + gh * 32;
            asm volatile("st.shared.v4.b32 [%0], {%1,%2,%3,%4};" :: "r"(dl), "r"(lw[0]), "r"(lw[1]), "r"(lw[2]), "r"(lw[3]));
            asm volatile("st.shared.v4.b32 [%0], {%1,%2,%3,%4};" :: "r"(dl+16), "r"(lw[4]), "r"(lw[5]), "r"(lw[6]), "r"(lw[7]));
        }
    };

    // ---- prologue: fill stages 0..1, one commit each ----
#pragma unroll
    for (int pc = 0; pc < 2; ++pc) {
        u32 sb = smb + (u32)pc * STG_SZ;
        fillB(pc, sb);
        if constexpr (MODE == 1 || MODE == 3) {
            fillA_async(pc, sb);
        } else {
            float xr[16], yr[16];
            ldgA(pc, xr, yr);
            stsA(pc, sb, xr, yr);
        }
        CP_COMMIT;
    }

    // ---- main loop ----
    for (int c = 0; c < NCH; ++c) {
        CP_WAIT1;           // group for chunk c complete
        __syncthreads();
        const u32 sb = smb + (u32)(c % 3) * STG_SZ;
        const bool nxt = (c + 2 < NCH);
        const u32 nb = smb + (u32)((c + 2) % 3) * STG_SZ;
        float xr[16], yr[16];
        if (nxt) {
            fillB(c + 2, nb);
            fillA_async(c + 2, nb);
            ldgA(c + 2, xr, yr);
        }
        // ---- compute: 2 k16 steps ----
#pragma unroll
        for (int ks = 0; ks < 2; ++ks) {
            u32 ah[4][4], al[4][4];
#pragma unroll
            for (int am = 0; am < 4; ++am) {
                u32 aaddr = sb + a_lane + (u32)(am * 16 * 80 + ks * 32);
                LDSM4(ah[am], aaddr + AHO);
                LDSM4(al[am], aaddr + ALO);
            }
#pragma unroll
            for (int gn = 0; gn < 4; ++gn) {
                u32 bh[4], bl[4];
                u32 baddr = sb + b_lane + (u32)(ks * 16 * 528 + gn * 32);
                LDSM4T(bh, baddr + BHO);
                LDSM4T(bl, baddr + BLO);
#pragma unroll
                for (int am = 0; am < 4; ++am)
#pragma unroll
                    for (int sub = 0; sub < 2; ++sub) {
                        float* cc4 = acc[am][gn * 2 + sub];
                        mma_bf16(cc4, ah[am], bh[sub*2], bh[sub*2+1]);
                        mma_bf16(cc4, ah[am], bl[sub*2], bl[sub*2+1]);
                        mma_bf16(cc4, al[am], bh[sub*2], bh[sub*2+1]);
                    }
            }
        }
        if (nxt) stsA(c + 2, nb, xr, yr);
        CP_COMMIT;          // exactly one group per iteration (may be empty)
    }

    // ---------------- epilogue ----------------
    if constexpr (MODE == 0 || MODE == 2) {
        __nv_bfloat16* OH = (MODE == 0) ? g_h1hi : g_h1thi;
        __nv_bfloat16* OL = (MODE == 0) ? g_h1lo : g_h1tlo;
#pragma unroll
        for (int am = 0; am < 4; ++am) {
            int row0 = p0 + wm * 64 + am * 16 + (lane >> 2);
#pragma unroll
            for (int h = 0; h < 2; ++h) {
                int p = row0 + h * 8;
                bool act = (MODE == 0) || (p < 6240);
                const float *fw = nullptr, *vw = nullptr;
                if constexpr (MODE == 0) {
                    int i = p / 160, j = p - i * 160;
                    fw = g_FWVW + (size_t)i * 1024;
                    vw = g_FWVW + (size_t)(320 + j) * 1024;
                }
#pragma unroll
                for (int nn = 0; nn < 8; ++nn) {
                    int col = n0 + wn * 64 + nn * 8 + (lane & 3) * 2;
                    float v0 = acc[am][nn][h * 2 + 0];
                    float v1 = acc[am][nn][h * 2 + 1];
                    float x0 = v0 + bias1[col], x1 = v1 + bias1[col + 1];
                    if (MODE == 0) { x0 += fw[col] + vw[col]; x1 += fw[col + 1] + vw[col + 1]; }
                    x0 = fmaxf(x0, 0.f); x1 = fmaxf(x1, 0.f);
                    u32 hp, lp; bsplit2(x0, x1, hp, lp);
                    if (act) {
                        *(u32*)(OH + (size_t)p * 1024 + col) = hp;
                        *(u32*)(OL + (size_t)p * 1024 + col) = lp;
                    }
                }
            }
        }
    } else {
        float s[8];
#pragma unroll
        for (int q = 0; q < 8; ++q) s[q] = 0.f;
#pragma unroll
        for (int am = 0; am < 4; ++am)
#pragma unroll
            for (int nn = 0; nn < 8; ++nn) {
                int col = n0 + wn * 64 + nn * 8 + (lane & 3) * 2;
                float b0 = bias1[col], b1v = bias1[col + 1];
                float w0 = w3v[col],  w1v = w3v[col + 1];
                s[am*2+0] += fmaxf(acc[am][nn][0] + b0, 0.f) * w0 + fmaxf(acc[am][nn][1] + b1v, 0.f) * w1v;
                s[am*2+1] += fmaxf(acc[am][nn][2] + b0, 0.f) * w0 + fmaxf(acc[am][nn][3] + b1v, 0.f) * w1v;
            }
#pragma unroll
        for (int q = 0; q < 8; ++q) {
            float v = s[q];
            v += __shfl_xor_sync(0xffffffffu, v, 1);
            v += __shfl_xor_sync(0xffffffffu, v, 2);
            if ((lane & 3) == 0) {
                int rowl = wm * 64 + (q >> 1) * 16 + (lane >> 2) + (q & 1) * 8;
                red[wn * 128 + rowl] = v;
            }
        }
        __syncthreads();
        if (t < 128) {
            int pp = p0 + t;
            float v = red[t] + red[128 + t] + red[256 + t] + red[384 + t];
            if (MODE == 1) g_part[(size_t)pp * 4 + blockIdx.x] = v;
            else if (pp < 6240) g_partt[(size_t)pp * 4 + blockIdx.x] = v;
        }
    }
}

// =====================================================================
// finalize + reductions
// =====================================================================
__global__ void fin_g(const float* __restrict__ smask, const float* __restrict__ imask,
                      const float* __restrict__ gb3, float* __restrict__ out_g)
{
    int p = blockIdx.x * 256 + threadIdx.x;
    float s = gb3[0];
#pragma unroll
    for (int nb = 0; nb < 4; ++nb) s += g_part[(size_t)p * 4 + nb];
    int i = p / 160, j = p - i * 160;
    out_g[p] = s * (smask[i] * imask[j]);
}

__global__ void fin_t(const float* __restrict__ tb3, float* __restrict__ out_t)
{
    int p = blockIdx.x * 256 + threadIdx.x;
    if (p >= 6240) return;
    float s = tb3[0];
#pragma unroll
    for (int nb = 0; nb < 4; ++nb) s += g_partt[(size_t)p * 4 + nb];
    out_t[p] = s;
}

__global__ void sreduce_kernel(const float* __restrict__ gsc) {
    __shared__ float red[256];
    int k = blockIdx.x;
    float s = 0.f;
    for (int idx = threadIdx.x; idx < 800; idx += 256) s += gsc[k * 800 + idx];
    red[threadIdx.x] = s;
    __syncthreads();
    for (int st = 128; st > 0; st >>= 1) {
        if (threadIdx.x < st) red[threadIdx.x] += red[threadIdx.x + st];
        __syncthreads();
    }
    if (threadIdx.x == 0) g_S[k] = red[0];
}

__global__ void loss_kernel(float* __restrict__ out) {
    if (threadIdx.x == 0) {
        float S[64];
        for (int k = 0; k < 64; ++k) S[k] = g_S[k];
        float lr = 0.f, lc = 0.f, tot = 0.f;
        for (int r = 0; r < 8; ++r) {
            float m = -1e30f;
            for (int c = 0; c < 8; ++c) m = fmaxf(m, S[r * 8 + c]);
            float e = 0.f;
            for (int c = 0; c < 8; ++c) e += expf(S[r * 8 + c] - m);
            lr += m + logf(e);
        }
        for (int c = 0; c < 8; ++c) {
            float m = -1e30f;
            for (int r = 0; r < 8; ++r) m = fmaxf(m, S[r * 8 + c]);
            float e = 0.f;
            for (int r = 0; r < 8; ++r) e += expf(S[r * 8 + c] - m);
            lc += m + logf(e);
        }
        for (int k = 0; k < 64; ++k) tot += S[k];
        out[0] = -(2.f * tot - 8.f * (lr + lc)) / 8.f;
    }
}

// =====================================================================
extern "C" void kernel_launch(void* const* d_in, const int* in_sizes, int n_in,
                              void* d_out, int out_size) {
    (void)in_sizes; (void)n_in; (void)out_size;
    const float* span  = (const float*)d_in[0];
    const float* img   = (const float*)d_in[1];
    const float* smask = (const float*)d_in[2];
    const float* imask = (const float*)d_in[3];
    const float* tW1 = (const float*)d_in[4];  const float* tb1 = (const float*)d_in[5];
    const float* tW2 = (const float*)d_in[6];  const float* tb2 = (const float*)d_in[7];
    const float* tW3 = (const float*)d_in[8];  const float* tb3 = (const float*)d_in[9];
    const float* gW1 = (const float*)d_in[10]; const float* gb1 = (const float*)d_in[11];
    const float* gW2 = (const float*)d_in[12]; const float* gb2 = (const float*)d_in[13];
    const float* gW3 = (const float*)d_in[14]; const float* gb3 = (const float*)d_in[15];
    float* out = (float*)d_out;

    cudaFuncSetAttribute(hmma_kernel<0>, cudaFuncAttributeMaxDynamicSharedMemorySize, HM_SMEM);
    cudaFuncSetAttribute(hmma_kernel<1>, cudaFuncAttributeMaxDynamicSharedMemorySize, HM_SMEM);
    cudaFuncSetAttribute(hmma_kernel<2>, cudaFuncAttributeMaxDynamicSharedMemorySize, HM_SMEM);
    cudaFuncSetAttribute(hmma_kernel<3>, cudaFuncAttributeMaxDynamicSharedMemorySize, HM_SMEM);

    wconv<0><<<4096,  256>>>(gW1 + (size_t)2 * 1024 * 1024, 1024 * 1024);
    wconv<1><<<4096,  256>>>(gW2, 1024 * 1024);
    wconv<2><<<12288, 256>>>(tW1, 3072 * 1024);
    wconv<3><<<4096,  256>>>(tW2, 1024 * 1024);
    fwvw_kernel<<<dim3(15, 8), 256>>>(span, img, gW1);

    hmma_kernel<0><<<dim3(4, 400), 256, HM_SMEM>>>(span, img, gb1, nullptr);
    hmma_kernel<1><<<dim3(4, 400), 256, HM_SMEM>>>(nullptr, nullptr, gb2, gW3);
    hmma_kernel<2><<<dim3(4, 49),  256, HM_SMEM>>>(span, nullptr, tb1, nullptr);
    hmma_kernel<3><<<dim3(4, 49),  256, HM_SMEM>>>(nullptr, nullptr, tb2, tW3);

    fin_g<<<200, 256>>>(smask, imask, gb3, out + 1);
    fin_t<<<25, 256>>>(tb3, out + 1 + 51200);
    sreduce_kernel<<<64, 256>>>(out + 1);
    loss_kernel<<<1, 32>>>(out);
}

// round 8
// speedup vs baseline: 2.8754x; 1.3841x over previous
#include <cuda_runtime.h>
#include <cuda_bf16.h>
#include <cuda_fp16.h>
#include <cstdint>

typedef unsigned long long ull;
typedef unsigned int u32;

// ---------------- helpers ----------------
__device__ __forceinline__ ull pack2(float x, float y) {
    ull r; asm("mov.b64 %0, {%1, %2};" : "=l"(r) : "f"(x), "f"(y)); return r;
}
__device__ __forceinline__ void fma2(ull& acc, ull a, ull b) {
    asm("fma.rn.f32x2 %0, %1, %2, %0;" : "+l"(acc) : "l"(a), "l"(b));
}
__device__ __forceinline__ float2 unpack2(ull a) {
    float2 r; asm("mov.b64 {%0, %1}, %2;" : "=f"(r.x), "=f"(r.y) : "l"(a)); return r;
}
__device__ __forceinline__ u32 su32(const void* p) {
    u32 a;
    asm("{ .reg .u64 t; cvta.to.shared.u64 t, %1; cvt.u32.u64 %0, t; }" : "=r"(a) : "l"(p));
    return a;
}
__device__ __forceinline__ void cpa16(u32 s, const void* g) {
    asm volatile("cp.async.cg.shared.global [%0], [%1], 16;" :: "r"(s), "l"(g));
}
#define CP_COMMIT asm volatile("cp.async.commit_group;")
#define CP_WAIT1  asm volatile("cp.async.wait_group 1;")

#define LDSM4(r, a) \
    asm volatile("ldmatrix.sync.aligned.m8n8.x4.shared.b16 {%0,%1,%2,%3}, [%4];" \
        : "=r"((r)[0]), "=r"((r)[1]), "=r"((r)[2]), "=r"((r)[3]) : "r"(a))
#define LDSM4T(r, a) \
    asm volatile("ldmatrix.sync.aligned.m8n8.x4.trans.shared.b16 {%0,%1,%2,%3}, [%4];" \
        : "=r"((r)[0]), "=r"((r)[1]), "=r"((r)[2]), "=r"((r)[3]) : "r"(a))

__device__ __forceinline__ void mma_f16(float* c, const u32* a, u32 b0, u32 b1) {
    asm volatile(
        "mma.sync.aligned.m16n8k16.row.col.f32.f16.f16.f32 "
        "{%0,%1,%2,%3}, {%4,%5,%6,%7}, {%8,%9}, {%0,%1,%2,%3};"
        : "+f"(c[0]), "+f"(c[1]), "+f"(c[2]), "+f"(c[3])
        : "r"(a[0]), "r"(a[1]), "r"(a[2]), "r"(a[3]), "r"(b0), "r"(b1));
}
// fp16 hi/lo split of two floats, packed
__device__ __forceinline__ void hsplit2(float a, float b, u32& hi, u32& lo) {
    __half ha = __float2half_rn(a), hb = __float2half_rn(b);
    __half la = __float2half_rn(a - __half2float(ha));
    __half lb = __float2half_rn(b - __half2float(hb));
    hi = (u32)__half_as_ushort(ha) | ((u32)__half_as_ushort(hb) << 16);
    lo = (u32)__half_as_ushort(la) | ((u32)__half_as_ushort(lb) << 16);
}
__device__ __forceinline__ u32 hpack2(float a, float b) {
    __half2 h = __floats2half2_rn(a, b);
    return *(u32*)&h;
}

// ---------------- scratch ----------------
__device__ float g_FWVW[480 * 1024];
__device__ float g_S[64];
__device__ __half g_Wp[2][1024 * 1024];
__device__ __half g_W2[2][1024 * 1024];
__device__ __half g_tW1[2][(size_t)3072 * 1024];
__device__ __half g_tW2[2][1024 * 1024];
__device__ __half g_h1[(size_t)51200 * 1024];
__device__ __half g_h1t[(size_t)6272 * 1024];
__device__ float g_part[(size_t)51200 * 4];
__device__ float g_partt[6240 * 4];

// =====================================================================
// weight fp16 hi/lo split
// =====================================================================
template<int WSEL>
__global__ void wconv(const float* __restrict__ W, int n)
{
    __half *hi, *lo;
    if constexpr (WSEL == 0) { hi = g_Wp[0];  lo = g_Wp[1];  }
    else if constexpr (WSEL == 1) { hi = g_W2[0];  lo = g_W2[1];  }
    else if constexpr (WSEL == 2) { hi = g_tW1[0]; lo = g_tW1[1]; }
    else { hi = g_tW2[0]; lo = g_tW2[1]; }
    int i = blockIdx.x * 256 + threadIdx.x;
    if (i < n) {
        float x = W[i];
        __half h = __float2half_rn(x);
        __half l = __float2half_rn(x - __half2float(h));
        hi[i] = h; lo[i] = l;
    }
}

// =====================================================================
// FW/VW precompute (exact fp32)
// =====================================================================
__global__ __launch_bounds__(256) void fwvw_kernel(
    const float* __restrict__ span, const float* __restrict__ img,
    const float* __restrict__ gW1)
{
    __shared__ float At[32 * 33];
    __shared__ float Wt[32 * 128];
    const int g0 = blockIdx.x * 32;
    const int n0 = blockIdx.y * 128;
    const int t = threadIdx.x, tx = t & 15, ty = t >> 4;
    const bool isv = (g0 >= 320);
    const float* Wsrc = gW1 + (isv ? (size_t)1024 * 1024 : 0);

    ull acc[8] = {0,0,0,0,0,0,0,0};
    for (int kt = 0; kt < 32; ++kt) {
#pragma unroll
        for (int it = 0; it < 4; ++it) {
            int idx = t + it * 256; int k = idx & 31, r = idx >> 5;
            int g = g0 + r;
            const float* srow = isv ? (img + (size_t)(g - 320) * 1024) : (span + (size_t)g * 1024);
            At[k * 33 + r] = srow[kt * 32 + k];
        }
#pragma unroll
        for (int it = 0; it < 4; ++it) {
            int idx = t + it * 256; int kk = idx >> 5, c4 = idx & 31;
            ((float4*)Wt)[kk * 32 + c4] =
                *(const float4*)&Wsrc[(size_t)(kt * 32 + kk) * 1024 + n0 + c4 * 4];
        }
        __syncthreads();
#pragma unroll
        for (int k = 0; k < 32; ++k) {
            float a0s = At[k * 33 + 2 * ty], a1s = At[k * 33 + 2 * ty + 1];
            ull A0 = pack2(a0s, a0s), A1 = pack2(a1s, a1s);
            const ull* wrow = (const ull*)&Wt[k * 128 + tx * 8];
            ull w0 = wrow[0], w1 = wrow[1], w2 = wrow[2], w3 = wrow[3];
            fma2(acc[0], A0, w0); fma2(acc[1], A0, w1); fma2(acc[2], A0, w2); fma2(acc[3], A0, w3);
            fma2(acc[4], A1, w0); fma2(acc[5], A1, w1); fma2(acc[6], A1, w2); fma2(acc[7], A1, w3);
        }
        __syncthreads();
    }
#pragma unroll
    for (int dr = 0; dr < 2; ++dr) {
        int g = g0 + 2 * ty + dr;
#pragma unroll
        for (int cp = 0; cp < 4; ++cp) {
            float2 v = unpack2(acc[dr * 4 + cp]);
            int n = n0 + tx * 8 + cp * 2;
            g_FWVW[(size_t)g * 1024 + n] = v.x;
            g_FWVW[(size_t)g * 1024 + n + 1] = v.y;
        }
    }
}

// =====================================================================
// HMMA GEMM, fp16 2-pass (A fp16, B hi/lo). CTA 128x256, warp 64x64,
// 3-stage pipeline. MODE: 0 ground L1, 1 ground L2, 2 text L1, 3 text L2
// =====================================================================
#define AHO 0
#define BHO 10240
#define BLO 27136
#define STG_SZ 44032
#define RED_O (3 * STG_SZ)
#define HM_SMEM (RED_O + 2048)

template<int MODE>
__global__ __launch_bounds__(256) void hmma_kernel(
    const float* __restrict__ span, const float* __restrict__ img,
    const float* __restrict__ bias1, const float* __restrict__ w3v)
{
    constexpr int KB  = (MODE == 2) ? 3072 : 1024;
    constexpr int NCH = KB / 32;
    extern __shared__ char sm[];
    const u32 smb = su32(sm);
    float* red = (float*)(sm + RED_O);
    const int t = threadIdx.x, w = t >> 5, lane = t & 31;
    const int wm = w >> 2, wn = w & 3;
    const int n0 = blockIdx.x * 256, p0 = blockIdx.y * 128;

    const __half *Wh, *Wl;
    if constexpr (MODE == 0) { Wh = g_Wp[0];  Wl = g_Wp[1];  }
    else if constexpr (MODE == 1) { Wh = g_W2[0];  Wl = g_W2[1];  }
    else if constexpr (MODE == 2) { Wh = g_tW1[0]; Wl = g_tW1[1]; }
    else { Wh = g_tW2[0]; Wl = g_tW2[1]; }
    const __half *Asrc = nullptr;
    if constexpr (MODE == 1) Asrc = g_h1;
    if constexpr (MODE == 3) Asrc = g_h1t;

    // ---- A-gen setup (MODE 0/2): thread -> row gr, k-half gh ----
    const int gr = t >> 1, gh = t & 1;
    const float *fp = nullptr, *vp = nullptr;
    if constexpr (MODE == 0) {
        int p = p0 + gr, i = p / 160, j = p - i * 160;
        fp = span + (size_t)i * 1024 + gh * 16;
        vp = img  + (size_t)j * 1024 + gh * 16;
    }
    if constexpr (MODE == 2) {
        int p = p0 + gr; if (p > 6239) p = 6239;
        int b = p / 780, q = p - b * 780, fi = 0, cnt = 39, rem = q;
        while (rem >= cnt) { rem -= cnt; fi++; cnt--; }
        fp = span + (size_t)(b * 40 + fi) * 1024 + gh * 16;
        vp = span + (size_t)(b * 40 + fi + 1 + rem) * 1024 + gh * 16;
    }

    // ldmatrix lane addressing
    const int lr = lane & 15, lh = lane >> 4;              // A
    const u32 a_lane = (u32)((wm * 64 + lr) * 80 + lh * 16);
    const int bg = lane >> 3, bk = lane & 7;               // B (.trans), stride 528
    const u32 b_lane = (u32)(((bg & 1) * 8 + bk) * 528 + (wn * 64 + (bg >> 1) * 8) * 2);

    float acc[4][8][4];
#pragma unroll
    for (int am = 0; am < 4; ++am)
#pragma unroll
        for (int nn = 0; nn < 8; ++nn) { acc[am][nn][0]=0.f; acc[am][nn][1]=0.f; acc[am][nn][2]=0.f; acc[am][nn][3]=0.f; }

    // ---- fill helpers ----
    auto fillB = [&](int cc, u32 sb) {
        int k0 = cc * 32;
#pragma unroll
        for (int it = 0; it < 8; ++it) {
            int idx = t + it * 256;
            int m = idx >> 10, rem = idx & 1023, row = rem >> 5, ch = rem & 31;
            const __half* src = (m ? Wl : Wh) + (size_t)(k0 + row) * 1024 + n0 + ch * 8;
            cpa16(sb + (m ? BLO : BHO) + row * 528 + ch * 16, src);
        }
    };
    auto fillA_async = [&](int cc, u32 sb) {
        if constexpr (MODE == 1 || MODE == 3) {
            int k0 = cc * 32;
#pragma unroll
            for (int it = 0; it < 2; ++it) {
                int idx = t + it * 256;
                int row = idx >> 2, ch = idx & 3;
                int prow = p0 + row; if (MODE == 3 && prow > 6239) prow = 6239;
                const __half* src = Asrc + (size_t)prow * 1024 + k0 + ch * 8;
                cpa16(sb + AHO + row * 80 + ch * 16, src);
            }
        }
    };
    auto ldgA = [&](int cc, float* xr, float* yr) {
        if constexpr (MODE == 0 || MODE == 2) {
            int db = (cc * 32) & 1023;
            const float *fa = fp + db, *vb = vp + db;
#pragma unroll
            for (int q = 0; q < 4; ++q) {
                float4 x = *(const float4*)(fa + q * 4);
                float4 y = *(const float4*)(vb + q * 4);
                xr[q*4+0]=x.x; xr[q*4+1]=x.y; xr[q*4+2]=x.z; xr[q*4+3]=x.w;
                yr[q*4+0]=y.x; yr[q*4+1]=y.y; yr[q*4+2]=y.z; yr[q*4+3]=y.w;
            }
        }
    };
    auto stsA = [&](int cc, u32 sb, const float* xr, const float* yr) {
        if constexpr (MODE == 0 || MODE == 2) {
            int reg = (cc * 32) >> 10;
            u32 hw[8];
#pragma unroll
            for (int q = 0; q < 8; ++q) {
                float z0, z1;
                if (MODE == 0 || reg == 2) { z0 = xr[2*q] * yr[2*q]; z1 = xr[2*q+1] * yr[2*q+1]; }
                else if (reg == 0) { z0 = xr[2*q]; z1 = xr[2*q+1]; }
                else { z0 = yr[2*q]; z1 = yr[2*q+1]; }
                hw[q] = hpack2(z0, z1);
            }
            u32 da = sb + AHO + gr * 80 + gh * 32;
            asm volatile("st.shared.v4.b32 [%0], {%1,%2,%3,%4};" :: "r"(da), "r"(hw[0]), "r"(hw[1]), "r"(hw[2]), "r"(hw[3]));
            asm volatile("st.shared.v4.b32 [%0], {%1,%2,%3,%4};" :: "r"(da+16), "r"(hw[4]), "r"(hw[5]), "r"(hw[6]), "r"(hw[7]));
        }
    };

    // ---- prologue: fill stages 0..1, one commit each ----
#pragma unroll
    for (int pc = 0; pc < 2; ++pc) {
        u32 sb = smb + (u32)pc * STG_SZ;
        fillB(pc, sb);
        if constexpr (MODE == 1 || MODE == 3) {
            fillA_async(pc, sb);
        } else {
            float xr[16], yr[16];
            ldgA(pc, xr, yr);
            stsA(pc, sb, xr, yr);
        }
        CP_COMMIT;
    }

    // ---- main loop ----
    for (int c = 0; c < NCH; ++c) {
        CP_WAIT1;
        __syncthreads();
        const u32 sb = smb + (u32)(c % 3) * STG_SZ;
        const bool nxt = (c + 2 < NCH);
        const u32 nb = smb + (u32)((c + 2) % 3) * STG_SZ;
        float xr[16], yr[16];
        if (nxt) {
            fillB(c + 2, nb);
            fillA_async(c + 2, nb);
            ldgA(c + 2, xr, yr);
        }
        // ---- compute: 2 k16 steps, 2 passes (A*Bh + A*Bl) ----
#pragma unroll
        for (int ks = 0; ks < 2; ++ks) {
            u32 ah[4][4];
#pragma unroll
            for (int am = 0; am < 4; ++am) {
                u32 aaddr = sb + a_lane + (u32)(am * 16 * 80 + ks * 32);
                LDSM4(ah[am], aaddr + AHO);
            }
#pragma unroll
            for (int gn = 0; gn < 4; ++gn) {
                u32 bh[4], bl[4];
                u32 baddr = sb + b_lane + (u32)(ks * 16 * 528 + gn * 32);
                LDSM4T(bh, baddr + BHO);
                LDSM4T(bl, baddr + BLO);
#pragma unroll
                for (int am = 0; am < 4; ++am)
#pragma unroll
                    for (int sub = 0; sub < 2; ++sub) {
                        float* cc4 = acc[am][gn * 2 + sub];
                        mma_f16(cc4, ah[am], bh[sub*2], bh[sub*2+1]);
                        mma_f16(cc4, ah[am], bl[sub*2], bl[sub*2+1]);
                    }
            }
        }
        if (nxt) stsA(c + 2, nb, xr, yr);
        CP_COMMIT;
    }

    // ---------------- epilogue ----------------
    if constexpr (MODE == 0 || MODE == 2) {
        __half* OH = (MODE == 0) ? g_h1 : g_h1t;
#pragma unroll
        for (int am = 0; am < 4; ++am) {
            int row0 = p0 + wm * 64 + am * 16 + (lane >> 2);
#pragma unroll
            for (int h = 0; h < 2; ++h) {
                int p = row0 + h * 8;
                bool act = (MODE == 0) || (p < 6240);
                const float *fw = nullptr, *vw = nullptr;
                if constexpr (MODE == 0) {
                    int i = p / 160, j = p - i * 160;
                    fw = g_FWVW + (size_t)i * 1024;
                    vw = g_FWVW + (size_t)(320 + j) * 1024;
                }
#pragma unroll
                for (int nn = 0; nn < 8; ++nn) {
                    int col = n0 + wn * 64 + nn * 8 + (lane & 3) * 2;
                    float v0 = acc[am][nn][h * 2 + 0];
                    float v1 = acc[am][nn][h * 2 + 1];
                    float x0 = v0 + bias1[col], x1 = v1 + bias1[col + 1];
                    if (MODE == 0) { x0 += fw[col] + vw[col]; x1 += fw[col + 1] + vw[col + 1]; }
                    x0 = fmaxf(x0, 0.f); x1 = fmaxf(x1, 0.f);
                    if (act) *(u32*)(OH + (size_t)p * 1024 + col) = hpack2(x0, x1);
                }
            }
        }
    } else {
        float s[8];
#pragma unroll
        for (int q = 0; q < 8; ++q) s[q] = 0.f;
#pragma unroll
        for (int am = 0; am < 4; ++am)
#pragma unroll
            for (int nn = 0; nn < 8; ++nn) {
                int col = n0 + wn * 64 + nn * 8 + (lane & 3) * 2;
                float b0 = bias1[col], b1v = bias1[col + 1];
                float w0 = w3v[col],  w1v = w3v[col + 1];
                s[am*2+0] += fmaxf(acc[am][nn][0] + b0, 0.f) * w0 + fmaxf(acc[am][nn][1] + b1v, 0.f) * w1v;
                s[am*2+1] += fmaxf(acc[am][nn][2] + b0, 0.f) * w0 + fmaxf(acc[am][nn][3] + b1v, 0.f) * w1v;
            }
#pragma unroll
        for (int q = 0; q < 8; ++q) {
            float v = s[q];
            v += __shfl_xor_sync(0xffffffffu, v, 1);
            v += __shfl_xor_sync(0xffffffffu, v, 2);
            if ((lane & 3) == 0) {
                int rowl = wm * 64 + (q >> 1) * 16 + (lane >> 2) + (q & 1) * 8;
                red[wn * 128 + rowl] = v;
            }
        }
        __syncthreads();
        if (t < 128) {
            int pp = p0 + t;
            float v = red[t] + red[128 + t] + red[256 + t] + red[384 + t];
            if (MODE == 1) g_part[(size_t)pp * 4 + blockIdx.x] = v;
            else if (pp < 6240) g_partt[(size_t)pp * 4 + blockIdx.x] = v;
        }
    }
}

// =====================================================================
// finalize + reductions
// =====================================================================
__global__ void fin_g(const float* __restrict__ smask, const float* __restrict__ imask,
                      const float* __restrict__ gb3, float* __restrict__ out_g)
{
    int p = blockIdx.x * 256 + threadIdx.x;
    float s = gb3[0];
#pragma unroll
    for (int nb = 0; nb < 4; ++nb) s += g_part[(size_t)p * 4 + nb];
    int i = p / 160, j = p - i * 160;
    out_g[p] = s * (smask[i] * imask[j]);
}

__global__ void fin_t(const float* __restrict__ tb3, float* __restrict__ out_t)
{
    int p = blockIdx.x * 256 + threadIdx.x;
    if (p >= 6240) return;
    float s = tb3[0];
#pragma unroll
    for (int nb = 0; nb < 4; ++nb) s += g_partt[(size_t)p * 4 + nb];
    out_t[p] = s;
}

__global__ void sreduce_kernel(const float* __restrict__ gsc) {
    __shared__ float red[256];
    int k = blockIdx.x;
    float s = 0.f;
    for (int idx = threadIdx.x; idx < 800; idx += 256) s += gsc[k * 800 + idx];
    red[threadIdx.x] = s;
    __syncthreads();
    for (int st = 128; st > 0; st >>= 1) {
        if (threadIdx.x < st) red[threadIdx.x] += red[threadIdx.x + st];
        __syncthreads();
    }
    if (threadIdx.x == 0) g_S[k] = red[0];
}

__global__ void loss_kernel(float* __restrict__ out) {
    if (threadIdx.x == 0) {
        float S[64];
        for (int k = 0; k < 64; ++k) S[k] = g_S[k];
        float lr = 0.f, lc = 0.f, tot = 0.f;
        for (int r = 0; r < 8; ++r) {
            float m = -1e30f;
            for (int c = 0; c < 8; ++c) m = fmaxf(m, S[r * 8 + c]);
            float e = 0.f;
            for (int c = 0; c < 8; ++c) e += expf(S[r * 8 + c] - m);
            lr += m + logf(e);
        }
        for (int c = 0; c < 8; ++c) {
            float m = -1e30f;
            for (int r = 0; r < 8; ++r) m = fmaxf(m, S[r * 8 + c]);
            float e = 0.f;
            for (int r = 0; r < 8; ++r) e += expf(S[r * 8 + c] - m);
            lc += m + logf(e);
        }
        for (int k = 0; k < 64; ++k) tot += S[k];
        out[0] = -(2.f * tot - 8.f * (lr + lc)) / 8.f;
    }
}

// =====================================================================
extern "C" void kernel_launch(void* const* d_in, const int* in_sizes, int n_in,
                              void* d_out, int out_size) {
    (void)in_sizes; (void)n_in; (void)out_size;
    const float* span  = (const float*)d_in[0];
    const float* img   = (const float*)d_in[1];
    const float* smask = (const float*)d_in[2];
    const float* imask = (const float*)d_in[3];
    const float* tW1 = (const float*)d_in[4];  const float* tb1 = (const float*)d_in[5];
    const float* tW2 = (const float*)d_in[6];  const float* tb2 = (const float*)d_in[7];
    const float* tW3 = (const float*)d_in[8];  const float* tb3 = (const float*)d_in[9];
    const float* gW1 = (const float*)d_in[10]; const float* gb1 = (const float*)d_in[11];
    const float* gW2 = (const float*)d_in[12]; const float* gb2 = (const float*)d_in[13];
    const float* gW3 = (const float*)d_in[14]; const float* gb3 = (const float*)d_in[15];
    float* out = (float*)d_out;

    cudaFuncSetAttribute(hmma_kernel<0>, cudaFuncAttributeMaxDynamicSharedMemorySize, HM_SMEM);
    cudaFuncSetAttribute(hmma_kernel<1>, cudaFuncAttributeMaxDynamicSharedMemorySize, HM_SMEM);
    cudaFuncSetAttribute(hmma_kernel<2>, cudaFuncAttributeMaxDynamicSharedMemorySize, HM_SMEM);
    cudaFuncSetAttribute(hmma_kernel<3>, cudaFuncAttributeMaxDynamicSharedMemorySize, HM_SMEM);

    wconv<0><<<4096,  256>>>(gW1 + (size_t)2 * 1024 * 1024, 1024 * 1024);
    wconv<1><<<4096,  256>>>(gW2, 1024 * 1024);
    wconv<2><<<12288, 256>>>(tW1, 3072 * 1024);
    wconv<3><<<4096,  256>>>(tW2, 1024 * 1024);
    fwvw_kernel<<<dim3(15, 8), 256>>>(span, img, gW1);

    hmma_kernel<0><<<dim3(4, 400), 256, HM_SMEM>>>(span, img, gb1, nullptr);
    hmma_kernel<1><<<dim3(4, 400), 256, HM_SMEM>>>(nullptr, nullptr, gb2, gW3);
    hmma_kernel<2><<<dim3(4, 49),  256, HM_SMEM>>>(span, nullptr, tb1, nullptr);
    hmma_kernel<3><<<dim3(4, 49),  256, HM_SMEM>>>(nullptr, nullptr, tb2, tW3);

    fin_g<<<200, 256>>>(smask, imask, gb3, out + 1);
    fin_t<<<25, 256>>>(tb3, out + 1 + 51200);
    sreduce_kernel<<<64, 256>>>(out + 1);
    loss_kernel<<<1, 32>>>(out);
}

// round 9
// speedup vs baseline: 4.4837x; 1.5593x over previous
#include <cuda_runtime.h>
#include <cuda_fp16.h>
#include <cstdint>

typedef unsigned long long ull;
typedef unsigned int u32;

// ---------------- helpers ----------------
__device__ __forceinline__ ull pack2(float x, float y) {
    ull r; asm("mov.b64 %0, {%1, %2};" : "=l"(r) : "f"(x), "f"(y)); return r;
}
__device__ __forceinline__ void fma2(ull& acc, ull a, ull b) {
    asm("fma.rn.f32x2 %0, %1, %2, %0;" : "+l"(acc) : "l"(a), "l"(b));
}
__device__ __forceinline__ float2 unpack2(ull a) {
    float2 r; asm("mov.b64 {%0, %1}, %2;" : "=f"(r.x), "=f"(r.y) : "l"(a)); return r;
}
__device__ __forceinline__ u32 su32(const void* p) {
    u32 a;
    asm("{ .reg .u64 t; cvta.to.shared.u64 t, %1; cvt.u32.u64 %0, t; }" : "=r"(a) : "l"(p));
    return a;
}
__device__ __forceinline__ void cpa16(u32 s, const void* g) {
    asm volatile("cp.async.cg.shared.global [%0], [%1], 16;" :: "r"(s), "l"(g));
}
#define CP_COMMIT asm volatile("cp.async.commit_group;")
#define CP_WAIT1  asm volatile("cp.async.wait_group 1;")

#define LDSM4(r, a) \
    asm volatile("ldmatrix.sync.aligned.m8n8.x4.shared.b16 {%0,%1,%2,%3}, [%4];" \
        : "=r"((r)[0]), "=r"((r)[1]), "=r"((r)[2]), "=r"((r)[3]) : "r"(a))
#define LDSM4T(r, a) \
    asm volatile("ldmatrix.sync.aligned.m8n8.x4.trans.shared.b16 {%0,%1,%2,%3}, [%4];" \
        : "=r"((r)[0]), "=r"((r)[1]), "=r"((r)[2]), "=r"((r)[3]) : "r"(a))

__device__ __forceinline__ void mma_f16(float* c, const u32* a, u32 b0, u32 b1) {
    asm volatile(
        "mma.sync.aligned.m16n8k16.row.col.f32.f16.f16.f32 "
        "{%0,%1,%2,%3}, {%4,%5,%6,%7}, {%8,%9}, {%0,%1,%2,%3};"
        : "+f"(c[0]), "+f"(c[1]), "+f"(c[2]), "+f"(c[3])
        : "r"(a[0]), "r"(a[1]), "r"(a[2]), "r"(a[3]), "r"(b0), "r"(b1));
}
__device__ __forceinline__ u32 hpack2(float a, float b) {
    __half2 h = __floats2half2_rn(a, b);
    return *(u32*)&h;
}

// ---------------- scratch ----------------
__device__ float g_FWVW[480 * 1024];
__device__ float g_S[64];
__device__ __half g_Wp[1024 * 1024];
__device__ __half g_W2[1024 * 1024];
__device__ __half g_tW1[(size_t)3072 * 1024];
__device__ __half g_tW2[1024 * 1024];
__device__ __half g_h1[(size_t)51200 * 1024];
__device__ __half g_h1t[(size_t)6272 * 1024];
__device__ float g_part[(size_t)51200 * 4];
__device__ float g_partt[6240 * 4];

// =====================================================================
// weight fp16 convert (single precision level — single-pass MMA)
// =====================================================================
template<int WSEL>
__global__ void wconv(const float* __restrict__ W, int n)
{
    __half* dst;
    if constexpr (WSEL == 0) dst = g_Wp;
    else if constexpr (WSEL == 1) dst = g_W2;
    else if constexpr (WSEL == 2) dst = g_tW1;
    else dst = g_tW2;
    int i = blockIdx.x * 256 + threadIdx.x;
    if (i < n) dst[i] = __float2half_rn(W[i]);
}

// =====================================================================
// FW/VW precompute (exact fp32)
// =====================================================================
__global__ __launch_bounds__(256) void fwvw_kernel(
    const float* __restrict__ span, const float* __restrict__ img,
    const float* __restrict__ gW1)
{
    __shared__ float At[32 * 33];
    __shared__ float Wt[32 * 128];
    const int g0 = blockIdx.x * 32;
    const int n0 = blockIdx.y * 128;
    const int t = threadIdx.x, tx = t & 15, ty = t >> 4;
    const bool isv = (g0 >= 320);
    const float* Wsrc = gW1 + (isv ? (size_t)1024 * 1024 : 0);

    ull acc[8] = {0,0,0,0,0,0,0,0};
    for (int kt = 0; kt < 32; ++kt) {
#pragma unroll
        for (int it = 0; it < 4; ++it) {
            int idx = t + it * 256; int k = idx & 31, r = idx >> 5;
            int g = g0 + r;
            const float* srow = isv ? (img + (size_t)(g - 320) * 1024) : (span + (size_t)g * 1024);
            At[k * 33 + r] = srow[kt * 32 + k];
        }
#pragma unroll
        for (int it = 0; it < 4; ++it) {
            int idx = t + it * 256; int kk = idx >> 5, c4 = idx & 31;
            ((float4*)Wt)[kk * 32 + c4] =
                *(const float4*)&Wsrc[(size_t)(kt * 32 + kk) * 1024 + n0 + c4 * 4];
        }
        __syncthreads();
#pragma unroll
        for (int k = 0; k < 32; ++k) {
            float a0s = At[k * 33 + 2 * ty], a1s = At[k * 33 + 2 * ty + 1];
            ull A0 = pack2(a0s, a0s), A1 = pack2(a1s, a1s);
            const ull* wrow = (const ull*)&Wt[k * 128 + tx * 8];
            ull w0 = wrow[0], w1 = wrow[1], w2 = wrow[2], w3 = wrow[3];
            fma2(acc[0], A0, w0); fma2(acc[1], A0, w1); fma2(acc[2], A0, w2); fma2(acc[3], A0, w3);
            fma2(acc[4], A1, w0); fma2(acc[5], A1, w1); fma2(acc[6], A1, w2); fma2(acc[7], A1, w3);
        }
        __syncthreads();
    }
#pragma unroll
    for (int dr = 0; dr < 2; ++dr) {
        int g = g0 + 2 * ty + dr;
#pragma unroll
        for (int cp = 0; cp < 4; ++cp) {
            float2 v = unpack2(acc[dr * 4 + cp]);
            int n = n0 + tx * 8 + cp * 2;
            g_FWVW[(size_t)g * 1024 + n] = v.x;
            g_FWVW[(size_t)g * 1024 + n + 1] = v.y;
        }
    }
}

// =====================================================================
// Single-pass fp16 HMMA GEMM body. CTA 128x256, warp 64x64, 3 stages.
// MODE: 0 ground L1, 1 ground L2, 2 text L1 (K=3072), 3 text L2
// =====================================================================
#define AHO 0
#define BHO 10240
#define STG_SZ 27136
#define RED_O (3 * STG_SZ)
#define HM_SMEM (RED_O + 2048)

template<int MODE>
__device__ __forceinline__ void gemm_body(
    int nb, int pb,
    const float* __restrict__ span, const float* __restrict__ img,
    const float* __restrict__ bias1, const float* __restrict__ w3v,
    char* sm)
{
    constexpr int KB  = (MODE == 2) ? 3072 : 1024;
    constexpr int NCH = KB / 32;
    const u32 smb = su32(sm);
    float* red = (float*)(sm + RED_O);
    const int t = threadIdx.x, w = t >> 5, lane = t & 31;
    const int wm = w >> 2, wn = w & 3;
    const int n0 = nb * 256, p0 = pb * 128;

    const __half* Wh;
    if constexpr (MODE == 0) Wh = g_Wp;
    else if constexpr (MODE == 1) Wh = g_W2;
    else if constexpr (MODE == 2) Wh = g_tW1;
    else Wh = g_tW2;
    const __half* Asrc = nullptr;
    if constexpr (MODE == 1) Asrc = g_h1;
    if constexpr (MODE == 3) Asrc = g_h1t;

    // ---- A-gen setup (MODE 0/2): thread -> row gr, k-half gh ----
    const int gr = t >> 1, gh = t & 1;
    const float *fp = nullptr, *vp = nullptr;
    if constexpr (MODE == 0) {
        int p = p0 + gr, i = p / 160, j = p - i * 160;
        fp = span + (size_t)i * 1024 + gh * 16;
        vp = img  + (size_t)j * 1024 + gh * 16;
    }
    if constexpr (MODE == 2) {
        int p = p0 + gr; if (p > 6239) p = 6239;
        int b = p / 780, q = p - b * 780, fi = 0, cnt = 39, rem = q;
        while (rem >= cnt) { rem -= cnt; fi++; cnt--; }
        fp = span + (size_t)(b * 40 + fi) * 1024 + gh * 16;
        vp = span + (size_t)(b * 40 + fi + 1 + rem) * 1024 + gh * 16;
    }

    // ldmatrix lane addressing
    const int lr = lane & 15, lh = lane >> 4;              // A
    const u32 a_lane = (u32)((wm * 64 + lr) * 80 + lh * 16);
    const int bg = lane >> 3, bk = lane & 7;               // B (.trans), stride 528
    const u32 b_lane = (u32)(((bg & 1) * 8 + bk) * 528 + (wn * 64 + (bg >> 1) * 8) * 2);

    float acc[4][8][4];
#pragma unroll
    for (int am = 0; am < 4; ++am)
#pragma unroll
        for (int nn = 0; nn < 8; ++nn) { acc[am][nn][0]=0.f; acc[am][nn][1]=0.f; acc[am][nn][2]=0.f; acc[am][nn][3]=0.f; }

    // ---- fill helpers ----
    auto fillB = [&](int cc, u32 sb) {
        int k0 = cc * 32;
#pragma unroll
        for (int it = 0; it < 4; ++it) {
            int idx = t + it * 256;
            int row = idx >> 5, ch = idx & 31;
            const __half* src = Wh + (size_t)(k0 + row) * 1024 + n0 + ch * 8;
            cpa16(sb + BHO + row * 528 + ch * 16, src);
        }
    };
    auto fillA_async = [&](int cc, u32 sb) {
        if constexpr (MODE == 1 || MODE == 3) {
            int k0 = cc * 32;
#pragma unroll
            for (int it = 0; it < 2; ++it) {
                int idx = t + it * 256;
                int row = idx >> 2, ch = idx & 3;
                int prow = p0 + row; if (MODE == 3 && prow > 6239) prow = 6239;
                const __half* src = Asrc + (size_t)prow * 1024 + k0 + ch * 8;
                cpa16(sb + AHO + row * 80 + ch * 16, src);
            }
        }
    };
    auto ldgA = [&](int cc, float* xr, float* yr) {
        if constexpr (MODE == 0 || MODE == 2) {
            int db = (cc * 32) & 1023;
            const float *fa = fp + db, *vb = vp + db;
#pragma unroll
            for (int q = 0; q < 4; ++q) {
                float4 x = *(const float4*)(fa + q * 4);
                float4 y = *(const float4*)(vb + q * 4);
                xr[q*4+0]=x.x; xr[q*4+1]=x.y; xr[q*4+2]=x.z; xr[q*4+3]=x.w;
                yr[q*4+0]=y.x; yr[q*4+1]=y.y; yr[q*4+2]=y.z; yr[q*4+3]=y.w;
            }
        }
    };
    auto stsA = [&](int cc, u32 sb, const float* xr, const float* yr) {
        if constexpr (MODE == 0 || MODE == 2) {
            int reg = (cc * 32) >> 10;
            u32 hw[8];
#pragma unroll
            for (int q = 0; q < 8; ++q) {
                float z0, z1;
                if (MODE == 0 || reg == 2) { z0 = xr[2*q] * yr[2*q]; z1 = xr[2*q+1] * yr[2*q+1]; }
                else if (reg == 0) { z0 = xr[2*q]; z1 = xr[2*q+1]; }
                else { z0 = yr[2*q]; z1 = yr[2*q+1]; }
                hw[q] = hpack2(z0, z1);
            }
            u32 da = sb + AHO + gr * 80 + gh * 32;
            asm volatile("st.shared.v4.b32 [%0], {%1,%2,%3,%4};" :: "r"(da), "r"(hw[0]), "r"(hw[1]), "r"(hw[2]), "r"(hw[3]));
            asm volatile("st.shared.v4.b32 [%0], {%1,%2,%3,%4};" :: "r"(da+16), "r"(hw[4]), "r"(hw[5]), "r"(hw[6]), "r"(hw[7]));
        }
    };

    // ---- prologue: fill stages 0..1 ----
#pragma unroll
    for (int pc = 0; pc < 2; ++pc) {
        u32 sb = smb + (u32)pc * STG_SZ;
        fillB(pc, sb);
        if constexpr (MODE == 1 || MODE == 3) {
            fillA_async(pc, sb);
        } else {
            float xr[16], yr[16];
            ldgA(pc, xr, yr);
            stsA(pc, sb, xr, yr);
        }
        CP_COMMIT;
    }

    // ---- main loop ----
    for (int c = 0; c < NCH; ++c) {
        CP_WAIT1;
        __syncthreads();
        const u32 sb = smb + (u32)(c % 3) * STG_SZ;
        const bool nxt = (c + 2 < NCH);
        const u32 nbuf = smb + (u32)((c + 2) % 3) * STG_SZ;
        float xr[16], yr[16];
        if (nxt) {
            fillB(c + 2, nbuf);
            fillA_async(c + 2, nbuf);
            ldgA(c + 2, xr, yr);
        }
        // ---- compute: 2 k16 steps, single pass ----
#pragma unroll
        for (int ks = 0; ks < 2; ++ks) {
            u32 ah[4][4];
#pragma unroll
            for (int am = 0; am < 4; ++am) {
                u32 aaddr = sb + a_lane + (u32)(am * 16 * 80 + ks * 32);
                LDSM4(ah[am], aaddr + AHO);
            }
#pragma unroll
            for (int gn = 0; gn < 4; ++gn) {
                u32 bh[4];
                u32 baddr = sb + b_lane + (u32)(ks * 16 * 528 + gn * 32);
                LDSM4T(bh, baddr + BHO);
#pragma unroll
                for (int am = 0; am < 4; ++am)
#pragma unroll
                    for (int sub = 0; sub < 2; ++sub)
                        mma_f16(acc[am][gn * 2 + sub], ah[am], bh[sub*2], bh[sub*2+1]);
            }
        }
        if (nxt) stsA(c + 2, nbuf, xr, yr);
        CP_COMMIT;
    }

    // ---------------- epilogue ----------------
    if constexpr (MODE == 0 || MODE == 2) {
        __half* OH = (MODE == 0) ? g_h1 : g_h1t;
#pragma unroll
        for (int am = 0; am < 4; ++am) {
            int row0 = p0 + wm * 64 + am * 16 + (lane >> 2);
#pragma unroll
            for (int h = 0; h < 2; ++h) {
                int p = row0 + h * 8;
                bool act = (MODE == 0) || (p < 6240);
                const float *fw = nullptr, *vw = nullptr;
                if constexpr (MODE == 0) {
                    int i = p / 160, j = p - i * 160;
                    fw = g_FWVW + (size_t)i * 1024;
                    vw = g_FWVW + (size_t)(320 + j) * 1024;
                }
#pragma unroll
                for (int nn = 0; nn < 8; ++nn) {
                    int col = n0 + wn * 64 + nn * 8 + (lane & 3) * 2;
                    float v0 = acc[am][nn][h * 2 + 0];
                    float v1 = acc[am][nn][h * 2 + 1];
                    float x0 = v0 + bias1[col], x1 = v1 + bias1[col + 1];
                    if (MODE == 0) { x0 += fw[col] + vw[col]; x1 += fw[col + 1] + vw[col + 1]; }
                    x0 = fmaxf(x0, 0.f); x1 = fmaxf(x1, 0.f);
                    if (act) *(u32*)(OH + (size_t)p * 1024 + col) = hpack2(x0, x1);
                }
            }
        }
    } else {
        float s[8];
#pragma unroll
        for (int q = 0; q < 8; ++q) s[q] = 0.f;
#pragma unroll
        for (int am = 0; am < 4; ++am)
#pragma unroll
            for (int nn = 0; nn < 8; ++nn) {
                int col = n0 + wn * 64 + nn * 8 + (lane & 3) * 2;
                float b0 = bias1[col], b1v = bias1[col + 1];
                float w0 = w3v[col],  w1v = w3v[col + 1];
                s[am*2+0] += fmaxf(acc[am][nn][0] + b0, 0.f) * w0 + fmaxf(acc[am][nn][1] + b1v, 0.f) * w1v;
                s[am*2+1] += fmaxf(acc[am][nn][2] + b0, 0.f) * w0 + fmaxf(acc[am][nn][3] + b1v, 0.f) * w1v;
            }
#pragma unroll
        for (int q = 0; q < 8; ++q) {
            float v = s[q];
            v += __shfl_xor_sync(0xffffffffu, v, 1);
            v += __shfl_xor_sync(0xffffffffu, v, 2);
            if ((lane & 3) == 0) {
                int rowl = wm * 64 + (q >> 1) * 16 + (lane >> 2) + (q & 1) * 8;
                red[wn * 128 + rowl] = v;
            }
        }
        __syncthreads();
        if (t < 128) {
            int pp = p0 + t;
            float v = red[t] + red[128 + t] + red[256 + t] + red[384 + t];
            if (MODE == 1) g_part[(size_t)pp * 4 + nb] = v;
            else if (pp < 6240) g_partt[(size_t)pp * 4 + nb] = v;
        }
    }
}

// =====================================================================
// Combined phase kernels: long text CTAs first, grounding fills behind.
// PHASE 1: t1 (196 blocks) + g1 (1600).  PHASE 2: t2 + g2.
// =====================================================================
template<int PHASE>
__global__ __launch_bounds__(256) void comb_kernel(
    const float* __restrict__ span, const float* __restrict__ img,
    const float* __restrict__ gb1, const float* __restrict__ tb1,
    const float* __restrict__ gb2, const float* __restrict__ gw3,
    const float* __restrict__ tb2, const float* __restrict__ tw3)
{
    extern __shared__ char sm[];
    int bx = blockIdx.x;
    if constexpr (PHASE == 1) {
        if (bx < 196) gemm_body<2>(bx & 3, bx >> 2, span, img, tb1, nullptr, sm);
        else { int i = bx - 196; gemm_body<0>(i & 3, i >> 2, span, img, gb1, nullptr, sm); }
    } else {
        if (bx < 196) gemm_body<3>(bx & 3, bx >> 2, span, img, tb2, tw3, sm);
        else { int i = bx - 196; gemm_body<1>(i & 3, i >> 2, span, img, gb2, gw3, sm); }
    }
}

// =====================================================================
// finalize + reductions
// =====================================================================
__global__ void fin_g(const float* __restrict__ smask, const float* __restrict__ imask,
                      const float* __restrict__ gb3, float* __restrict__ out_g)
{
    int p = blockIdx.x * 256 + threadIdx.x;
    float s = gb3[0];
#pragma unroll
    for (int nb = 0; nb < 4; ++nb) s += g_part[(size_t)p * 4 + nb];
    int i = p / 160, j = p - i * 160;
    out_g[p] = s * (smask[i] * imask[j]);
}

__global__ void fin_t(const float* __restrict__ tb3, float* __restrict__ out_t)
{
    int p = blockIdx.x * 256 + threadIdx.x;
    if (p >= 6240) return;
    float s = tb3[0];
#pragma unroll
    for (int nb = 0; nb < 4; ++nb) s += g_partt[(size_t)p * 4 + nb];
    out_t[p] = s;
}

__global__ void sreduce_kernel(const float* __restrict__ gsc) {
    __shared__ float red[256];
    int k = blockIdx.x;
    float s = 0.f;
    for (int idx = threadIdx.x; idx < 800; idx += 256) s += gsc[k * 800 + idx];
    red[threadIdx.x] = s;
    __syncthreads();
    for (int st = 128; st > 0; st >>= 1) {
        if (threadIdx.x < st) red[threadIdx.x] += red[threadIdx.x + st];
        __syncthreads();
    }
    if (threadIdx.x == 0) g_S[k] = red[0];
}

__global__ void loss_kernel(float* __restrict__ out) {
    if (threadIdx.x == 0) {
        float S[64];
        for (int k = 0; k < 64; ++k) S[k] = g_S[k];
        float lr = 0.f, lc = 0.f, tot = 0.f;
        for (int r = 0; r < 8; ++r) {
            float m = -1e30f;
            for (int c = 0; c < 8; ++c) m = fmaxf(m, S[r * 8 + c]);
            float e = 0.f;
            for (int c = 0; c < 8; ++c) e += expf(S[r * 8 + c] - m);
            lr += m + logf(e);
        }
        for (int c = 0; c < 8; ++c) {
            float m = -1e30f;
            for (int r = 0; r < 8; ++r) m = fmaxf(m, S[r * 8 + c]);
            float e = 0.f;
            for (int r = 0; r < 8; ++r) e += expf(S[r * 8 + c] - m);
            lc += m + logf(e);
        }
        for (int k = 0; k < 64; ++k) tot += S[k];
        out[0] = -(2.f * tot - 8.f * (lr + lc)) / 8.f;
    }
}

// =====================================================================
extern "C" void kernel_launch(void* const* d_in, const int* in_sizes, int n_in,
                              void* d_out, int out_size) {
    (void)in_sizes; (void)n_in; (void)out_size;
    const float* span  = (const float*)d_in[0];
    const float* img   = (const float*)d_in[1];
    const float* smask = (const float*)d_in[2];
    const float* imask = (const float*)d_in[3];
    const float* tW1 = (const float*)d_in[4];  const float* tb1 = (const float*)d_in[5];
    const float* tW2 = (const float*)d_in[6];  const float* tb2 = (const float*)d_in[7];
    const float* tW3 = (const float*)d_in[8];  const float* tb3 = (const float*)d_in[9];
    const float* gW1 = (const float*)d_in[10]; const float* gb1 = (const float*)d_in[11];
    const float* gW2 = (const float*)d_in[12]; const float* gb2 = (const float*)d_in[13];
    const float* gW3 = (const float*)d_in[14]; const float* gb3 = (const float*)d_in[15];
    float* out = (float*)d_out;

    cudaFuncSetAttribute(comb_kernel<1>, cudaFuncAttributeMaxDynamicSharedMemorySize, HM_SMEM);
    cudaFuncSetAttribute(comb_kernel<2>, cudaFuncAttributeMaxDynamicSharedMemorySize, HM_SMEM);

    wconv<0><<<4096,  256>>>(gW1 + (size_t)2 * 1024 * 1024, 1024 * 1024);
    wconv<1><<<4096,  256>>>(gW2, 1024 * 1024);
    wconv<2><<<12288, 256>>>(tW1, 3072 * 1024);
    wconv<3><<<4096,  256>>>(tW2, 1024 * 1024);
    fwvw_kernel<<<dim3(15, 8), 256>>>(span, img, gW1);

    comb_kernel<1><<<1796, 256, HM_SMEM>>>(span, img, gb1, tb1, gb2, gW3, tb2, tW3);
    comb_kernel<2><<<1796, 256, HM_SMEM>>>(span, img, gb1, tb1, gb2, gW3, tb2, tW3);

    fin_g<<<200, 256>>>(smask, imask, gb3, out + 1);
    fin_t<<<25, 256>>>(tb3, out + 1 + 51200);
    sreduce_kernel<<<64, 256>>>(out + 1);
    loss_kernel<<<1, 32>>>(out);
}

// round 10
// speedup vs baseline: 5.0652x; 1.1297x over previous
#include <cuda_runtime.h>
#include <cuda_fp16.h>
#include <cstdint>

typedef unsigned long long ull;
typedef unsigned int u32;

// ---------------- helpers ----------------
__device__ __forceinline__ u32 su32(const void* p) {
    u32 a;
    asm("{ .reg .u64 t; cvta.to.shared.u64 t, %1; cvt.u32.u64 %0, t; }" : "=r"(a) : "l"(p));
    return a;
}
__device__ __forceinline__ void cpa16(u32 s, const void* g) {
    asm volatile("cp.async.cg.shared.global [%0], [%1], 16;" :: "r"(s), "l"(g));
}
#define CP_COMMIT asm volatile("cp.async.commit_group;")
#define CP_WAIT1  asm volatile("cp.async.wait_group 1;")

#define LDSM4(r, a) \
    asm volatile("ldmatrix.sync.aligned.m8n8.x4.shared.b16 {%0,%1,%2,%3}, [%4];" \
        : "=r"((r)[0]), "=r"((r)[1]), "=r"((r)[2]), "=r"((r)[3]) : "r"(a))
#define LDSM4T(r, a) \
    asm volatile("ldmatrix.sync.aligned.m8n8.x4.trans.shared.b16 {%0,%1,%2,%3}, [%4];" \
        : "=r"((r)[0]), "=r"((r)[1]), "=r"((r)[2]), "=r"((r)[3]) : "r"(a))

__device__ __forceinline__ void mma_f16(float* c, const u32* a, u32 b0, u32 b1) {
    asm volatile(
        "mma.sync.aligned.m16n8k16.row.col.f32.f16.f16.f32 "
        "{%0,%1,%2,%3}, {%4,%5,%6,%7}, {%8,%9}, {%0,%1,%2,%3};"
        : "+f"(c[0]), "+f"(c[1]), "+f"(c[2]), "+f"(c[3])
        : "r"(a[0]), "r"(a[1]), "r"(a[2]), "r"(a[3]), "r"(b0), "r"(b1));
}
__device__ __forceinline__ u32 hpack2(float a, float b) {
    __half2 h = __floats2half2_rn(a, b);
    return *(u32*)&h;
}

// ---------------- scratch ----------------
__device__ float g_FWVW[480 * 1024];     // 0..319 f@gW1f, 320..479 v@gW1s
__device__ float g_TXT[640 * 1024];      // 0..319 s@tW1f, 320..639 s@tW1s
__device__ float g_S[64];
__device__ __half g_gW1h[(size_t)3072 * 1024];
__device__ __half g_tW1h[(size_t)3072 * 1024];
__device__ __half g_W2[1024 * 1024];
__device__ __half g_tW2[1024 * 1024];
__device__ __half g_h1[(size_t)51200 * 1024];
__device__ __half g_h1t[(size_t)6272 * 1024];
__device__ float g_part[(size_t)51200 * 4];
__device__ float g_partt[6240 * 4];

// =====================================================================
// vectorized fp32 -> fp16 weight convert (8 elem/thread)
// =====================================================================
template<int WSEL>
__global__ void wconv(const float* __restrict__ W)
{
    __half* dst;
    if constexpr (WSEL == 0) dst = g_gW1h;
    else if constexpr (WSEL == 1) dst = g_W2;
    else if constexpr (WSEL == 2) dst = g_tW1h;
    else dst = g_tW2;
    int i = (blockIdx.x * 256 + threadIdx.x) * 8;
    float4 a = *(const float4*)(W + i);
    float4 b = *(const float4*)(W + i + 4);
    u32 o0 = hpack2(a.x, a.y), o1 = hpack2(a.z, a.w);
    u32 o2 = hpack2(b.x, b.y), o3 = hpack2(b.z, b.w);
    *(uint4*)(dst + i) = make_uint4(o0, o1, o2, o3);
}

// =====================================================================
// GEMM tiling constants (CTA 128x256, warp 64x64, 3 stages)
// =====================================================================
#define AHO 0
#define BHO 10240
#define STG_SZ 27136
#define RED_O (3 * STG_SZ)
#define HM_SMEM (RED_O + 2048)

// =====================================================================
// prep kernel: fp16-MMA projections of span/img rows through W slices
// 44 blocks: [0,12) span@gW1f; [12,20) img@gW1s; [20,32) span@tW1f; [32,44) span@tW1s
// =====================================================================
__global__ __launch_bounds__(256) void prep_kernel(
    const float* __restrict__ span, const float* __restrict__ img)
{
    extern __shared__ char sm[];
    const u32 smb = su32(sm);
    const int t = threadIdx.x, w = t >> 5, lane = t & 31;
    const int wm = w >> 2, wn = w & 3;

    int bid = blockIdx.x;
    const float* asrc; const __half* Wh; float* dst; int lim, lb;
    if (bid < 12)      { lb = bid;      asrc = span; Wh = g_gW1h;               dst = g_FWVW;               lim = 320; }
    else if (bid < 20) { lb = bid - 12; asrc = img;  Wh = g_gW1h + 1024*1024;   dst = g_FWVW + 320*1024;    lim = 160; }
    else if (bid < 32) { lb = bid - 20; asrc = span; Wh = g_tW1h;               dst = g_TXT;                lim = 320; }
    else               { lb = bid - 32; asrc = span; Wh = g_tW1h + 1024*1024;   dst = g_TXT + 320*1024;     lim = 320; }
    const int pt = lb >> 2, nb = lb & 3;
    const int n0 = nb * 256, p0 = pt * 128;

    const int gr = t >> 1, gh = t & 1;
    int arow = p0 + gr; if (arow > lim - 1) arow = lim - 1;
    const float* ap = asrc + (size_t)arow * 1024 + gh * 16;

    const int lr = lane & 15, lh = lane >> 4;
    const u32 a_lane = (u32)((wm * 64 + lr) * 80 + lh * 16);
    const int bg = lane >> 3, bk = lane & 7;
    const u32 b_lane = (u32)(((bg & 1) * 8 + bk) * 528 + (wn * 64 + (bg >> 1) * 8) * 2);

    float acc[4][8][4];
#pragma unroll
    for (int am = 0; am < 4; ++am)
#pragma unroll
        for (int nn = 0; nn < 8; ++nn) { acc[am][nn][0]=0.f; acc[am][nn][1]=0.f; acc[am][nn][2]=0.f; acc[am][nn][3]=0.f; }

    auto fillB = [&](int cc, u32 sb) {
        int k0 = cc * 32;
#pragma unroll
        for (int it = 0; it < 4; ++it) {
            int idx = t + it * 256;
            int row = idx >> 5, ch = idx & 31;
            cpa16(sb + BHO + row * 528 + ch * 16, Wh + (size_t)(k0 + row) * 1024 + n0 + ch * 8);
        }
    };
    auto fillA = [&](int cc, u32 sb) {
        const float* fa = ap + cc * 32;
        float4 x0 = *(const float4*)(fa);
        float4 x1 = *(const float4*)(fa + 4);
        float4 x2 = *(const float4*)(fa + 8);
        float4 x3 = *(const float4*)(fa + 12);
        u32 hw[8];
        hw[0]=hpack2(x0.x,x0.y); hw[1]=hpack2(x0.z,x0.w);
        hw[2]=hpack2(x1.x,x1.y); hw[3]=hpack2(x1.z,x1.w);
        hw[4]=hpack2(x2.x,x2.y); hw[5]=hpack2(x2.z,x2.w);
        hw[6]=hpack2(x3.x,x3.y); hw[7]=hpack2(x3.z,x3.w);
        u32 da = sb + AHO + gr * 80 + gh * 32;
        asm volatile("st.shared.v4.b32 [%0], {%1,%2,%3,%4};" :: "r"(da), "r"(hw[0]), "r"(hw[1]), "r"(hw[2]), "r"(hw[3]));
        asm volatile("st.shared.v4.b32 [%0], {%1,%2,%3,%4};" :: "r"(da+16), "r"(hw[4]), "r"(hw[5]), "r"(hw[6]), "r"(hw[7]));
    };

#pragma unroll
    for (int pc = 0; pc < 2; ++pc) {
        u32 sb = smb + (u32)pc * STG_SZ;
        fillB(pc, sb);
        fillA(pc, sb);
        CP_COMMIT;
    }
    for (int c = 0; c < 32; ++c) {
        CP_WAIT1;
        __syncthreads();
        const u32 sb = smb + (u32)(c % 3) * STG_SZ;
        const bool nxt = (c + 2 < 32);
        const u32 nbuf = smb + (u32)((c + 2) % 3) * STG_SZ;
        if (nxt) fillB(c + 2, nbuf);
#pragma unroll
        for (int ks = 0; ks < 2; ++ks) {
            u32 ah[4][4];
#pragma unroll
            for (int am = 0; am < 4; ++am)
                LDSM4(ah[am], sb + a_lane + (u32)(am * 16 * 80 + ks * 32) + AHO);
#pragma unroll
            for (int gn = 0; gn < 4; ++gn) {
                u32 bh[4];
                LDSM4T(bh, sb + b_lane + (u32)(ks * 16 * 528 + gn * 32) + BHO);
#pragma unroll
                for (int am = 0; am < 4; ++am)
#pragma unroll
                    for (int sub = 0; sub < 2; ++sub)
                        mma_f16(acc[am][gn * 2 + sub], ah[am], bh[sub*2], bh[sub*2+1]);
            }
        }
        if (nxt) fillA(c + 2, nbuf);
        CP_COMMIT;
    }
    // epilogue: fp32 store
#pragma unroll
    for (int am = 0; am < 4; ++am) {
        int row0 = p0 + wm * 64 + am * 16 + (lane >> 2);
#pragma unroll
        for (int h = 0; h < 2; ++h) {
            int p = row0 + h * 8;
            if (p >= lim) continue;
#pragma unroll
            for (int nn = 0; nn < 8; ++nn) {
                int col = n0 + wn * 64 + nn * 8 + (lane & 3) * 2;
                *(float2*)(dst + (size_t)p * 1024 + col) =
                    make_float2(acc[am][nn][h * 2 + 0], acc[am][nn][h * 2 + 1]);
            }
        }
    }
}

// =====================================================================
// Main GEMM body. MODE: 0 ground L1, 1 ground L2, 2 text L1, 3 text L2
// All K=1024 now.
// =====================================================================
template<int MODE>
__device__ __forceinline__ void gemm_body(
    int nb, int pb,
    const float* __restrict__ span, const float* __restrict__ img,
    const float* __restrict__ bias1, const float* __restrict__ w3v,
    char* sm)
{
    constexpr int NCH = 32;
    const u32 smb = su32(sm);
    float* red = (float*)(sm + RED_O);
    int* ti = (int*)(sm + RED_O);
    const int t = threadIdx.x, w = t >> 5, lane = t & 31;
    const int wm = w >> 2, wn = w & 3;
    const int n0 = nb * 256, p0 = pb * 128;

    const __half* Wh;
    if constexpr (MODE == 0) Wh = g_gW1h + (size_t)2 * 1024 * 1024;
    else if constexpr (MODE == 1) Wh = g_W2;
    else if constexpr (MODE == 2) Wh = g_tW1h + (size_t)2 * 1024 * 1024;
    else Wh = g_tW2;
    const __half* Asrc = nullptr;
    if constexpr (MODE == 1) Asrc = g_h1;
    if constexpr (MODE == 3) Asrc = g_h1t;

    // ---- A-gen setup (MODE 0/2) ----
    const int gr = t >> 1, gh = t & 1;
    const float *fp = nullptr, *vp = nullptr;
    if constexpr (MODE == 0) {
        int p = p0 + gr, i = p / 160, j = p - i * 160;
        fp = span + (size_t)i * 1024 + gh * 16;
        vp = img  + (size_t)j * 1024 + gh * 16;
    }
    if constexpr (MODE == 2) {
        int p = p0 + gr; if (p > 6239) p = 6239;
        int b = p / 780, q = p - b * 780, fi = 0, cnt = 39, rem = q;
        while (rem >= cnt) { rem -= cnt; fi++; cnt--; }
        int si = fi + 1 + rem;
        fp = span + (size_t)(b * 40 + fi) * 1024 + gh * 16;
        vp = span + (size_t)(b * 40 + si) * 1024 + gh * 16;
        if (gh == 0) { ti[gr] = b * 40 + fi; ti[128 + gr] = b * 40 + si; }
    }

    const int lr = lane & 15, lh = lane >> 4;
    const u32 a_lane = (u32)((wm * 64 + lr) * 80 + lh * 16);
    const int bg = lane >> 3, bk = lane & 7;
    const u32 b_lane = (u32)(((bg & 1) * 8 + bk) * 528 + (wn * 64 + (bg >> 1) * 8) * 2);

    float acc[4][8][4];
#pragma unroll
    for (int am = 0; am < 4; ++am)
#pragma unroll
        for (int nn = 0; nn < 8; ++nn) { acc[am][nn][0]=0.f; acc[am][nn][1]=0.f; acc[am][nn][2]=0.f; acc[am][nn][3]=0.f; }

    auto fillB = [&](int cc, u32 sb) {
        int k0 = cc * 32;
#pragma unroll
        for (int it = 0; it < 4; ++it) {
            int idx = t + it * 256;
            int row = idx >> 5, ch = idx & 31;
            cpa16(sb + BHO + row * 528 + ch * 16, Wh + (size_t)(k0 + row) * 1024 + n0 + ch * 8);
        }
    };
    auto fillA_async = [&](int cc, u32 sb) {
        if constexpr (MODE == 1 || MODE == 3) {
            int k0 = cc * 32;
#pragma unroll
            for (int it = 0; it < 2; ++it) {
                int idx = t + it * 256;
                int row = idx >> 2, ch = idx & 3;
                int prow = p0 + row; if (MODE == 3 && prow > 6239) prow = 6239;
                cpa16(sb + AHO + row * 80 + ch * 16, Asrc + (size_t)prow * 1024 + k0 + ch * 8);
            }
        }
    };
    auto ldgA = [&](int cc, float* xr, float* yr) {
        if constexpr (MODE == 0 || MODE == 2) {
            int db = cc * 32;
            const float *fa = fp + db, *vb = vp + db;
#pragma unroll
            for (int q = 0; q < 4; ++q) {
                float4 x = *(const float4*)(fa + q * 4);
                float4 y = *(const float4*)(vb + q * 4);
                xr[q*4+0]=x.x; xr[q*4+1]=x.y; xr[q*4+2]=x.z; xr[q*4+3]=x.w;
                yr[q*4+0]=y.x; yr[q*4+1]=y.y; yr[q*4+2]=y.z; yr[q*4+3]=y.w;
            }
        }
    };
    auto stsA = [&](u32 sb, const float* xr, const float* yr) {
        if constexpr (MODE == 0 || MODE == 2) {
            u32 hw[8];
#pragma unroll
            for (int q = 0; q < 8; ++q)
                hw[q] = hpack2(xr[2*q] * yr[2*q], xr[2*q+1] * yr[2*q+1]);
            u32 da = sb + AHO + gr * 80 + gh * 32;
            asm volatile("st.shared.v4.b32 [%0], {%1,%2,%3,%4};" :: "r"(da), "r"(hw[0]), "r"(hw[1]), "r"(hw[2]), "r"(hw[3]));
            asm volatile("st.shared.v4.b32 [%0], {%1,%2,%3,%4};" :: "r"(da+16), "r"(hw[4]), "r"(hw[5]), "r"(hw[6]), "r"(hw[7]));
        }
    };

#pragma unroll
    for (int pc = 0; pc < 2; ++pc) {
        u32 sb = smb + (u32)pc * STG_SZ;
        fillB(pc, sb);
        if constexpr (MODE == 1 || MODE == 3) {
            fillA_async(pc, sb);
        } else {
            float xr[16], yr[16];
            ldgA(pc, xr, yr);
            stsA(sb, xr, yr);
        }
        CP_COMMIT;
    }

    for (int c = 0; c < NCH; ++c) {
        CP_WAIT1;
        __syncthreads();
        const u32 sb = smb + (u32)(c % 3) * STG_SZ;
        const bool nxt = (c + 2 < NCH);
        const u32 nbuf = smb + (u32)((c + 2) % 3) * STG_SZ;
        float xr[16], yr[16];
        if (nxt) {
            fillB(c + 2, nbuf);
            fillA_async(c + 2, nbuf);
            ldgA(c + 2, xr, yr);
        }
#pragma unroll
        for (int ks = 0; ks < 2; ++ks) {
            u32 ah[4][4];
#pragma unroll
            for (int am = 0; am < 4; ++am)
                LDSM4(ah[am], sb + a_lane + (u32)(am * 16 * 80 + ks * 32) + AHO);
#pragma unroll
            for (int gn = 0; gn < 4; ++gn) {
                u32 bh[4];
                LDSM4T(bh, sb + b_lane + (u32)(ks * 16 * 528 + gn * 32) + BHO);
#pragma unroll
                for (int am = 0; am < 4; ++am)
#pragma unroll
                    for (int sub = 0; sub < 2; ++sub)
                        mma_f16(acc[am][gn * 2 + sub], ah[am], bh[sub*2], bh[sub*2+1]);
            }
        }
        if (nxt) stsA(nbuf, xr, yr);
        CP_COMMIT;
    }

    // ---------------- epilogue ----------------
    if constexpr (MODE == 0 || MODE == 2) {
        __half* OH = (MODE == 0) ? g_h1 : g_h1t;
#pragma unroll
        for (int am = 0; am < 4; ++am) {
            int rl0 = wm * 64 + am * 16 + (lane >> 2);
#pragma unroll
            for (int h = 0; h < 2; ++h) {
                int rl = rl0 + h * 8;
                int p = p0 + rl;
                bool act = (MODE == 0) || (p < 6240);
                const float *fw, *vw;
                if constexpr (MODE == 0) {
                    int i = p / 160, j = p - i * 160;
                    fw = g_FWVW + (size_t)i * 1024;
                    vw = g_FWVW + (size_t)(320 + j) * 1024;
                } else {
                    fw = g_TXT + (size_t)ti[rl] * 1024;
                    vw = g_TXT + (size_t)(320 + ti[128 + rl]) * 1024;
                }
#pragma unroll
                for (int nn = 0; nn < 8; ++nn) {
                    int col = n0 + wn * 64 + nn * 8 + (lane & 3) * 2;
                    float x0 = acc[am][nn][h*2+0] + bias1[col]   + fw[col]   + vw[col];
                    float x1 = acc[am][nn][h*2+1] + bias1[col+1] + fw[col+1] + vw[col+1];
                    x0 = fmaxf(x0, 0.f); x1 = fmaxf(x1, 0.f);
                    if (act) *(u32*)(OH + (size_t)p * 1024 + col) = hpack2(x0, x1);
                }
            }
        }
    } else {
        float s[8];
#pragma unroll
        for (int q = 0; q < 8; ++q) s[q] = 0.f;
#pragma unroll
        for (int am = 0; am < 4; ++am)
#pragma unroll
            for (int nn = 0; nn < 8; ++nn) {
                int col = n0 + wn * 64 + nn * 8 + (lane & 3) * 2;
                float b0 = bias1[col], b1v = bias1[col + 1];
                float w0 = w3v[col],  w1v = w3v[col + 1];
                s[am*2+0] += fmaxf(acc[am][nn][0] + b0, 0.f) * w0 + fmaxf(acc[am][nn][1] + b1v, 0.f) * w1v;
                s[am*2+1] += fmaxf(acc[am][nn][2] + b0, 0.f) * w0 + fmaxf(acc[am][nn][3] + b1v, 0.f) * w1v;
            }
#pragma unroll
        for (int q = 0; q < 8; ++q) {
            float v = s[q];
            v += __shfl_xor_sync(0xffffffffu, v, 1);
            v += __shfl_xor_sync(0xffffffffu, v, 2);
            if ((lane & 3) == 0) {
                int rowl = wm * 64 + (q >> 1) * 16 + (lane >> 2) + (q & 1) * 8;
                red[wn * 128 + rowl] = v;
            }
        }
        __syncthreads();
        if (t < 128) {
            int pp = p0 + t;
            float v = red[t] + red[128 + t] + red[256 + t] + red[384 + t];
            if (MODE == 1) g_part[(size_t)pp * 4 + nb] = v;
            else if (pp < 6240) g_partt[(size_t)pp * 4 + nb] = v;
        }
    }
}

// =====================================================================
// Combined phase kernels
// =====================================================================
template<int PHASE>
__global__ __launch_bounds__(256) void comb_kernel(
    const float* __restrict__ span, const float* __restrict__ img,
    const float* __restrict__ gb1, const float* __restrict__ tb1,
    const float* __restrict__ gb2, const float* __restrict__ gw3,
    const float* __restrict__ tb2, const float* __restrict__ tw3)
{
    extern __shared__ char sm[];
    int bx = blockIdx.x;
    if constexpr (PHASE == 1) {
        if (bx < 196) gemm_body<2>(bx & 3, bx >> 2, span, img, tb1, nullptr, sm);
        else { int i = bx - 196; gemm_body<0>(i & 3, i >> 2, span, img, gb1, nullptr, sm); }
    } else {
        if (bx < 196) gemm_body<3>(bx & 3, bx >> 2, span, img, tb2, tw3, sm);
        else { int i = bx - 196; gemm_body<1>(i & 3, i >> 2, span, img, gb2, gw3, sm); }
    }
}

// =====================================================================
// finalize + reductions
// =====================================================================
__global__ void fin_g(const float* __restrict__ smask, const float* __restrict__ imask,
                      const float* __restrict__ gb3, float* __restrict__ out_g)
{
    int p = blockIdx.x * 256 + threadIdx.x;
    float s = gb3[0];
#pragma unroll
    for (int nb = 0; nb < 4; ++nb) s += g_part[(size_t)p * 4 + nb];
    int i = p / 160, j = p - i * 160;
    out_g[p] = s * (smask[i] * imask[j]);
}

__global__ void fin_t(const float* __restrict__ tb3, float* __restrict__ out_t)
{
    int p = blockIdx.x * 256 + threadIdx.x;
    if (p >= 6240) return;
    float s = tb3[0];
#pragma unroll
    for (int nb = 0; nb < 4; ++nb) s += g_partt[(size_t)p * 4 + nb];
    out_t[p] = s;
}

__global__ void sreduce_kernel(const float* __restrict__ gsc) {
    __shared__ float red[256];
    int k = blockIdx.x;
    float s = 0.f;
    for (int idx = threadIdx.x; idx < 800; idx += 256) s += gsc[k * 800 + idx];
    red[threadIdx.x] = s;
    __syncthreads();
    for (int st = 128; st > 0; st >>= 1) {
        if (threadIdx.x < st) red[threadIdx.x] += red[threadIdx.x + st];
        __syncthreads();
    }
    if (threadIdx.x == 0) g_S[k] = red[0];
}

__global__ void loss_kernel(float* __restrict__ out) {
    if (threadIdx.x == 0) {
        float S[64];
        for (int k = 0; k < 64; ++k) S[k] = g_S[k];
        float lr = 0.f, lc = 0.f, tot = 0.f;
        for (int r = 0; r < 8; ++r) {
            float m = -1e30f;
            for (int c = 0; c < 8; ++c) m = fmaxf(m, S[r * 8 + c]);
            float e = 0.f;
            for (int c = 0; c < 8; ++c) e += expf(S[r * 8 + c] - m);
            lr += m + logf(e);
        }
        for (int c = 0; c < 8; ++c) {
            float m = -1e30f;
            for (int r = 0; r < 8; ++r) m = fmaxf(m, S[r * 8 + c]);
            float e = 0.f;
            for (int r = 0; r < 8; ++r) e += expf(S[r * 8 + c] - m);
            lc += m + logf(e);
        }
        for (int k = 0; k < 64; ++k) tot += S[k];
        out[0] = -(2.f * tot - 8.f * (lr + lc)) / 8.f;
    }
}

// =====================================================================
extern "C" void kernel_launch(void* const* d_in, const int* in_sizes, int n_in,
                              void* d_out, int out_size) {
    (void)in_sizes; (void)n_in; (void)out_size;
    const float* span  = (const float*)d_in[0];
    const float* img   = (const float*)d_in[1];
    const float* smask = (const float*)d_in[2];
    const float* imask = (const float*)d_in[3];
    const float* tW1 = (const float*)d_in[4];  const float* tb1 = (const float*)d_in[5];
    const float* tW2 = (const float*)d_in[6];  const float* tb2 = (const float*)d_in[7];
    const float* tW3 = (const float*)d_in[8];  const float* tb3 = (const float*)d_in[9];
    const float* gW1 = (const float*)d_in[10]; const float* gb1 = (const float*)d_in[11];
    const float* gW2 = (const float*)d_in[12]; const float* gb2 = (const float*)d_in[13];
    const float* gW3 = (const float*)d_in[14]; const float* gb3 = (const float*)d_in[15];
    float* out = (float*)d_out;

    cudaFuncSetAttribute(prep_kernel,    cudaFuncAttributeMaxDynamicSharedMemorySize, HM_SMEM);
    cudaFuncSetAttribute(comb_kernel<1>, cudaFuncAttributeMaxDynamicSharedMemorySize, HM_SMEM);
    cudaFuncSetAttribute(comb_kernel<2>, cudaFuncAttributeMaxDynamicSharedMemorySize, HM_SMEM);

    wconv<0><<<1536, 256>>>(gW1);
    wconv<1><<<512,  256>>>(gW2);
    wconv<2><<<1536, 256>>>(tW1);
    wconv<3><<<512,  256>>>(tW2);

    prep_kernel<<<44, 256, HM_SMEM>>>(span, img);

    comb_kernel<1><<<1796, 256, HM_SMEM>>>(span, img, gb1, tb1, gb2, gW3, tb2, tW3);
    comb_kernel<2><<<1796, 256, HM_SMEM>>>(span, img, gb1, tb1, gb2, gW3, tb2, tW3);

    fin_g<<<200, 256>>>(smask, imask, gb3, out + 1);
    fin_t<<<25, 256>>>(tb3, out + 1 + 51200);
    sreduce_kernel<<<64, 256>>>(out + 1);
    loss_kernel<<<1, 32>>>(out);
}

// round 11
// speedup vs baseline: 5.2788x; 1.0422x over previous
#include <cuda_runtime.h>
#include <cuda_fp16.h>
#include <cstdint>

typedef unsigned long long ull;
typedef unsigned int u32;

// ---------------- helpers ----------------
__device__ __forceinline__ u32 su32(const void* p) {
    u32 a;
    asm("{ .reg .u64 t; cvta.to.shared.u64 t, %1; cvt.u32.u64 %0, t; }" : "=r"(a) : "l"(p));
    return a;
}
__device__ __forceinline__ void cpa16(u32 s, const void* g) {
    asm volatile("cp.async.cg.shared.global [%0], [%1], 16;" :: "r"(s), "l"(g));
}
#define CP_COMMIT asm volatile("cp.async.commit_group;")
#define CP_WAIT1  asm volatile("cp.async.wait_group 1;")

#define LDSM4(r, a) \
    asm volatile("ldmatrix.sync.aligned.m8n8.x4.shared.b16 {%0,%1,%2,%3}, [%4];" \
        : "=r"((r)[0]), "=r"((r)[1]), "=r"((r)[2]), "=r"((r)[3]) : "r"(a))
#define LDSM4T(r, a) \
    asm volatile("ldmatrix.sync.aligned.m8n8.x4.trans.shared.b16 {%0,%1,%2,%3}, [%4];" \
        : "=r"((r)[0]), "=r"((r)[1]), "=r"((r)[2]), "=r"((r)[3]) : "r"(a))

__device__ __forceinline__ void mma_f16(float* c, const u32* a, u32 b0, u32 b1) {
    asm volatile(
        "mma.sync.aligned.m16n8k16.row.col.f32.f16.f16.f32 "
        "{%0,%1,%2,%3}, {%4,%5,%6,%7}, {%8,%9}, {%0,%1,%2,%3};"
        : "+f"(c[0]), "+f"(c[1]), "+f"(c[2]), "+f"(c[3])
        : "r"(a[0]), "r"(a[1]), "r"(a[2]), "r"(a[3]), "r"(b0), "r"(b1));
}
__device__ __forceinline__ u32 hpack2(float a, float b) {
    __half2 h = __floats2half2_rn(a, b);
    return *(u32*)&h;
}

// ---------------- scratch ----------------
__device__ float g_FWVW[480 * 1024];     // 0..319 f@gW1f, 320..479 v@gW1s
__device__ float g_TXT[640 * 1024];      // 0..319 s@tW1f, 320..639 s@tW1s
__device__ float g_S[64];
__device__ __half g_gW1h[(size_t)3072 * 1024];
__device__ __half g_tW1h[(size_t)3072 * 1024];
__device__ __half g_W2[1024 * 1024];
__device__ __half g_tW2[1024 * 1024];
__device__ __half g_h1[(size_t)51200 * 1024];
__device__ __half g_h1t[(size_t)6272 * 1024];
__device__ float g_part[(size_t)51200 * 4];
__device__ float g_partt[6240 * 4];

// dependency counters (reset by loss_kernel each launch)
__device__ int g_prep_cnt;
__device__ int g_cnt1g[400];
__device__ int g_cnt1t[49];

// ---------------- spin sync helpers ----------------
__device__ __forceinline__ void spin_wait(int* cnt, int target, int t) {
    if (t == 0) {
        while (atomicAdd(cnt, 0) < target) __nanosleep(64);
        __threadfence();
    }
    __syncthreads();
}
__device__ __forceinline__ void signal_done(int* cnt, int t) {
    __syncthreads();
    if (t == 0) { __threadfence(); atomicAdd(cnt, 1); }
}

// =====================================================================
// merged fp32 -> fp16 weight convert, all 4 weights in one launch
// segments (elements): [0,3145728) gW1; [,4194304) gW2; [,7340032) tW1; [,8388608) tW2
// =====================================================================
__global__ void wconv_all(const float* __restrict__ gW1, const float* __restrict__ gW2,
                          const float* __restrict__ tW1, const float* __restrict__ tW2)
{
    size_t i = ((size_t)blockIdx.x * 256 + threadIdx.x) * 8;
    const float* src; __half* dst; size_t off;
    if (i < 3145728)      { src = gW1; dst = g_gW1h; off = i; }
    else if (i < 4194304) { src = gW2; dst = g_W2;   off = i - 3145728; }
    else if (i < 7340032) { src = tW1; dst = g_tW1h; off = i - 4194304; }
    else                  { src = tW2; dst = g_tW2;  off = i - 7340032; }
    float4 a = *(const float4*)(src + off);
    float4 b = *(const float4*)(src + off + 4);
    *(uint4*)(dst + off) = make_uint4(hpack2(a.x, a.y), hpack2(a.z, a.w),
                                      hpack2(b.x, b.y), hpack2(b.z, b.w));
}

// =====================================================================
// GEMM tiling constants (CTA 128x256, warp 64x64, 3 stages)
// =====================================================================
#define AHO 0
#define BHO 10240
#define STG_SZ 27136
#define RED_O (3 * STG_SZ)
#define HM_SMEM (RED_O + 2048)

// =====================================================================
// prep body: fp16-MMA projections of span/img rows through W slices
// bid in [0,44): [0,12) span@gW1f; [12,20) img@gW1s; [20,32) span@tW1f; [32,44) span@tW1s
// =====================================================================
__device__ __forceinline__ void prep_body(
    int bid, const float* __restrict__ span, const float* __restrict__ img, char* sm)
{
    const u32 smb = su32(sm);
    const int t = threadIdx.x, w = t >> 5, lane = t & 31;
    const int wm = w >> 2, wn = w & 3;

    const float* asrc; const __half* Wh; float* dst; int lim, lb;
    if (bid < 12)      { lb = bid;      asrc = span; Wh = g_gW1h;               dst = g_FWVW;               lim = 320; }
    else if (bid < 20) { lb = bid - 12; asrc = img;  Wh = g_gW1h + 1024*1024;   dst = g_FWVW + 320*1024;    lim = 160; }
    else if (bid < 32) { lb = bid - 20; asrc = span; Wh = g_tW1h;               dst = g_TXT;                lim = 320; }
    else               { lb = bid - 32; asrc = span; Wh = g_tW1h + 1024*1024;   dst = g_TXT + 320*1024;     lim = 320; }
    const int pt = lb >> 2, nb = lb & 3;
    const int n0 = nb * 256, p0 = pt * 128;

    const int gr = t >> 1, gh = t & 1;
    int arow = p0 + gr; if (arow > lim - 1) arow = lim - 1;
    const float* ap = asrc + (size_t)arow * 1024 + gh * 16;

    const int lr = lane & 15, lh = lane >> 4;
    const u32 a_lane = (u32)((wm * 64 + lr) * 80 + lh * 16);
    const int bg = lane >> 3, bk = lane & 7;
    const u32 b_lane = (u32)(((bg & 1) * 8 + bk) * 528 + (wn * 64 + (bg >> 1) * 8) * 2);

    float acc[4][8][4];
#pragma unroll
    for (int am = 0; am < 4; ++am)
#pragma unroll
        for (int nn = 0; nn < 8; ++nn) { acc[am][nn][0]=0.f; acc[am][nn][1]=0.f; acc[am][nn][2]=0.f; acc[am][nn][3]=0.f; }

    auto fillB = [&](int cc, u32 sb) {
        int k0 = cc * 32;
#pragma unroll
        for (int it = 0; it < 4; ++it) {
            int idx = t + it * 256;
            int row = idx >> 5, ch = idx & 31;
            cpa16(sb + BHO + row * 528 + ch * 16, Wh + (size_t)(k0 + row) * 1024 + n0 + ch * 8);
        }
    };
    auto fillA = [&](int cc, u32 sb) {
        const float* fa = ap + cc * 32;
        float4 x0 = *(const float4*)(fa);
        float4 x1 = *(const float4*)(fa + 4);
        float4 x2 = *(const float4*)(fa + 8);
        float4 x3 = *(const float4*)(fa + 12);
        u32 hw[8];
        hw[0]=hpack2(x0.x,x0.y); hw[1]=hpack2(x0.z,x0.w);
        hw[2]=hpack2(x1.x,x1.y); hw[3]=hpack2(x1.z,x1.w);
        hw[4]=hpack2(x2.x,x2.y); hw[5]=hpack2(x2.z,x2.w);
        hw[6]=hpack2(x3.x,x3.y); hw[7]=hpack2(x3.z,x3.w);
        u32 da = sb + AHO + gr * 80 + gh * 32;
        asm volatile("st.shared.v4.b32 [%0], {%1,%2,%3,%4};" :: "r"(da), "r"(hw[0]), "r"(hw[1]), "r"(hw[2]), "r"(hw[3]));
        asm volatile("st.shared.v4.b32 [%0], {%1,%2,%3,%4};" :: "r"(da+16), "r"(hw[4]), "r"(hw[5]), "r"(hw[6]), "r"(hw[7]));
    };

#pragma unroll
    for (int pc = 0; pc < 2; ++pc) {
        u32 sb = smb + (u32)pc * STG_SZ;
        fillB(pc, sb);
        fillA(pc, sb);
        CP_COMMIT;
    }
    for (int c = 0; c < 32; ++c) {
        CP_WAIT1;
        __syncthreads();
        const u32 sb = smb + (u32)(c % 3) * STG_SZ;
        const bool nxt = (c + 2 < 32);
        const u32 nbuf = smb + (u32)((c + 2) % 3) * STG_SZ;
        if (nxt) fillB(c + 2, nbuf);
#pragma unroll
        for (int ks = 0; ks < 2; ++ks) {
            u32 ah[4][4];
#pragma unroll
            for (int am = 0; am < 4; ++am)
                LDSM4(ah[am], sb + a_lane + (u32)(am * 16 * 80 + ks * 32) + AHO);
#pragma unroll
            for (int gn = 0; gn < 4; ++gn) {
                u32 bh[4];
                LDSM4T(bh, sb + b_lane + (u32)(ks * 16 * 528 + gn * 32) + BHO);
#pragma unroll
                for (int am = 0; am < 4; ++am)
#pragma unroll
                    for (int sub = 0; sub < 2; ++sub)
                        mma_f16(acc[am][gn * 2 + sub], ah[am], bh[sub*2], bh[sub*2+1]);
            }
        }
        if (nxt) fillA(c + 2, nbuf);
        CP_COMMIT;
    }
#pragma unroll
    for (int am = 0; am < 4; ++am) {
        int row0 = p0 + wm * 64 + am * 16 + (lane >> 2);
#pragma unroll
        for (int h = 0; h < 2; ++h) {
            int p = row0 + h * 8;
            if (p >= lim) continue;
#pragma unroll
            for (int nn = 0; nn < 8; ++nn) {
                int col = n0 + wn * 64 + nn * 8 + (lane & 3) * 2;
                *(float2*)(dst + (size_t)p * 1024 + col) =
                    make_float2(acc[am][nn][h * 2 + 0], acc[am][nn][h * 2 + 1]);
            }
        }
    }
    signal_done(&g_prep_cnt, t);
}

// =====================================================================
// Main GEMM body. MODE: 0 ground L1, 1 ground L2, 2 text L1, 3 text L2
// =====================================================================
template<int MODE>
__device__ __forceinline__ void gemm_body(
    int nb, int pb,
    const float* __restrict__ span, const float* __restrict__ img,
    const float* __restrict__ bias1, const float* __restrict__ w3v,
    char* sm)
{
    constexpr int NCH = 32;
    const u32 smb = su32(sm);
    float* red = (float*)(sm + RED_O);
    int* ti = (int*)(sm + RED_O);
    const int t = threadIdx.x, w = t >> 5, lane = t & 31;
    const int wm = w >> 2, wn = w & 3;
    const int n0 = nb * 256, p0 = pb * 128;

    // consumers wait for their producer L1 tiles
    if constexpr (MODE == 1) spin_wait(&g_cnt1g[pb], 4, t);
    if constexpr (MODE == 3) spin_wait(&g_cnt1t[pb], 4, t);

    const __half* Wh;
    if constexpr (MODE == 0) Wh = g_gW1h + (size_t)2 * 1024 * 1024;
    else if constexpr (MODE == 1) Wh = g_W2;
    else if constexpr (MODE == 2) Wh = g_tW1h + (size_t)2 * 1024 * 1024;
    else Wh = g_tW2;
    const __half* Asrc = nullptr;
    if constexpr (MODE == 1) Asrc = g_h1;
    if constexpr (MODE == 3) Asrc = g_h1t;

    const int gr = t >> 1, gh = t & 1;
    const float *fp = nullptr, *vp = nullptr;
    if constexpr (MODE == 0) {
        int p = p0 + gr, i = p / 160, j = p - i * 160;
        fp = span + (size_t)i * 1024 + gh * 16;
        vp = img  + (size_t)j * 1024 + gh * 16;
    }
    if constexpr (MODE == 2) {
        int p = p0 + gr; if (p > 6239) p = 6239;
        int b = p / 780, q = p - b * 780, fi = 0, cnt = 39, rem = q;
        while (rem >= cnt) { rem -= cnt; fi++; cnt--; }
        int si = fi + 1 + rem;
        fp = span + (size_t)(b * 40 + fi) * 1024 + gh * 16;
        vp = span + (size_t)(b * 40 + si) * 1024 + gh * 16;
        if (gh == 0) { ti[gr] = b * 40 + fi; ti[128 + gr] = b * 40 + si; }
    }

    const int lr = lane & 15, lh = lane >> 4;
    const u32 a_lane = (u32)((wm * 64 + lr) * 80 + lh * 16);
    const int bg = lane >> 3, bk = lane & 7;
    const u32 b_lane = (u32)(((bg & 1) * 8 + bk) * 528 + (wn * 64 + (bg >> 1) * 8) * 2);

    float acc[4][8][4];
#pragma unroll
    for (int am = 0; am < 4; ++am)
#pragma unroll
        for (int nn = 0; nn < 8; ++nn) { acc[am][nn][0]=0.f; acc[am][nn][1]=0.f; acc[am][nn][2]=0.f; acc[am][nn][3]=0.f; }

    auto fillB = [&](int cc, u32 sb) {
        int k0 = cc * 32;
#pragma unroll
        for (int it = 0; it < 4; ++it) {
            int idx = t + it * 256;
            int row = idx >> 5, ch = idx & 31;
            cpa16(sb + BHO + row * 528 + ch * 16, Wh + (size_t)(k0 + row) * 1024 + n0 + ch * 8);
        }
    };
    auto fillA_async = [&](int cc, u32 sb) {
        if constexpr (MODE == 1 || MODE == 3) {
            int k0 = cc * 32;
#pragma unroll
            for (int it = 0; it < 2; ++it) {
                int idx = t + it * 256;
                int row = idx >> 2, ch = idx & 3;
                int prow = p0 + row; if (MODE == 3 && prow > 6239) prow = 6239;
                cpa16(sb + AHO + row * 80 + ch * 16, Asrc + (size_t)prow * 1024 + k0 + ch * 8);
            }
        }
    };
    auto ldgA = [&](int cc, float* xr, float* yr) {
        if constexpr (MODE == 0 || MODE == 2) {
            int db = cc * 32;
            const float *fa = fp + db, *vb = vp + db;
#pragma unroll
            for (int q = 0; q < 4; ++q) {
                float4 x = *(const float4*)(fa + q * 4);
                float4 y = *(const float4*)(vb + q * 4);
                xr[q*4+0]=x.x; xr[q*4+1]=x.y; xr[q*4+2]=x.z; xr[q*4+3]=x.w;
                yr[q*4+0]=y.x; yr[q*4+1]=y.y; yr[q*4+2]=y.z; yr[q*4+3]=y.w;
            }
        }
    };
    auto stsA = [&](u32 sb, const float* xr, const float* yr) {
        if constexpr (MODE == 0 || MODE == 2) {
            u32 hw[8];
#pragma unroll
            for (int q = 0; q < 8; ++q)
                hw[q] = hpack2(xr[2*q] * yr[2*q], xr[2*q+1] * yr[2*q+1]);
            u32 da = sb + AHO + gr * 80 + gh * 32;
            asm volatile("st.shared.v4.b32 [%0], {%1,%2,%3,%4};" :: "r"(da), "r"(hw[0]), "r"(hw[1]), "r"(hw[2]), "r"(hw[3]));
            asm volatile("st.shared.v4.b32 [%0], {%1,%2,%3,%4};" :: "r"(da+16), "r"(hw[4]), "r"(hw[5]), "r"(hw[6]), "r"(hw[7]));
        }
    };

#pragma unroll
    for (int pc = 0; pc < 2; ++pc) {
        u32 sb = smb + (u32)pc * STG_SZ;
        fillB(pc, sb);
        if constexpr (MODE == 1 || MODE == 3) {
            fillA_async(pc, sb);
        } else {
            float xr[16], yr[16];
            ldgA(pc, xr, yr);
            stsA(sb, xr, yr);
        }
        CP_COMMIT;
    }

    for (int c = 0; c < NCH; ++c) {
        CP_WAIT1;
        __syncthreads();
        const u32 sb = smb + (u32)(c % 3) * STG_SZ;
        const bool nxt = (c + 2 < NCH);
        const u32 nbuf = smb + (u32)((c + 2) % 3) * STG_SZ;
        float xr[16], yr[16];
        if (nxt) {
            fillB(c + 2, nbuf);
            fillA_async(c + 2, nbuf);
            ldgA(c + 2, xr, yr);
        }
#pragma unroll
        for (int ks = 0; ks < 2; ++ks) {
            u32 ah[4][4];
#pragma unroll
            for (int am = 0; am < 4; ++am)
                LDSM4(ah[am], sb + a_lane + (u32)(am * 16 * 80 + ks * 32) + AHO);
#pragma unroll
            for (int gn = 0; gn < 4; ++gn) {
                u32 bh[4];
                LDSM4T(bh, sb + b_lane + (u32)(ks * 16 * 528 + gn * 32) + BHO);
#pragma unroll
                for (int am = 0; am < 4; ++am)
#pragma unroll
                    for (int sub = 0; sub < 2; ++sub)
                        mma_f16(acc[am][gn * 2 + sub], ah[am], bh[sub*2], bh[sub*2+1]);
            }
        }
        if (nxt) stsA(nbuf, xr, yr);
        CP_COMMIT;
    }

    // ---------------- epilogue ----------------
    if constexpr (MODE == 0 || MODE == 2) {
        // need prep projections now
        spin_wait(&g_prep_cnt, 44, t);
        __half* OH = (MODE == 0) ? g_h1 : g_h1t;
#pragma unroll
        for (int am = 0; am < 4; ++am) {
            int rl0 = wm * 64 + am * 16 + (lane >> 2);
#pragma unroll
            for (int h = 0; h < 2; ++h) {
                int rl = rl0 + h * 8;
                int p = p0 + rl;
                bool act = (MODE == 0) || (p < 6240);
                const float *fw, *vw;
                if constexpr (MODE == 0) {
                    int i = p / 160, j = p - i * 160;
                    fw = g_FWVW + (size_t)i * 1024;
                    vw = g_FWVW + (size_t)(320 + j) * 1024;
                } else {
                    fw = g_TXT + (size_t)ti[rl] * 1024;
                    vw = g_TXT + (size_t)(320 + ti[128 + rl]) * 1024;
                }
#pragma unroll
                for (int nn = 0; nn < 8; ++nn) {
                    int col = n0 + wn * 64 + nn * 8 + (lane & 3) * 2;
                    float x0 = acc[am][nn][h*2+0] + bias1[col]   + fw[col]   + vw[col];
                    float x1 = acc[am][nn][h*2+1] + bias1[col+1] + fw[col+1] + vw[col+1];
                    x0 = fmaxf(x0, 0.f); x1 = fmaxf(x1, 0.f);
                    if (act) *(u32*)(OH + (size_t)p * 1024 + col) = hpack2(x0, x1);
                }
            }
        }
        // signal this L1 tile done
        if constexpr (MODE == 0) signal_done(&g_cnt1g[pb], t);
        else signal_done(&g_cnt1t[pb], t);
    } else {
        float s[8];
#pragma unroll
        for (int q = 0; q < 8; ++q) s[q] = 0.f;
#pragma unroll
        for (int am = 0; am < 4; ++am)
#pragma unroll
            for (int nn = 0; nn < 8; ++nn) {
                int col = n0 + wn * 64 + nn * 8 + (lane & 3) * 2;
                float b0 = bias1[col], b1v = bias1[col + 1];
                float w0 = w3v[col],  w1v = w3v[col + 1];
                s[am*2+0] += fmaxf(acc[am][nn][0] + b0, 0.f) * w0 + fmaxf(acc[am][nn][1] + b1v, 0.f) * w1v;
                s[am*2+1] += fmaxf(acc[am][nn][2] + b0, 0.f) * w0 + fmaxf(acc[am][nn][3] + b1v, 0.f) * w1v;
            }
#pragma unroll
        for (int q = 0; q < 8; ++q) {
            float v = s[q];
            v += __shfl_xor_sync(0xffffffffu, v, 1);
            v += __shfl_xor_sync(0xffffffffu, v, 2);
            if ((lane & 3) == 0) {
                int rowl = wm * 64 + (q >> 1) * 16 + (lane >> 2) + (q & 1) * 8;
                red[wn * 128 + rowl] = v;
            }
        }
        __syncthreads();
        if (t < 128) {
            int pp = p0 + t;
            float v = red[t] + red[128 + t] + red[256 + t] + red[384 + t];
            if (MODE == 1) g_part[(size_t)pp * 4 + nb] = v;
            else if (pp < 6240) g_partt[(size_t)pp * 4 + nb] = v;
        }
    }
}

// =====================================================================
// mega kernel: prep [0,44) | t1 [44,240) | g1 [240,1840) | t2 [1840,2036) | g2 [2036,3636)
// =====================================================================
__global__ __launch_bounds__(256) void mega_kernel(
    const float* __restrict__ span, const float* __restrict__ img,
    const float* __restrict__ gb1, const float* __restrict__ tb1,
    const float* __restrict__ gb2, const float* __restrict__ gw3,
    const float* __restrict__ tb2, const float* __restrict__ tw3)
{
    extern __shared__ char sm[];
    int bx = blockIdx.x;
    if (bx < 44) {
        prep_body(bx, span, img, sm);
    } else if (bx < 240) {
        int i = bx - 44;   gemm_body<2>(i & 3, i >> 2, span, img, tb1, nullptr, sm);
    } else if (bx < 1840) {
        int i = bx - 240;  gemm_body<0>(i & 3, i >> 2, span, img, gb1, nullptr, sm);
    } else if (bx < 2036) {
        int i = bx - 1840; gemm_body<3>(i & 3, i >> 2, span, img, tb2, tw3, sm);
    } else {
        int i = bx - 2036; gemm_body<1>(i & 3, i >> 2, span, img, gb2, gw3, sm);
    }
}

// =====================================================================
// finalize + reductions
// =====================================================================
__global__ void fin_g(const float* __restrict__ smask, const float* __restrict__ imask,
                      const float* __restrict__ gb3, float* __restrict__ out_g)
{
    int p = blockIdx.x * 256 + threadIdx.x;
    float s = gb3[0];
#pragma unroll
    for (int nb = 0; nb < 4; ++nb) s += g_part[(size_t)p * 4 + nb];
    int i = p / 160, j = p - i * 160;
    out_g[p] = s * (smask[i] * imask[j]);
}

__global__ void fin_t(const float* __restrict__ tb3, float* __restrict__ out_t)
{
    int p = blockIdx.x * 256 + threadIdx.x;
    if (p >= 6240) return;
    float s = tb3[0];
#pragma unroll
    for (int nb = 0; nb < 4; ++nb) s += g_partt[(size_t)p * 4 + nb];
    out_t[p] = s;
}

__global__ void sreduce_kernel(const float* __restrict__ gsc) {
    __shared__ float red[256];
    int k = blockIdx.x;
    float s = 0.f;
    for (int idx = threadIdx.x; idx < 800; idx += 256) s += gsc[k * 800 + idx];
    red[threadIdx.x] = s;
    __syncthreads();
    for (int st = 128; st > 0; st >>= 1) {
        if (threadIdx.x < st) red[threadIdx.x] += red[threadIdx.x + st];
        __syncthreads();
    }
    if (threadIdx.x == 0) g_S[k] = red[0];
}

__global__ void loss_kernel(float* __restrict__ out) {
    // reset dependency counters for next (graph-replayed) launch
    for (int k = threadIdx.x; k < 400; k += 32) g_cnt1g[k] = 0;
    for (int k = threadIdx.x; k < 49; k += 32) g_cnt1t[k] = 0;
    if (threadIdx.x == 0) {
        g_prep_cnt = 0;
        float S[64];
        for (int k = 0; k < 64; ++k) S[k] = g_S[k];
        float lr = 0.f, lc = 0.f, tot = 0.f;
        for (int r = 0; r < 8; ++r) {
            float m = -1e30f;
            for (int c = 0; c < 8; ++c) m = fmaxf(m, S[r * 8 + c]);
            float e = 0.f;
            for (int c = 0; c < 8; ++c) e += expf(S[r * 8 + c] - m);
            lr += m + logf(e);
        }
        for (int c = 0; c < 8; ++c) {
            float m = -1e30f;
            for (int r = 0; r < 8; ++r) m = fmaxf(m, S[r * 8 + c]);
            float e = 0.f;
            for (int r = 0; r < 8; ++r) e += expf(S[r * 8 + c] - m);
            lc += m + logf(e);
        }
        for (int k = 0; k < 64; ++k) tot += S[k];
        out[0] = -(2.f * tot - 8.f * (lr + lc)) / 8.f;
    }
}

// =====================================================================
extern "C" void kernel_launch(void* const* d_in, const int* in_sizes, int n_in,
                              void* d_out, int out_size) {
    (void)in_sizes; (void)n_in; (void)out_size;
    const float* span  = (const float*)d_in[0];
    const float* img   = (const float*)d_in[1];
    const float* smask = (const float*)d_in[2];
    const float* imask = (const float*)d_in[3];
    const float* tW1 = (const float*)d_in[4];  const float* tb1 = (const float*)d_in[5];
    const float* tW2 = (const float*)d_in[6];  const float* tb2 = (const float*)d_in[7];
    const float* tW3 = (const float*)d_in[8];  const float* tb3 = (const float*)d_in[9];
    const float* gW1 = (const float*)d_in[10]; const float* gb1 = (const float*)d_in[11];
    const float* gW2 = (const float*)d_in[12]; const float* gb2 = (const float*)d_in[13];
    const float* gW3 = (const float*)d_in[14]; const float* gb3 = (const float*)d_in[15];
    float* out = (float*)d_out;

    cudaFuncSetAttribute(mega_kernel, cudaFuncAttributeMaxDynamicSharedMemorySize, HM_SMEM);

    wconv_all<<<4096, 256>>>(gW1, gW2, tW1, tW2);
    mega_kernel<<<3636, 256, HM_SMEM>>>(span, img, gb1, tb1, gb2, gW3, tb2, tW3);
    fin_g<<<200, 256>>>(smask, imask, gb3, out + 1);
    fin_t<<<25, 256>>>(tb3, out + 1 + 51200);
    sreduce_kernel<<<64, 256>>>(out + 1);
    loss_kernel<<<1, 32>>>(out);
}